// round 4
// baseline (speedup 1.0000x reference)
#include <cuda_runtime.h>
#include <cstdint>
#include <math.h>

// ---------------------------------------------------------------------------
// Problem constants
// ---------------------------------------------------------------------------
#define Bn   4
#define Sn   2048
#define En   768
#define DFFn 3072
#define MTOT (Bn * Sn)          // 8192
#define LNEPS 1e-5f

// tcgen05/TMEM are "a"/family-target only; harness also builds plain
// compute_103 PTX which rejects them -> gate all tcgen05 usage.
#if defined(__CUDA_ARCH__) && \
    (defined(__CUDA_ARCH_FEAT_SM103_ALL) || defined(__CUDA_ARCH_FEAT_SM100_ALL) || \
     defined(__CUDA_ARCH_FEAT_SM101_ALL) || \
     (defined(__CUDA_ARCH_SPECIFIC__)        && (__CUDA_ARCH_SPECIFIC__        >= 1000)) || \
     (defined(__CUDA_ARCH_FAMILY_SPECIFIC__) && (__CUDA_ARCH_FAMILY_SPECIFIC__ >= 1000)))
#define HAS_TC 1
#else
#define HAS_TC 0
#endif

// ---------------------------------------------------------------------------
// Scratch (allocation-free: __device__ globals). hi/lo = Dekker tf32 split.
// ---------------------------------------------------------------------------
__device__ float g_qh [MTOT * En];
__device__ float g_ql [MTOT * En];
__device__ float g_kh [MTOT * En];
__device__ float g_kl [MTOT * En];
__device__ float g_vth[MTOT * En];              // V^T split: [En, MTOT]
__device__ float g_vtl[MTOT * En];
__device__ float g_s  [(size_t)Bn * Sn * Sn];   // raw attention scores
__device__ float g_big0[(size_t)MTOT * DFFn];   // probs_hi, then hid_hi
__device__ float g_big1[(size_t)MTOT * DFFn];   // probs_lo, then hid_lo
__device__ float g_h  [MTOT * En];              // attention out (plain)
__device__ float g_x1 [MTOT * En];
__device__ float g_x1h[MTOT * En];
__device__ float g_x1l[MTOT * En];
__device__ float g_x2 [MTOT * En];
__device__ float g_x2h[MTOT * En];
__device__ float g_x2l[MTOT * En];
__device__ float g_mlp[MTOT * En];
__device__ float g_xh [MTOT * En];
__device__ float g_xl [MTOT * En];
__device__ float g_kvh[MTOT * En];
__device__ float g_kvl[MTOT * En];
__device__ float g_wh [6 * En * En + 2 * DFFn * En];   // all weight hi, packed
__device__ float g_wl [6 * En * En + 2 * DFFn * En];   // all weight lo, packed

// ---------------------------------------------------------------------------
// Helpers
// ---------------------------------------------------------------------------
__device__ __forceinline__ uint32_t smem_u32(const void* p) {
    uint32_t a;
    asm("{ .reg .u64 t; cvta.to.shared.u64 t, %1; cvt.u32.u64 %0, t; }"
        : "=r"(a) : "l"(p));
    return a;
}

__device__ __forceinline__ float tf32_round(float x) {
    uint32_t u;
    asm("cvt.rna.tf32.f32 %0, %1;" : "=r"(u) : "f"(x));
    return __uint_as_float(u);
}

#if HAS_TC
__device__ __forceinline__ uint32_t elect_one() {
    uint32_t pred;
    asm volatile("{\n\t.reg .pred p;\n\telect.sync _|p, 0xFFFFFFFF;\n\t"
                 "selp.b32 %0, 1, 0, p;\n\t}" : "=r"(pred));
    return pred;
}

#define MBARRIER_INIT(addr, cnt) \
    asm volatile("mbarrier.init.shared.b64 [%0], %1;" :: "r"(addr), "r"(cnt) : "memory")

#define MBARRIER_WAIT_PARITY(mbar_addr, phase_parity) do {                          \
    uint32_t _mbar = (uint32_t)(mbar_addr);                                         \
    uint32_t _par  = (uint32_t)(phase_parity);                                      \
    uint32_t _done;                                                                 \
    asm volatile("{\n\t.reg .pred p;\n\t"                                           \
        "mbarrier.try_wait.parity.acquire.cta.shared::cta.b64 p, [%1], %2;\n\t"     \
        "selp.b32 %0, 1, 0, p;\n\t}"                                                \
        : "=r"(_done) : "r"(_mbar), "r"(_par) : "memory");                          \
    if (!_done) {                                                                   \
        asm volatile("{\n\t.reg .pred P1;\n\t"                                      \
        "WAIT_LOOP_%=:\n\t"                                                         \
        "mbarrier.try_wait.parity.acquire.cta.shared::cta.b64 P1, [%0], %1, 0x989680;\n\t" \
        "@P1 bra.uni WAIT_DONE_%=;\n\t"                                             \
        "bra.uni WAIT_LOOP_%=;\n\t"                                                 \
        "WAIT_DONE_%=:\n\t}"                                                        \
        :: "r"(_mbar), "r"(_par) : "memory");                                       \
    }                                                                               \
} while (0)

#define TCGEN05_ALLOC(smem_res, ncols) \
    asm volatile("tcgen05.alloc.cta_group::1.sync.aligned.shared::cta.b32 [%0], %1;" \
                 :: "r"((uint32_t)(smem_res)), "r"((uint32_t)(ncols)) : "memory")
#define TCGEN05_DEALLOC(tmem, ncols) \
    asm volatile("tcgen05.dealloc.cta_group::1.sync.aligned.b32 %0, %1;" \
                 :: "r"(tmem), "r"((uint32_t)(ncols)))
#define TCGEN05_RELINQUISH() \
    asm volatile("tcgen05.relinquish_alloc_permit.cta_group::1.sync.aligned;")
#define TCGEN05_COMMIT(mbar) \
    asm volatile("tcgen05.commit.cta_group::1.mbarrier::arrive::one.shared::cluster.b64 [%0];" \
                 :: "r"((uint32_t)(mbar)) : "memory")
#define TCGEN05_FENCE_AFTER() \
    asm volatile("tcgen05.fence::after_thread_sync;" ::: "memory")
#define TCGEN05_FENCE_BEFORE() \
    asm volatile("tcgen05.fence::before_thread_sync;" ::: "memory")
#define TCGEN05_WAIT_LD() \
    asm volatile("tcgen05.wait::ld.sync.aligned;" ::: "memory")
#define FENCE_ASYNC() \
    asm volatile("fence.proxy.async;" ::: "memory")

#define TCGEN05_LD_32X32B_X32(r, tmem_addr) \
    asm volatile( \
        "tcgen05.ld.sync.aligned.32x32b.x32.b32 " \
        "{%0, %1, %2, %3, %4, %5, %6, %7, " \
        " %8, %9, %10, %11, %12, %13, %14, %15, " \
        " %16, %17, %18, %19, %20, %21, %22, %23, " \
        " %24, %25, %26, %27, %28, %29, %30, %31}, [%32];" \
        : "=r"((r)[0]),  "=r"((r)[1]),  "=r"((r)[2]),  "=r"((r)[3]), \
          "=r"((r)[4]),  "=r"((r)[5]),  "=r"((r)[6]),  "=r"((r)[7]), \
          "=r"((r)[8]),  "=r"((r)[9]),  "=r"((r)[10]), "=r"((r)[11]), \
          "=r"((r)[12]), "=r"((r)[13]), "=r"((r)[14]), "=r"((r)[15]), \
          "=r"((r)[16]), "=r"((r)[17]), "=r"((r)[18]), "=r"((r)[19]), \
          "=r"((r)[20]), "=r"((r)[21]), "=r"((r)[22]), "=r"((r)[23]), \
          "=r"((r)[24]), "=r"((r)[25]), "=r"((r)[26]), "=r"((r)[27]), \
          "=r"((r)[28]), "=r"((r)[29]), "=r"((r)[30]), "=r"((r)[31]) \
        : "r"(tmem_addr))

// SW128 K-major smem descriptor (validated layout).
__device__ __forceinline__ uint64_t make_desc(uint32_t addr) {
    constexpr uint64_t base =
        (uint64_t(2)  << 61) | (uint64_t(1) << 46) |
        (uint64_t(64) << 32) | (uint64_t(1) << 16);
    return base | ((uint64_t)(addr >> 4) & 0x3FFF);
}

// tcgen05.mma kind::tf32 SS; idesc: D=f32, A/B=TF32, N=128, M=128.
__device__ __forceinline__ void mma_tf32(uint32_t d_tmem, uint64_t da, uint64_t db,
                                         uint32_t idesc, uint32_t acc) {
    asm volatile(
        "{\n\t.reg .pred p;\n\tsetp.ne.u32 p, %4, 0;\n\t"
        "tcgen05.mma.cta_group::1.kind::tf32 [%0], %1, %2, %3, {%5, %5, %5, %5}, p;\n\t}"
        :: "r"(d_tmem), "l"(da), "l"(db), "r"(idesc), "r"(acc), "r"(0u)
        : "memory");
}
#endif  // HAS_TC

// ---------------------------------------------------------------------------
// GEMM (NT): C[M,N] = A[M,K] * B[N,K]^T, operands pre-split (hi/lo tf32).
//   EPI 0: +bias   1: relu(+bias)   2: *scale   4: none
//   OUT 0: plain C          1: split (Chi, Clo)        2: split transposed
// tcgen05 path: BM=BN=128, BK=32, 3xTF32, cp.async loaders, 2-stage buffer.
// ---------------------------------------------------------------------------
static constexpr int SM_TILE0   = 1024;
static constexpr int SM_STAGE   = 65536;       // 4 tiles x 16KB
static constexpr int SM_A_HI    = 0;
static constexpr int SM_A_LO    = 16384;
static constexpr int SM_B_HI    = 32768;
static constexpr int SM_B_LO    = 49152;
static constexpr int GEMM_SMEM  = SM_TILE0 + 2 * SM_STAGE;   // 132096 B
static constexpr uint32_t IDESC_128 =
    (1u << 4) | (2u << 7) | (2u << 10) | ((128u / 8u) << 17) | ((128u / 16u) << 24);

#if HAS_TC
// Copy one 128x32f tile (gmem, row-major, ld floats) into SW128 smem via cp.async.
__device__ __forceinline__ void cpa_tile(const float* __restrict__ g, int ld,
                                         long koff, uint32_t dst, int tid)
{
#pragma unroll
    for (int i = 0; i < 4; i++) {
        const int q   = i * 256 + tid;          // 1024 16B-quads
        const int row = q >> 3;
        const int qc  = q & 7;
        const float* src = g + (long)row * ld + koff + qc * 4;
        uint32_t off = (uint32_t)(row * 128 + qc * 16);
        off ^= (off >> 3) & 0x70;               // SW128 swizzle
        asm volatile("cp.async.cg.shared.global [%0], [%1], 16;"
                     :: "r"(dst + off), "l"(src));
    }
}
#define CPA_COMMIT_WAIT() do {                                      \
    asm volatile("cp.async.commit_group;" ::: "memory");            \
    asm volatile("cp.async.wait_group 0;" ::: "memory");            \
} while (0)
#endif

template<int EPI, int OUT>
__global__ void __launch_bounds__(288, 1)
gemm_tc(const float* __restrict__ Ah, const float* __restrict__ Al,
        const float* __restrict__ Bh, const float* __restrict__ Bl,
        const float* __restrict__ bias,
        float* __restrict__ C, float* __restrict__ C2,
        int K, int lda, int ldb, int ldc,
        long sA, long sB, long sC, float scale, int causal)
{
    extern __shared__ __align__(1024) char smem[];
    const int tid = threadIdx.x;

    const int rm = blockIdx.y * 128;
    const int cn = blockIdx.x * 128;
    if (causal && cn > rm + 127) return;        // fully above diagonal

    Ah += (long)blockIdx.z * sA;  Al += (long)blockIdx.z * sA;
    Bh += (long)blockIdx.z * sB;  Bl += (long)blockIdx.z * sB;
    C  += (long)blockIdx.z * sC;
    if (OUT != 0) C2 += (long)blockIdx.z * sC;

#if HAS_TC
    // ------------------------- tcgen05 3xTF32 path -------------------------
    const uint32_t smem_base = smem_u32(smem);
    const int wid = tid >> 5;

    if (tid == 0) {
        MBARRIER_INIT(smem_base + 8, 1);
        MBARRIER_INIT(smem_base + 16, 1);
    }
    if (wid == 8) TCGEN05_ALLOC(smem_base + 0, 128);
    __syncthreads();

    uint32_t tmem;
    asm volatile("ld.shared.b32 %0, [%1];" : "=r"(tmem) : "r"(smem_base));

    const int NC = K >> 5;
    const float* Abh = Ah + (long)rm * lda;
    const float* Abl = Al + (long)rm * lda;
    const float* Bbh = Bh + (long)cn * ldb;
    const float* Bbl = Bl + (long)cn * ldb;

    if (tid < 256) {                            // preload chunk 0 -> stage 0
        const uint32_t t0 = smem_base + SM_TILE0;
        cpa_tile(Abh, lda, 0, t0 + SM_A_HI, tid);
        cpa_tile(Abl, lda, 0, t0 + SM_A_LO, tid);
        cpa_tile(Bbh, ldb, 0, t0 + SM_B_HI, tid);
        cpa_tile(Bbl, ldb, 0, t0 + SM_B_LO, tid);
        CPA_COMMIT_WAIT();
        FENCE_ASYNC();
    }
    __syncthreads();

    for (int c = 0; c < NC; c++) {
        const int s = c & 1;
        if (wid == 8 && elect_one()) {
            const uint32_t tb = smem_base + SM_TILE0 + s * SM_STAGE;
            const uint64_t dah = make_desc(tb + SM_A_HI);
            const uint64_t dal = make_desc(tb + SM_A_LO);
            const uint64_t dbh = make_desc(tb + SM_B_HI);
            const uint64_t dbl = make_desc(tb + SM_B_LO);
#pragma unroll
            for (int st = 0; st < 4; st++)       // hi*hi
                mma_tf32(tmem, dah + st * 2, dbh + st * 2, IDESC_128,
                         (c == 0 && st == 0) ? 0u : 1u);
#pragma unroll
            for (int st = 0; st < 4; st++)       // hi*lo
                mma_tf32(tmem, dah + st * 2, dbl + st * 2, IDESC_128, 1u);
#pragma unroll
            for (int st = 0; st < 4; st++)       // lo*hi
                mma_tf32(tmem, dal + st * 2, dbh + st * 2, IDESC_128, 1u);
            TCGEN05_COMMIT(smem_base + 8 + s * 8);
        }
        if (tid < 256 && c + 1 < NC) {
            if (c >= 1)   // stage s^1 still feeding chunk c-1's MMAs
                MBARRIER_WAIT_PARITY(smem_base + 8 + (s ^ 1) * 8, ((c - 1) >> 1) & 1);
            const uint32_t tn = smem_base + SM_TILE0 + (s ^ 1) * SM_STAGE;
            const long koff = (long)(c + 1) << 5;
            cpa_tile(Abh, lda, koff, tn + SM_A_HI, tid);
            cpa_tile(Abl, lda, koff, tn + SM_A_LO, tid);
            cpa_tile(Bbh, ldb, koff, tn + SM_B_HI, tid);
            cpa_tile(Bbl, ldb, koff, tn + SM_B_LO, tid);
            CPA_COMMIT_WAIT();
            FENCE_ASYNC();
        }
        __syncthreads();
    }

    MBARRIER_WAIT_PARITY(smem_base + 8 + ((NC - 1) & 1) * 8, ((NC - 1) >> 1) & 1);
    TCGEN05_FENCE_AFTER();

    if (wid < 4) {
        const int lane = tid & 31;
        const int m = rm + wid * 32 + lane;      // TMEM lane -> D row
#pragma unroll
        for (int seg = 0; seg < 4; seg++) {
            uint32_t r[32];
            TCGEN05_LD_32X32B_X32(r, tmem + seg * 32);
            TCGEN05_WAIT_LD();
            if (OUT == 2) {
#pragma unroll
                for (int j = 0; j < 32; j++) {
                    const int n = cn + seg * 32 + j;
                    float x = __uint_as_float(r[j]);
                    if (EPI == 0)      x += bias[n];
                    else if (EPI == 1) x = fmaxf(x + bias[n], 0.f);
                    else if (EPI == 2) x *= scale;
                    const float hi = tf32_round(x);
                    C [(long)n * ldc + m] = hi;
                    C2[(long)n * ldc + m] = x - hi;
                }
            } else {
#pragma unroll
                for (int j = 0; j < 32; j += 4) {
                    float v[4], w[4];
#pragma unroll
                    for (int t = 0; t < 4; t++) {
                        const int n = cn + seg * 32 + j + t;
                        float x = __uint_as_float(r[j + t]);
                        if (EPI == 0)      x += bias[n];
                        else if (EPI == 1) x = fmaxf(x + bias[n], 0.f);
                        else if (EPI == 2) x *= scale;
                        if (OUT == 1) {
                            const float hi = tf32_round(x);
                            v[t] = hi; w[t] = x - hi;
                        } else v[t] = x;
                    }
                    *(float4*)(C + (long)m * ldc + cn + seg * 32 + j) =
                        make_float4(v[0], v[1], v[2], v[3]);
                    if (OUT == 1)
                        *(float4*)(C2 + (long)m * ldc + cn + seg * 32 + j) =
                            make_float4(w[0], w[1], w[2], w[3]);
                }
            }
        }
        TCGEN05_FENCE_BEFORE();
    }
    __syncthreads();
    if (wid == 8) {
        TCGEN05_RELINQUISH();
        TCGEN05_DEALLOC(tmem, 128);
    }
#else
    // --------------------- SIMT fp32 fallback path -------------------------
    constexpr int BK = 16;
    float (*As)[132] = (float (*)[132])(smem);
    float (*Bs)[132] = (float (*)[132])(smem + BK * 132 * sizeof(float));

    const int tx = tid & 15, ty = tid >> 4;
    float acc[8][8];
#pragma unroll
    for (int i = 0; i < 8; i++)
#pragma unroll
        for (int j = 0; j < 8; j++) acc[i][j] = 0.f;

    const float* Abh = Ah + (long)rm * lda;
    const float* Abl = Al + (long)rm * lda;
    const float* Bbh = Bh + (long)cn * ldb;
    const float* Bbl = Bl + (long)cn * ldb;

    for (int k0 = 0; k0 < K; k0 += BK) {
        if (tid < 256) {
#pragma unroll
            for (int i = 0; i < 2; i++) {
                const int q = i * 256 + tid;
                const int row = q >> 2, qc = q & 3;
                float4 fa = *(const float4*)(Abh + (long)row * lda + k0 + qc * 4);
                float4 fal = *(const float4*)(Abl + (long)row * lda + k0 + qc * 4);
                float4 fb = *(const float4*)(Bbh + (long)row * ldb + k0 + qc * 4);
                float4 fbl = *(const float4*)(Bbl + (long)row * ldb + k0 + qc * 4);
                As[qc * 4 + 0][row] = fa.x + fal.x; As[qc * 4 + 1][row] = fa.y + fal.y;
                As[qc * 4 + 2][row] = fa.z + fal.z; As[qc * 4 + 3][row] = fa.w + fal.w;
                Bs[qc * 4 + 0][row] = fb.x + fbl.x; Bs[qc * 4 + 1][row] = fb.y + fbl.y;
                Bs[qc * 4 + 2][row] = fb.z + fbl.z; Bs[qc * 4 + 3][row] = fb.w + fbl.w;
            }
        }
        __syncthreads();
        if (tid < 256) {
#pragma unroll
            for (int kk = 0; kk < BK; kk++) {
                float a[8], b[8];
#pragma unroll
                for (int i = 0; i < 8; i++) a[i] = As[kk][ty * 8 + i];
#pragma unroll
                for (int j = 0; j < 8; j++) b[j] = Bs[kk][tx * 8 + j];
#pragma unroll
                for (int i = 0; i < 8; i++)
#pragma unroll
                    for (int j = 0; j < 8; j++) acc[i][j] += a[i] * b[j];
            }
        }
        __syncthreads();
    }

    if (tid < 256) {
#pragma unroll
        for (int i = 0; i < 8; i++) {
            const int m = rm + ty * 8 + i;
#pragma unroll
            for (int j = 0; j < 8; j++) {
                const int n = cn + tx * 8 + j;
                float x = acc[i][j];
                if (EPI == 0)      x += bias[n];
                else if (EPI == 1) x = fmaxf(x + bias[n], 0.f);
                else if (EPI == 2) x *= scale;
                if (OUT == 2) {
                    const float hi = tf32_round(x);
                    C [(long)n * ldc + m] = hi;
                    C2[(long)n * ldc + m] = x - hi;
                } else if (OUT == 1) {
                    const float hi = tf32_round(x);
                    C [(long)m * ldc + n] = hi;
                    C2[(long)m * ldc + n] = x - hi;
                } else {
                    C[(long)m * ldc + n] = x;
                }
            }
        }
    }
#endif
}

// ---------------------------------------------------------------------------
// Elementwise Dekker split: hi = tf32(x), lo = x - hi.
// ---------------------------------------------------------------------------
__global__ void __launch_bounds__(256)
split_k(const float* __restrict__ src, float* __restrict__ hi,
        float* __restrict__ lo, long n4)
{
    for (long i = blockIdx.x * 256L + threadIdx.x; i < n4; i += (long)gridDim.x * 256) {
        const float4 f = *(const float4*)(src + i * 4);
        float4 h, l;
        h.x = tf32_round(f.x); l.x = f.x - h.x;
        h.y = tf32_round(f.y); l.y = f.y - h.y;
        h.z = tf32_round(f.z); l.z = f.z - h.z;
        h.w = tf32_round(f.w); l.w = f.w - h.w;
        *(float4*)(hi + i * 4) = h;
        *(float4*)(lo + i * 4) = l;
    }
}

// ---------------------------------------------------------------------------
// Row softmax -> split probs (hi/lo); causal rows L=i+1, masked tail -> 0.
// ---------------------------------------------------------------------------
__global__ void __launch_bounds__(256)
softmax_k(const float* __restrict__ S, float* __restrict__ Ph,
          float* __restrict__ Pl, int causal)
{
    const int row = blockIdx.x;
    const int b = row >> 11;
    const int i = row & 2047;
    const float* p = S + (long)b * Sn * Sn + (long)i * Sn;
    float* ph = Ph + (long)b * Sn * Sn + (long)i * Sn;
    float* pl = Pl + (long)b * Sn * Sn + (long)i * Sn;
    const int L = causal ? (i + 1) : Sn;
    const int tid = threadIdx.x;
    __shared__ float sh[8];

    float m = -3.4e38f;
    for (int j = tid; j < L; j += 256) m = fmaxf(m, p[j]);
#pragma unroll
    for (int o = 16; o > 0; o >>= 1) m = fmaxf(m, __shfl_xor_sync(~0u, m, o));
    if ((tid & 31) == 0) sh[tid >> 5] = m;
    __syncthreads();
    m = sh[0];
#pragma unroll
    for (int w = 1; w < 8; w++) m = fmaxf(m, sh[w]);

    float s = 0.f;
    for (int j = tid; j < L; j += 256) {
        float e = __expf(p[j] - m);
        ph[j] = e;                               // stash exp temporarily
        s += e;
    }
#pragma unroll
    for (int o = 16; o > 0; o >>= 1) s += __shfl_xor_sync(~0u, s, o);
    __syncthreads();
    if ((tid & 31) == 0) sh[tid >> 5] = s;
    __syncthreads();
    s = 0.f;
#pragma unroll
    for (int w = 0; w < 8; w++) s += sh[w];
    const float inv = 1.f / s;

    for (int j = tid; j < L; j += 256) {
        const float v = ph[j] * inv;
        const float hi = tf32_round(v);
        ph[j] = hi;
        pl[j] = v - hi;
    }
    for (int j = L + tid; j < Sn; j += 256) { ph[j] = 0.f; pl[j] = 0.f; }
}

// ---------------------------------------------------------------------------
// y = LayerNorm(x + h) * g + b; optional split outputs yh/yl.
// ---------------------------------------------------------------------------
__global__ void __launch_bounds__(256)
add_ln_k(const float* __restrict__ x, const float* __restrict__ h,
         const float* __restrict__ g, const float* __restrict__ bt,
         float* __restrict__ y, float* __restrict__ yh, float* __restrict__ yl)
{
    const long row = blockIdx.x;
    const float* xr = x + row * En;
    const float* hr = h + row * En;
    const int tid = threadIdx.x;

    float v[3];
    float s = 0.f, s2 = 0.f;
#pragma unroll
    for (int t = 0; t < 3; t++) {
        const int c = tid + t * 256;
        const float u = xr[c] + hr[c];
        v[t] = u;
        s += u;
        s2 += u * u;
    }
    __shared__ float shA[8], shB[8];
#pragma unroll
    for (int o = 16; o > 0; o >>= 1) {
        s  += __shfl_xor_sync(~0u, s,  o);
        s2 += __shfl_xor_sync(~0u, s2, o);
    }
    if ((tid & 31) == 0) { shA[tid >> 5] = s; shB[tid >> 5] = s2; }
    __syncthreads();
    s = 0.f; s2 = 0.f;
#pragma unroll
    for (int w = 0; w < 8; w++) { s += shA[w]; s2 += shB[w]; }

    const float mu   = s * (1.f / En);
    const float var  = s2 * (1.f / En) - mu * mu;
    const float rstd = rsqrtf(var + LNEPS);
#pragma unroll
    for (int t = 0; t < 3; t++) {
        const int c = tid + t * 256;
        const float o = (v[t] - mu) * rstd * g[c] + bt[c];
        y[row * En + c] = o;
        if (yh) {
            const float hi = tf32_round(o);
            yh[row * En + c] = hi;
            yl[row * En + c] = o - hi;
        }
    }
}

// ---------------------------------------------------------------------------
// Host launcher
// ---------------------------------------------------------------------------
extern "C" void kernel_launch(void* const* d_in, const int* in_sizes, int n_in,
                              void* d_out, int out_size)
{
    const float* x     = (const float*)d_in[0];
    const float* kv    = (const float*)d_in[1];
    const float* wq_w  = (const float*)d_in[2];
    const float* wq_b  = (const float*)d_in[3];
    const float* wk_w  = (const float*)d_in[4];
    const float* wk_b  = (const float*)d_in[5];
    const float* wv_w  = (const float*)d_in[6];
    const float* wv_b  = (const float*)d_in[7];
    const float* ln1_g = (const float*)d_in[8];
    const float* ln1_b = (const float*)d_in[9];
    const float* wq2_w = (const float*)d_in[10];
    const float* wq2_b = (const float*)d_in[11];
    const float* wk2_w = (const float*)d_in[12];
    const float* wk2_b = (const float*)d_in[13];
    const float* wv2_w = (const float*)d_in[14];
    const float* wv2_b = (const float*)d_in[15];
    const float* ln2_g = (const float*)d_in[16];
    const float* ln2_b = (const float*)d_in[17];
    const float* w1    = (const float*)d_in[18];
    const float* b1    = (const float*)d_in[19];
    const float* w2    = (const float*)d_in[20];
    const float* b2    = (const float*)d_in[21];
    const float* ln3_g = (const float*)d_in[22];
    const float* ln3_b = (const float*)d_in[23];
    float* out = (float*)d_out;

    float *qh, *ql, *kh, *kl, *vth, *vtl, *ps, *b0, *b1p, *ph;
    float *x1, *x1h, *x1l, *x2, *x2h, *x2l, *pmlp, *xh, *xl, *kvh, *kvl, *wh, *wl;
    cudaGetSymbolAddress((void**)&qh,  g_qh);
    cudaGetSymbolAddress((void**)&ql,  g_ql);
    cudaGetSymbolAddress((void**)&kh,  g_kh);
    cudaGetSymbolAddress((void**)&kl,  g_kl);
    cudaGetSymbolAddress((void**)&vth, g_vth);
    cudaGetSymbolAddress((void**)&vtl, g_vtl);
    cudaGetSymbolAddress((void**)&ps,  g_s);
    cudaGetSymbolAddress((void**)&b0,  g_big0);
    cudaGetSymbolAddress((void**)&b1p, g_big1);
    cudaGetSymbolAddress((void**)&ph,  g_h);
    cudaGetSymbolAddress((void**)&x1,  g_x1);
    cudaGetSymbolAddress((void**)&x1h, g_x1h);
    cudaGetSymbolAddress((void**)&x1l, g_x1l);
    cudaGetSymbolAddress((void**)&x2,  g_x2);
    cudaGetSymbolAddress((void**)&x2h, g_x2h);
    cudaGetSymbolAddress((void**)&x2l, g_x2l);
    cudaGetSymbolAddress((void**)&pmlp, g_mlp);
    cudaGetSymbolAddress((void**)&xh,  g_xh);
    cudaGetSymbolAddress((void**)&xl,  g_xl);
    cudaGetSymbolAddress((void**)&kvh, g_kvh);
    cudaGetSymbolAddress((void**)&kvl, g_kvl);
    cudaGetSymbolAddress((void**)&wh,  g_wh);
    cudaGetSymbolAddress((void**)&wl,  g_wl);

    // Packed weight-split offsets
    const long oWQ = 0, oWK = oWQ + (long)En * En, oWV = oWK + (long)En * En;
    const long oWQ2 = oWV + (long)En * En, oWK2 = oWQ2 + (long)En * En;
    const long oWV2 = oWK2 + (long)En * En;
    const long oW1 = oWV2 + (long)En * En, oW2 = oW1 + (long)DFFn * En;

    cudaFuncSetAttribute(gemm_tc<0,1>, cudaFuncAttributeMaxDynamicSharedMemorySize, GEMM_SMEM);
    cudaFuncSetAttribute(gemm_tc<0,2>, cudaFuncAttributeMaxDynamicSharedMemorySize, GEMM_SMEM);
    cudaFuncSetAttribute(gemm_tc<2,0>, cudaFuncAttributeMaxDynamicSharedMemorySize, GEMM_SMEM);
    cudaFuncSetAttribute(gemm_tc<4,0>, cudaFuncAttributeMaxDynamicSharedMemorySize, GEMM_SMEM);
    cudaFuncSetAttribute(gemm_tc<1,1>, cudaFuncAttributeMaxDynamicSharedMemorySize, GEMM_SMEM);
    cudaFuncSetAttribute(gemm_tc<1,0>, cudaFuncAttributeMaxDynamicSharedMemorySize, GEMM_SMEM);

    const float scale = 0.03608439182435161f;  // 1/sqrt(768)
    const long sQE = (long)Sn * En;
    const long sSS = (long)Sn * Sn;

    const dim3 gProj(En / 128, MTOT / 128, 1);       // 6 x 64
    const dim3 gScore(Sn / 128, Sn / 128, Bn);       // 16 x 16 x 4
    const dim3 gPV(En / 128, Sn / 128, Bn);          // 6 x 16 x 4
    const dim3 gFF1(DFFn / 128, MTOT / 128, 1);      // 24 x 64
    const dim3 gFF2(En / 128, MTOT / 128, 1);        // 6 x 64

    // ---- one-time (per launch) splits of inputs + weights ----
    split_k<<<592, 256>>>(x,  xh,  xl,  (long)MTOT * En / 4);
    split_k<<<592, 256>>>(kv, kvh, kvl, (long)MTOT * En / 4);
    split_k<<<148, 256>>>(wq_w,  wh + oWQ,  wl + oWQ,  (long)En * En / 4);
    split_k<<<148, 256>>>(wk_w,  wh + oWK,  wl + oWK,  (long)En * En / 4);
    split_k<<<148, 256>>>(wv_w,  wh + oWV,  wl + oWV,  (long)En * En / 4);
    split_k<<<148, 256>>>(wq2_w, wh + oWQ2, wl + oWQ2, (long)En * En / 4);
    split_k<<<148, 256>>>(wk2_w, wh + oWK2, wl + oWK2, (long)En * En / 4);
    split_k<<<148, 256>>>(wv2_w, wh + oWV2, wl + oWV2, (long)En * En / 4);
    split_k<<<592, 256>>>(w1, wh + oW1, wl + oW1, (long)DFFn * En / 4);
    split_k<<<592, 256>>>(w2, wh + oW2, wl + oW2, (long)DFFn * En / 4);

    // ---- causal self-attention ----
    gemm_tc<0,1><<<gProj, 288, GEMM_SMEM>>>(xh, xl, wh + oWQ, wl + oWQ, wq_b,
                                            qh, ql, En, En, En, En, 0, 0, 0, 1.f, 0);
    gemm_tc<0,1><<<gProj, 288, GEMM_SMEM>>>(xh, xl, wh + oWK, wl + oWK, wk_b,
                                            kh, kl, En, En, En, En, 0, 0, 0, 1.f, 0);
    gemm_tc<0,2><<<gProj, 288, GEMM_SMEM>>>(xh, xl, wh + oWV, wl + oWV, wv_b,
                                            vth, vtl, En, En, En, MTOT, 0, 0, 0, 1.f, 0);
    gemm_tc<2,0><<<gScore, 288, GEMM_SMEM>>>(qh, ql, kh, kl, nullptr,
                                             ps, nullptr, En, En, En, Sn,
                                             sQE, sQE, sSS, scale, 1);
    softmax_k<<<MTOT, 256>>>(ps, b0, b1p, 1);
    gemm_tc<4,0><<<gPV, 288, GEMM_SMEM>>>(b0, b1p, vth, vtl, nullptr,
                                          ph, nullptr, Sn, Sn, MTOT, En,
                                          sSS, (long)Sn, sQE, 1.f, 0);
    add_ln_k<<<MTOT, 256>>>(x, ph, ln1_g, ln1_b, x1, x1h, x1l);

    // ---- cross-attention (no mask) ----
    gemm_tc<0,1><<<gProj, 288, GEMM_SMEM>>>(x1h, x1l, wh + oWQ2, wl + oWQ2, wq2_b,
                                            qh, ql, En, En, En, En, 0, 0, 0, 1.f, 0);
    gemm_tc<0,1><<<gProj, 288, GEMM_SMEM>>>(kvh, kvl, wh + oWK2, wl + oWK2, wk2_b,
                                            kh, kl, En, En, En, En, 0, 0, 0, 1.f, 0);
    gemm_tc<0,2><<<gProj, 288, GEMM_SMEM>>>(kvh, kvl, wh + oWV2, wl + oWV2, wv2_b,
                                            vth, vtl, En, En, En, MTOT, 0, 0, 0, 1.f, 0);
    gemm_tc<2,0><<<gScore, 288, GEMM_SMEM>>>(qh, ql, kh, kl, nullptr,
                                             ps, nullptr, En, En, En, Sn,
                                             sQE, sQE, sSS, scale, 0);
    softmax_k<<<MTOT, 256>>>(ps, b0, b1p, 0);
    gemm_tc<4,0><<<gPV, 288, GEMM_SMEM>>>(b0, b1p, vth, vtl, nullptr,
                                          ph, nullptr, Sn, Sn, MTOT, En,
                                          sSS, (long)Sn, sQE, 1.f, 0);
    add_ln_k<<<MTOT, 256>>>(x1, ph, ln2_g, ln2_b, x2, x2h, x2l);

    // ---- MLP ----
    gemm_tc<1,1><<<gFF1, 288, GEMM_SMEM>>>(x2h, x2l, wh + oW1, wl + oW1, b1,
                                           b0, b1p, En, En, En, DFFn, 0, 0, 0, 1.f, 0);
    gemm_tc<1,0><<<gFF2, 288, GEMM_SMEM>>>(b0, b1p, wh + oW2, wl + oW2, b2,
                                           pmlp, nullptr, DFFn, DFFn, DFFn, En, 0, 0, 0, 1.f, 0);
    add_ln_k<<<MTOT, 256>>>(x2, pmlp, ln3_g, ln3_b, out, nullptr, nullptr);
}

// round 5
// speedup vs baseline: 1.7080x; 1.7080x over previous
#include <cuda_runtime.h>
#include <cuda_bf16.h>
#include <cstdint>
#include <math.h>

// ---------------------------------------------------------------------------
// Problem constants
// ---------------------------------------------------------------------------
#define Bn   4
#define Sn   2048
#define En   768
#define DFFn 3072
#define MTOT (Bn * Sn)          // 8192
#define LNEPS 1e-5f

// tcgen05/TMEM are "a"/family-target only; the build also runs a plain
// compute_103 PTX pass which rejects them -> gate all tcgen05 usage.
#if defined(__CUDA_ARCH__) && \
    (defined(__CUDA_ARCH_FEAT_SM103_ALL) || defined(__CUDA_ARCH_FEAT_SM100_ALL) || \
     defined(__CUDA_ARCH_FEAT_SM101_ALL) || \
     (defined(__CUDA_ARCH_SPECIFIC__)        && (__CUDA_ARCH_SPECIFIC__        >= 1000)) || \
     (defined(__CUDA_ARCH_FAMILY_SPECIFIC__) && (__CUDA_ARCH_FAMILY_SPECIFIC__ >= 1000)))
#define HAS_TC 1
#else
#define HAS_TC 0
#endif

typedef __nv_bfloat16 bf16;

// ---------------------------------------------------------------------------
// Scratch (allocation-free __device__ globals). (hi, lo) = bf16 Dekker planes.
// ---------------------------------------------------------------------------
__device__ bf16  g_qh [MTOT * En],  g_ql [MTOT * En];
__device__ bf16  g_kh [MTOT * En],  g_kl [MTOT * En];
__device__ bf16  g_vth[MTOT * En],  g_vtl[MTOT * En];     // V^T: [En, MTOT]
__device__ float g_s  [(size_t)Bn * Sn * Sn];             // raw scores (fp32)
__device__ bf16  g_ph [(size_t)Bn * Sn * Sn];             // prob planes
__device__ bf16  g_pl [(size_t)Bn * Sn * Sn];
__device__ bf16  g_hh [(size_t)MTOT * DFFn];              // MLP hidden planes
__device__ bf16  g_hl [(size_t)MTOT * DFFn];
__device__ float g_h  [MTOT * En];                        // attention out
__device__ float g_x1 [MTOT * En];
__device__ bf16  g_x1h[MTOT * En], g_x1l[MTOT * En];
__device__ float g_x2 [MTOT * En];
__device__ bf16  g_x2h[MTOT * En], g_x2l[MTOT * En];
__device__ float g_mlp[MTOT * En];
__device__ bf16  g_xh [MTOT * En], g_xl [MTOT * En];
__device__ bf16  g_kvh[MTOT * En], g_kvl[MTOT * En];
__device__ bf16  g_wh [6 * En * En + 2 * DFFn * En];      // weight hi, packed
__device__ bf16  g_wl [6 * En * En + 2 * DFFn * En];      // weight lo, packed

// ---------------------------------------------------------------------------
// Helpers
// ---------------------------------------------------------------------------
__device__ __forceinline__ uint32_t smem_u32(const void* p) {
    uint32_t a;
    asm("{ .reg .u64 t; cvta.to.shared.u64 t, %1; cvt.u32.u64 %0, t; }"
        : "=r"(a) : "l"(p));
    return a;
}

__device__ __forceinline__ void bf16_split(float x, bf16& h, bf16& l) {
    h = __float2bfloat16_rn(x);
    l = __float2bfloat16_rn(x - __bfloat162float(h));
}

#if HAS_TC
__device__ __forceinline__ uint32_t elect_one() {
    uint32_t pred;
    asm volatile("{\n\t.reg .pred p;\n\telect.sync _|p, 0xFFFFFFFF;\n\t"
                 "selp.b32 %0, 1, 0, p;\n\t}" : "=r"(pred));
    return pred;
}

#define MBARRIER_INIT(addr, cnt) \
    asm volatile("mbarrier.init.shared.b64 [%0], %1;" :: "r"(addr), "r"(cnt) : "memory")

#define MBARRIER_WAIT_PARITY(mbar_addr, phase_parity) do {                          \
    uint32_t _mbar = (uint32_t)(mbar_addr);                                         \
    uint32_t _par  = (uint32_t)(phase_parity);                                      \
    uint32_t _done;                                                                 \
    asm volatile("{\n\t.reg .pred p;\n\t"                                           \
        "mbarrier.try_wait.parity.acquire.cta.shared::cta.b64 p, [%1], %2;\n\t"     \
        "selp.b32 %0, 1, 0, p;\n\t}"                                                \
        : "=r"(_done) : "r"(_mbar), "r"(_par) : "memory");                          \
    if (!_done) {                                                                   \
        asm volatile("{\n\t.reg .pred P1;\n\t"                                      \
        "WAIT_LOOP_%=:\n\t"                                                         \
        "mbarrier.try_wait.parity.acquire.cta.shared::cta.b64 P1, [%0], %1, 0x989680;\n\t" \
        "@P1 bra.uni WAIT_DONE_%=;\n\t"                                             \
        "bra.uni WAIT_LOOP_%=;\n\t"                                                 \
        "WAIT_DONE_%=:\n\t}"                                                        \
        :: "r"(_mbar), "r"(_par) : "memory");                                       \
    }                                                                               \
} while (0)

#define TCGEN05_ALLOC(smem_res, ncols) \
    asm volatile("tcgen05.alloc.cta_group::1.sync.aligned.shared::cta.b32 [%0], %1;" \
                 :: "r"((uint32_t)(smem_res)), "r"((uint32_t)(ncols)) : "memory")
#define TCGEN05_DEALLOC(tmem, ncols) \
    asm volatile("tcgen05.dealloc.cta_group::1.sync.aligned.b32 %0, %1;" \
                 :: "r"(tmem), "r"((uint32_t)(ncols)))
#define TCGEN05_RELINQUISH() \
    asm volatile("tcgen05.relinquish_alloc_permit.cta_group::1.sync.aligned;")
#define TCGEN05_COMMIT(mbar) \
    asm volatile("tcgen05.commit.cta_group::1.mbarrier::arrive::one.shared::cluster.b64 [%0];" \
                 :: "r"((uint32_t)(mbar)) : "memory")
#define TCGEN05_FENCE_AFTER() \
    asm volatile("tcgen05.fence::after_thread_sync;" ::: "memory")
#define TCGEN05_FENCE_BEFORE() \
    asm volatile("tcgen05.fence::before_thread_sync;" ::: "memory")
#define TCGEN05_WAIT_LD() \
    asm volatile("tcgen05.wait::ld.sync.aligned;" ::: "memory")
#define FENCE_ASYNC() \
    asm volatile("fence.proxy.async;" ::: "memory")

#define TCGEN05_LD_32X32B_X32(r, tmem_addr) \
    asm volatile( \
        "tcgen05.ld.sync.aligned.32x32b.x32.b32 " \
        "{%0, %1, %2, %3, %4, %5, %6, %7, " \
        " %8, %9, %10, %11, %12, %13, %14, %15, " \
        " %16, %17, %18, %19, %20, %21, %22, %23, " \
        " %24, %25, %26, %27, %28, %29, %30, %31}, [%32];" \
        : "=r"((r)[0]),  "=r"((r)[1]),  "=r"((r)[2]),  "=r"((r)[3]), \
          "=r"((r)[4]),  "=r"((r)[5]),  "=r"((r)[6]),  "=r"((r)[7]), \
          "=r"((r)[8]),  "=r"((r)[9]),  "=r"((r)[10]), "=r"((r)[11]), \
          "=r"((r)[12]), "=r"((r)[13]), "=r"((r)[14]), "=r"((r)[15]), \
          "=r"((r)[16]), "=r"((r)[17]), "=r"((r)[18]), "=r"((r)[19]), \
          "=r"((r)[20]), "=r"((r)[21]), "=r"((r)[22]), "=r"((r)[23]), \
          "=r"((r)[24]), "=r"((r)[25]), "=r"((r)[26]), "=r"((r)[27]), \
          "=r"((r)[28]), "=r"((r)[29]), "=r"((r)[30]), "=r"((r)[31]) \
        : "r"(tmem_addr))

// SW128 K-major smem descriptor (validated layout).
__device__ __forceinline__ uint64_t make_desc(uint32_t addr) {
    constexpr uint64_t base =
        (uint64_t(2)  << 61) | (uint64_t(1) << 46) |
        (uint64_t(64) << 32) | (uint64_t(1) << 16);
    return base | ((uint64_t)(addr >> 4) & 0x3FFF);
}

// tcgen05.mma kind::f16 (bf16 in, fp32 acc), SS, cg1; M=128, N=256.
__device__ __forceinline__ void mma_bf16(uint32_t d_tmem, uint64_t da, uint64_t db,
                                         uint32_t idesc, uint32_t acc) {
    asm volatile(
        "{\n\t.reg .pred p;\n\tsetp.ne.u32 p, %4, 0;\n\t"
        "tcgen05.mma.cta_group::1.kind::f16 [%0], %1, %2, %3, {%5, %5, %5, %5}, p;\n\t}"
        :: "r"(d_tmem), "l"(da), "l"(db), "r"(idesc), "r"(acc), "r"(0u)
        : "memory");
}
#endif  // HAS_TC

// ---------------------------------------------------------------------------
// GEMM (NT): C[M,N] = A[M,K] * B[N,K]^T, operands = bf16 (hi, lo) planes,
// 3-pass emulation (hh + hl + lh). Tiles BM=128, BN=256, BK=64.
//   EPI 0: +bias[n]  1: relu(+bias[n])  2: *scale  3: +bias[m]  4: none
//   OUT 0: fp32 C    1: bf16 split planes (Ch, Cl)
// ---------------------------------------------------------------------------
static constexpr int SM_TILE0  = 1024;
static constexpr int SM_A_HI   = 0;          // 128x64 bf16 = 16 KB
static constexpr int SM_A_LO   = 16384;
static constexpr int SM_B_HI   = 32768;      // 256x64 bf16 = 32 KB
static constexpr int SM_B_LO   = 65536;
static constexpr int SM_STAGE  = 98304;
static constexpr int GEMM_SMEM = SM_TILE0 + 2 * SM_STAGE;   // 197632 B
static constexpr uint32_t IDESC_BF16 =
    (1u << 4) | (1u << 7) | (1u << 10) | ((256u / 8u) << 17) | ((128u / 16u) << 24);

#if HAS_TC
// Copy a ROWSx64 bf16 tile (row-major gmem, ld elems) into SW128 smem.
template<int ROWS>
__device__ __forceinline__ void cpa_plane(const bf16* __restrict__ g, int ld,
                                          long koff, uint32_t dst, int tid)
{
#pragma unroll
    for (int i = 0; i < ROWS / 32; i++) {     // ROWS*8 quads / 256 threads
        const int q   = i * 256 + tid;
        const int row = q >> 3;
        const int qc  = q & 7;
        const bf16* src = g + (long)row * ld + koff + qc * 8;
        uint32_t off = (uint32_t)(row * 128 + qc * 16);
        off ^= (off >> 3) & 0x70;             // SW128 swizzle
        asm volatile("cp.async.cg.shared.global [%0], [%1], 16;"
                     :: "r"(dst + off), "l"(src));
    }
}
#define CPA_COMMIT_WAIT() do {                                      \
    asm volatile("cp.async.commit_group;" ::: "memory");            \
    asm volatile("cp.async.wait_group 0;" ::: "memory");            \
} while (0)
#endif

template<int EPI, int OUT>
__global__ void __launch_bounds__(288, 1)
gemm_tc(const bf16* __restrict__ Ah, const bf16* __restrict__ Al,
        const bf16* __restrict__ Bh, const bf16* __restrict__ Bl,
        const float* __restrict__ bias,
        float* __restrict__ C, bf16* __restrict__ Ch, bf16* __restrict__ Cl,
        int K, int lda, int ldb, int ldc,
        long sA, long sB, long sC, float scale, int causal)
{
    extern __shared__ __align__(1024) char smem[];
    const int tid = threadIdx.x;

    const int rm = blockIdx.y * 128;
    const int cn = blockIdx.x * 256;
    if (causal && cn > rm + 127) return;        // tile fully above diagonal

    Ah += (long)blockIdx.z * sA;  Al += (long)blockIdx.z * sA;
    Bh += (long)blockIdx.z * sB;  Bl += (long)blockIdx.z * sB;
    if (OUT == 0) C += (long)blockIdx.z * sC;
    else { Ch += (long)blockIdx.z * sC; Cl += (long)blockIdx.z * sC; }

#if HAS_TC
    // -------------------- tcgen05 bf16x2 (3-pass) path ---------------------
    const uint32_t smem_base = smem_u32(smem);
    const int wid = tid >> 5;

    if (tid == 0) {
        MBARRIER_INIT(smem_base + 8, 1);
        MBARRIER_INIT(smem_base + 16, 1);
    }
    if (wid == 8) TCGEN05_ALLOC(smem_base + 0, 256);
    __syncthreads();

    uint32_t tmem;
    asm volatile("ld.shared.b32 %0, [%1];" : "=r"(tmem) : "r"(smem_base));

    const int NC = K >> 6;
    const bf16* Abh = Ah + (long)rm * lda;
    const bf16* Abl = Al + (long)rm * lda;
    const bf16* Bbh = Bh + (long)cn * ldb;
    const bf16* Bbl = Bl + (long)cn * ldb;

    if (tid < 256) {                            // preload chunk 0 -> stage 0
        const uint32_t t0 = smem_base + SM_TILE0;
        cpa_plane<128>(Abh, lda, 0, t0 + SM_A_HI, tid);
        cpa_plane<128>(Abl, lda, 0, t0 + SM_A_LO, tid);
        cpa_plane<256>(Bbh, ldb, 0, t0 + SM_B_HI, tid);
        cpa_plane<256>(Bbl, ldb, 0, t0 + SM_B_LO, tid);
        CPA_COMMIT_WAIT();
        FENCE_ASYNC();
    }
    __syncthreads();

    for (int c = 0; c < NC; c++) {
        const int s = c & 1;
        if (wid == 8 && elect_one()) {
            const uint32_t tb = smem_base + SM_TILE0 + s * SM_STAGE;
            const uint64_t dah = make_desc(tb + SM_A_HI);
            const uint64_t dal = make_desc(tb + SM_A_LO);
            const uint64_t dbh = make_desc(tb + SM_B_HI);
            const uint64_t dbl = make_desc(tb + SM_B_LO);
#pragma unroll
            for (int st = 0; st < 4; st++)       // hi*hi  (K=16 per step)
                mma_bf16(tmem, dah + st * 2, dbh + st * 2, IDESC_BF16,
                         (c == 0 && st == 0) ? 0u : 1u);
#pragma unroll
            for (int st = 0; st < 4; st++)       // hi*lo
                mma_bf16(tmem, dah + st * 2, dbl + st * 2, IDESC_BF16, 1u);
#pragma unroll
            for (int st = 0; st < 4; st++)       // lo*hi
                mma_bf16(tmem, dal + st * 2, dbh + st * 2, IDESC_BF16, 1u);
            TCGEN05_COMMIT(smem_base + 8 + s * 8);
        }
        if (tid < 256 && c + 1 < NC) {
            if (c >= 1)   // stage s^1 still feeding chunk c-1's MMAs
                MBARRIER_WAIT_PARITY(smem_base + 8 + (s ^ 1) * 8, ((c - 1) >> 1) & 1);
            const uint32_t tn = smem_base + SM_TILE0 + (s ^ 1) * SM_STAGE;
            const long koff = (long)(c + 1) << 6;
            cpa_plane<128>(Abh, lda, koff, tn + SM_A_HI, tid);
            cpa_plane<128>(Abl, lda, koff, tn + SM_A_LO, tid);
            cpa_plane<256>(Bbh, ldb, koff, tn + SM_B_HI, tid);
            cpa_plane<256>(Bbl, ldb, koff, tn + SM_B_LO, tid);
            CPA_COMMIT_WAIT();
            FENCE_ASYNC();
        }
        __syncthreads();
    }

    MBARRIER_WAIT_PARITY(smem_base + 8 + ((NC - 1) & 1) * 8, ((NC - 1) >> 1) & 1);
    TCGEN05_FENCE_AFTER();

    if (wid < 4) {
        const int lane = tid & 31;
        const int m = rm + wid * 32 + lane;      // TMEM lane -> D row
        const float biasm = (EPI == 3) ? bias[m] : 0.f;
#pragma unroll
        for (int seg = 0; seg < 8; seg++) {      // 256 cols
            uint32_t r[32];
            TCGEN05_LD_32X32B_X32(r, tmem + seg * 32);
            TCGEN05_WAIT_LD();
#pragma unroll
            for (int j = 0; j < 32; j += 4) {
                float v[4];
#pragma unroll
                for (int t = 0; t < 4; t++) {
                    const int n = cn + seg * 32 + j + t;
                    float x = __uint_as_float(r[j + t]);
                    if (EPI == 0)      x += bias[n];
                    else if (EPI == 1) x = fmaxf(x + bias[n], 0.f);
                    else if (EPI == 2) x *= scale;
                    else if (EPI == 3) x += biasm;
                    v[t] = x;
                }
                const long base = (long)m * ldc + cn + seg * 32 + j;
                if (OUT == 0) {
                    *(float4*)(C + base) = make_float4(v[0], v[1], v[2], v[3]);
                } else {
                    __nv_bfloat162 h0, h1, l0, l1;
                    bf16 hh, ll;
                    bf16_split(v[0], hh, ll); h0.x = hh; l0.x = ll;
                    bf16_split(v[1], hh, ll); h0.y = hh; l0.y = ll;
                    bf16_split(v[2], hh, ll); h1.x = hh; l1.x = ll;
                    bf16_split(v[3], hh, ll); h1.y = hh; l1.y = ll;
                    ((__nv_bfloat162*)(Ch + base))[0] = h0;
                    ((__nv_bfloat162*)(Ch + base))[1] = h1;
                    ((__nv_bfloat162*)(Cl + base))[0] = l0;
                    ((__nv_bfloat162*)(Cl + base))[1] = l1;
                }
            }
        }
        TCGEN05_FENCE_BEFORE();
    }
    __syncthreads();
    if (wid == 8) {
        TCGEN05_RELINQUISH();
        TCGEN05_DEALLOC(tmem, 256);
    }
#else
    // --------------------- SIMT fp32 fallback path -------------------------
    // Two 128-wide N sub-tiles sequentially (correctness-only path).
    constexpr int BK = 16;
    float (*As)[132] = (float (*)[132])(smem);
    float (*Bs)[132] = (float (*)[132])(smem + BK * 132 * sizeof(float));
    const int tx = tid & 15, ty = tid >> 4;

    for (int half = 0; half < 2; half++) {
        const int cnh = cn + half * 128;
        float acc[8][8];
#pragma unroll
        for (int i = 0; i < 8; i++)
#pragma unroll
            for (int j = 0; j < 8; j++) acc[i][j] = 0.f;

        for (int k0 = 0; k0 < K; k0 += BK) {
            if (tid < 256) {
#pragma unroll
                for (int i = 0; i < 2; i++) {
                    const int q = i * 256 + tid;
                    const int row = q >> 1, kc = (q & 1) * 8;
#pragma unroll
                    for (int u = 0; u < 8; u++) {
                        const long ai = (long)(rm + row) * lda + k0 + kc + u;
                        const long bi = (long)(cnh + row) * ldb + k0 + kc + u;
                        As[kc + u][row] = __bfloat162float(Ah[ai]) + __bfloat162float(Al[ai]);
                        Bs[kc + u][row] = __bfloat162float(Bh[bi]) + __bfloat162float(Bl[bi]);
                    }
                }
            }
            __syncthreads();
            if (tid < 256) {
#pragma unroll
                for (int kk = 0; kk < BK; kk++) {
                    float a[8], b[8];
#pragma unroll
                    for (int i = 0; i < 8; i++) a[i] = As[kk][ty * 8 + i];
#pragma unroll
                    for (int j = 0; j < 8; j++) b[j] = Bs[kk][tx * 8 + j];
#pragma unroll
                    for (int i = 0; i < 8; i++)
#pragma unroll
                        for (int j = 0; j < 8; j++) acc[i][j] += a[i] * b[j];
                }
            }
            __syncthreads();
        }

        if (tid < 256) {
#pragma unroll
            for (int i = 0; i < 8; i++) {
                const int m = rm + ty * 8 + i;
                const float biasm = (EPI == 3) ? bias[m] : 0.f;
#pragma unroll
                for (int j = 0; j < 8; j++) {
                    const int n = cnh + tx * 8 + j;
                    float x = acc[i][j];
                    if (EPI == 0)      x += bias[n];
                    else if (EPI == 1) x = fmaxf(x + bias[n], 0.f);
                    else if (EPI == 2) x *= scale;
                    else if (EPI == 3) x += biasm;
                    if (OUT == 0) C[(long)m * ldc + n] = x;
                    else {
                        bf16 hh, ll;
                        bf16_split(x, hh, ll);
                        Ch[(long)m * ldc + n] = hh;
                        Cl[(long)m * ldc + n] = ll;
                    }
                }
            }
        }
        __syncthreads();
    }
#endif
}

// ---------------------------------------------------------------------------
// Elementwise bf16 Dekker split of an fp32 array.
// ---------------------------------------------------------------------------
__global__ void __launch_bounds__(256)
split_k(const float* __restrict__ src, bf16* __restrict__ hi,
        bf16* __restrict__ lo, long n4)
{
    for (long i = blockIdx.x * 256L + threadIdx.x; i < n4; i += (long)gridDim.x * 256) {
        const float4 f = *(const float4*)(src + i * 4);
        __nv_bfloat162 h0, h1, l0, l1;
        bf16 hh, ll;
        bf16_split(f.x, hh, ll); h0.x = hh; l0.x = ll;
        bf16_split(f.y, hh, ll); h0.y = hh; l0.y = ll;
        bf16_split(f.z, hh, ll); h1.x = hh; l1.x = ll;
        bf16_split(f.w, hh, ll); h1.y = hh; l1.y = ll;
        ((__nv_bfloat162*)(hi + i * 4))[0] = h0;
        ((__nv_bfloat162*)(hi + i * 4))[1] = h1;
        ((__nv_bfloat162*)(lo + i * 4))[0] = l0;
        ((__nv_bfloat162*)(lo + i * 4))[1] = l1;
    }
}

// ---------------------------------------------------------------------------
// Row softmax over fp32 scores -> bf16 (hi, lo) prob planes.
// Causal rows use L=i+1; masked tail -> 0.
// ---------------------------------------------------------------------------
__global__ void __launch_bounds__(256)
softmax_k(const float* __restrict__ S, bf16* __restrict__ Ph,
          bf16* __restrict__ Pl, int causal)
{
    const int row = blockIdx.x;
    const int b = row >> 11;
    const int i = row & 2047;
    const float* p = S + (long)b * Sn * Sn + (long)i * Sn;
    bf16* ph = Ph + (long)b * Sn * Sn + (long)i * Sn;
    bf16* pl = Pl + (long)b * Sn * Sn + (long)i * Sn;
    const int L = causal ? (i + 1) : Sn;
    const int tid = threadIdx.x;
    __shared__ float sh[8];

    float m = -3.4e38f;
    for (int j = tid; j < L; j += 256) m = fmaxf(m, p[j]);
#pragma unroll
    for (int o = 16; o > 0; o >>= 1) m = fmaxf(m, __shfl_xor_sync(~0u, m, o));
    if ((tid & 31) == 0) sh[tid >> 5] = m;
    __syncthreads();
    m = sh[0];
#pragma unroll
    for (int w = 1; w < 8; w++) m = fmaxf(m, sh[w]);

    float s = 0.f;
    for (int j = tid; j < L; j += 256) s += __expf(p[j] - m);
#pragma unroll
    for (int o = 16; o > 0; o >>= 1) s += __shfl_xor_sync(~0u, s, o);
    __syncthreads();
    if ((tid & 31) == 0) sh[tid >> 5] = s;
    __syncthreads();
    s = 0.f;
#pragma unroll
    for (int w = 0; w < 8; w++) s += sh[w];
    const float inv = 1.f / s;

    for (int j = tid; j < L; j += 256) {
        const float v = __expf(p[j] - m) * inv;
        bf16 hh, ll;
        bf16_split(v, hh, ll);
        ph[j] = hh;
        pl[j] = ll;
    }
    const bf16 z = __float2bfloat16(0.f);
    for (int j = L + tid; j < Sn; j += 256) { ph[j] = z; pl[j] = z; }
}

// ---------------------------------------------------------------------------
// y = LayerNorm(x + h) * g + b; optional bf16 split planes (yh, yl).
// ---------------------------------------------------------------------------
__global__ void __launch_bounds__(256)
add_ln_k(const float* __restrict__ x, const float* __restrict__ h,
         const float* __restrict__ g, const float* __restrict__ bt,
         float* __restrict__ y, bf16* __restrict__ yh, bf16* __restrict__ yl)
{
    const long row = blockIdx.x;
    const float* xr = x + row * En;
    const float* hr = h + row * En;
    const int tid = threadIdx.x;

    float v[3];
    float s = 0.f, s2 = 0.f;
#pragma unroll
    for (int t = 0; t < 3; t++) {
        const int c = tid + t * 256;
        const float u = xr[c] + hr[c];
        v[t] = u;
        s += u;
        s2 += u * u;
    }
    __shared__ float shA[8], shB[8];
#pragma unroll
    for (int o = 16; o > 0; o >>= 1) {
        s  += __shfl_xor_sync(~0u, s,  o);
        s2 += __shfl_xor_sync(~0u, s2, o);
    }
    if ((tid & 31) == 0) { shA[tid >> 5] = s; shB[tid >> 5] = s2; }
    __syncthreads();
    s = 0.f; s2 = 0.f;
#pragma unroll
    for (int w = 0; w < 8; w++) { s += shA[w]; s2 += shB[w]; }

    const float mu   = s * (1.f / En);
    const float var  = s2 * (1.f / En) - mu * mu;
    const float rstd = rsqrtf(var + LNEPS);
#pragma unroll
    for (int t = 0; t < 3; t++) {
        const int c = tid + t * 256;
        const float o = (v[t] - mu) * rstd * g[c] + bt[c];
        y[row * En + c] = o;
        if (yh) {
            bf16 hh, ll;
            bf16_split(o, hh, ll);
            yh[row * En + c] = hh;
            yl[row * En + c] = ll;
        }
    }
}

// ---------------------------------------------------------------------------
// Host launcher
// ---------------------------------------------------------------------------
extern "C" void kernel_launch(void* const* d_in, const int* in_sizes, int n_in,
                              void* d_out, int out_size)
{
    const float* x     = (const float*)d_in[0];
    const float* kv    = (const float*)d_in[1];
    const float* wq_w  = (const float*)d_in[2];
    const float* wq_b  = (const float*)d_in[3];
    const float* wk_w  = (const float*)d_in[4];
    const float* wk_b  = (const float*)d_in[5];
    const float* wv_w  = (const float*)d_in[6];
    const float* wv_b  = (const float*)d_in[7];
    const float* ln1_g = (const float*)d_in[8];
    const float* ln1_b = (const float*)d_in[9];
    const float* wq2_w = (const float*)d_in[10];
    const float* wq2_b = (const float*)d_in[11];
    const float* wk2_w = (const float*)d_in[12];
    const float* wk2_b = (const float*)d_in[13];
    const float* wv2_w = (const float*)d_in[14];
    const float* wv2_b = (const float*)d_in[15];
    const float* ln2_g = (const float*)d_in[16];
    const float* ln2_b = (const float*)d_in[17];
    const float* w1    = (const float*)d_in[18];
    const float* b1    = (const float*)d_in[19];
    const float* w2    = (const float*)d_in[20];
    const float* b2    = (const float*)d_in[21];
    const float* ln3_g = (const float*)d_in[22];
    const float* ln3_b = (const float*)d_in[23];
    float* out = (float*)d_out;

    bf16 *qh, *ql, *kh, *kl, *vth, *vtl, *prh, *prl, *hh, *hl;
    bf16 *x1h, *x1l, *x2h, *x2l, *xh, *xl, *kvh, *kvl, *wh, *wl;
    float *ps, *phf, *x1, *x2, *pmlp;
    cudaGetSymbolAddress((void**)&qh,  g_qh);   cudaGetSymbolAddress((void**)&ql,  g_ql);
    cudaGetSymbolAddress((void**)&kh,  g_kh);   cudaGetSymbolAddress((void**)&kl,  g_kl);
    cudaGetSymbolAddress((void**)&vth, g_vth);  cudaGetSymbolAddress((void**)&vtl, g_vtl);
    cudaGetSymbolAddress((void**)&prh, g_ph);   cudaGetSymbolAddress((void**)&prl, g_pl);
    cudaGetSymbolAddress((void**)&hh,  g_hh);   cudaGetSymbolAddress((void**)&hl,  g_hl);
    cudaGetSymbolAddress((void**)&x1h, g_x1h);  cudaGetSymbolAddress((void**)&x1l, g_x1l);
    cudaGetSymbolAddress((void**)&x2h, g_x2h);  cudaGetSymbolAddress((void**)&x2l, g_x2l);
    cudaGetSymbolAddress((void**)&xh,  g_xh);   cudaGetSymbolAddress((void**)&xl,  g_xl);
    cudaGetSymbolAddress((void**)&kvh, g_kvh);  cudaGetSymbolAddress((void**)&kvl, g_kvl);
    cudaGetSymbolAddress((void**)&wh,  g_wh);   cudaGetSymbolAddress((void**)&wl,  g_wl);
    cudaGetSymbolAddress((void**)&ps,  g_s);
    cudaGetSymbolAddress((void**)&phf, g_h);
    cudaGetSymbolAddress((void**)&x1,  g_x1);
    cudaGetSymbolAddress((void**)&x2,  g_x2);
    cudaGetSymbolAddress((void**)&pmlp, g_mlp);

    const long oWQ = 0, oWK = oWQ + (long)En * En, oWV = oWK + (long)En * En;
    const long oWQ2 = oWV + (long)En * En, oWK2 = oWQ2 + (long)En * En;
    const long oWV2 = oWK2 + (long)En * En;
    const long oW1 = oWV2 + (long)En * En, oW2 = oW1 + (long)DFFn * En;

    cudaFuncSetAttribute(gemm_tc<0,1>, cudaFuncAttributeMaxDynamicSharedMemorySize, GEMM_SMEM);
    cudaFuncSetAttribute(gemm_tc<3,1>, cudaFuncAttributeMaxDynamicSharedMemorySize, GEMM_SMEM);
    cudaFuncSetAttribute(gemm_tc<2,0>, cudaFuncAttributeMaxDynamicSharedMemorySize, GEMM_SMEM);
    cudaFuncSetAttribute(gemm_tc<4,0>, cudaFuncAttributeMaxDynamicSharedMemorySize, GEMM_SMEM);
    cudaFuncSetAttribute(gemm_tc<1,1>, cudaFuncAttributeMaxDynamicSharedMemorySize, GEMM_SMEM);
    cudaFuncSetAttribute(gemm_tc<1,0>, cudaFuncAttributeMaxDynamicSharedMemorySize, GEMM_SMEM);

    const float scale = 0.03608439182435161f;  // 1/sqrt(768)
    const long sQE = (long)Sn * En;
    const long sSS = (long)Sn * Sn;

    const dim3 gProj(En / 256, MTOT / 128, 1);       // 3 x 64
    const dim3 gVT(MTOT / 256, En / 128, 1);         // 32 x 6
    const dim3 gScore(Sn / 256, Sn / 128, Bn);       // 8 x 16 x 4
    const dim3 gPV(En / 256, Sn / 128, Bn);          // 3 x 16 x 4
    const dim3 gFF1(DFFn / 256, MTOT / 128, 1);      // 12 x 64
    const dim3 gFF2(En / 256, MTOT / 128, 1);        // 3 x 64

    // ---- one-time per-launch splits ----
    split_k<<<592, 256>>>(x,  xh,  xl,  (long)MTOT * En / 4);
    split_k<<<592, 256>>>(kv, kvh, kvl, (long)MTOT * En / 4);
    split_k<<<148, 256>>>(wq_w,  wh + oWQ,  wl + oWQ,  (long)En * En / 4);
    split_k<<<148, 256>>>(wk_w,  wh + oWK,  wl + oWK,  (long)En * En / 4);
    split_k<<<148, 256>>>(wv_w,  wh + oWV,  wl + oWV,  (long)En * En / 4);
    split_k<<<148, 256>>>(wq2_w, wh + oWQ2, wl + oWQ2, (long)En * En / 4);
    split_k<<<148, 256>>>(wk2_w, wh + oWK2, wl + oWK2, (long)En * En / 4);
    split_k<<<148, 256>>>(wv2_w, wh + oWV2, wl + oWV2, (long)En * En / 4);
    split_k<<<592, 256>>>(w1, wh + oW1, wl + oW1, (long)DFFn * En / 4);
    split_k<<<592, 256>>>(w2, wh + oW2, wl + oW2, (long)DFFn * En / 4);

    // ---- causal self-attention ----
    gemm_tc<0,1><<<gProj, 288, GEMM_SMEM>>>(xh, xl, wh + oWQ, wl + oWQ, wq_b,
                                            nullptr, qh, ql, En, En, En, En, 0, 0, 0, 1.f, 0);
    gemm_tc<0,1><<<gProj, 288, GEMM_SMEM>>>(xh, xl, wh + oWK, wl + oWK, wk_b,
                                            nullptr, kh, kl, En, En, En, En, 0, 0, 0, 1.f, 0);
    // V^T = Wv * X^T  (A = Wv planes, B = X planes, row bias)
    gemm_tc<3,1><<<gVT, 288, GEMM_SMEM>>>(wh + oWV, wl + oWV, xh, xl, wv_b,
                                          nullptr, vth, vtl, En, En, En, MTOT, 0, 0, 0, 1.f, 0);
    gemm_tc<2,0><<<gScore, 288, GEMM_SMEM>>>(qh, ql, kh, kl, nullptr,
                                             ps, nullptr, nullptr, En, En, En, Sn,
                                             sQE, sQE, sSS, scale, 1);
    softmax_k<<<MTOT, 256>>>(ps, prh, prl, 1);
    gemm_tc<4,0><<<gPV, 288, GEMM_SMEM>>>(prh, prl, vth, vtl, nullptr,
                                          phf, nullptr, nullptr, Sn, Sn, MTOT, En,
                                          sSS, (long)Sn, sQE, 1.f, 0);
    add_ln_k<<<MTOT, 256>>>(x, phf, ln1_g, ln1_b, x1, x1h, x1l);

    // ---- cross-attention (no mask) ----
    gemm_tc<0,1><<<gProj, 288, GEMM_SMEM>>>(x1h, x1l, wh + oWQ2, wl + oWQ2, wq2_b,
                                            nullptr, qh, ql, En, En, En, En, 0, 0, 0, 1.f, 0);
    gemm_tc<0,1><<<gProj, 288, GEMM_SMEM>>>(kvh, kvl, wh + oWK2, wl + oWK2, wk2_b,
                                            nullptr, kh, kl, En, En, En, En, 0, 0, 0, 1.f, 0);
    gemm_tc<3,1><<<gVT, 288, GEMM_SMEM>>>(wh + oWV2, wl + oWV2, kvh, kvl, wv2_b,
                                          nullptr, vth, vtl, En, En, En, MTOT, 0, 0, 0, 1.f, 0);
    gemm_tc<2,0><<<gScore, 288, GEMM_SMEM>>>(qh, ql, kh, kl, nullptr,
                                             ps, nullptr, nullptr, En, En, En, Sn,
                                             sQE, sQE, sSS, scale, 0);
    softmax_k<<<MTOT, 256>>>(ps, prh, prl, 0);
    gemm_tc<4,0><<<gPV, 288, GEMM_SMEM>>>(prh, prl, vth, vtl, nullptr,
                                          phf, nullptr, nullptr, Sn, Sn, MTOT, En,
                                          sSS, (long)Sn, sQE, 1.f, 0);
    add_ln_k<<<MTOT, 256>>>(x1, phf, ln2_g, ln2_b, x2, x2h, x2l);

    // ---- MLP ----
    gemm_tc<1,1><<<gFF1, 288, GEMM_SMEM>>>(x2h, x2l, wh + oW1, wl + oW1, b1,
                                           nullptr, hh, hl, En, En, En, DFFn, 0, 0, 0, 1.f, 0);
    gemm_tc<1,0><<<gFF2, 288, GEMM_SMEM>>>(hh, hl, wh + oW2, wl + oW2, b2,
                                           pmlp, nullptr, nullptr, DFFn, DFFn, DFFn, En, 0, 0, 0, 1.f, 0);
    add_ln_k<<<MTOT, 256>>>(x2, pmlp, ln3_g, ln3_b, out, nullptr, nullptr);
}

// round 6
// speedup vs baseline: 1.7917x; 1.0490x over previous
#include <cuda_runtime.h>
#include <cuda_bf16.h>
#include <cstdint>
#include <math.h>

// ---------------------------------------------------------------------------
// Problem constants
// ---------------------------------------------------------------------------
#define Bn   4
#define Sn   2048
#define En   768
#define DFFn 3072
#define MTOT (Bn * Sn)          // 8192
#define LNEPS 1e-5f

// tcgen05/TMEM are "a"/family-target only; the build also runs a plain
// compute_103 PTX pass which rejects them -> gate all tcgen05 usage.
#if defined(__CUDA_ARCH__) && \
    (defined(__CUDA_ARCH_FEAT_SM103_ALL) || defined(__CUDA_ARCH_FEAT_SM100_ALL) || \
     defined(__CUDA_ARCH_FEAT_SM101_ALL) || \
     (defined(__CUDA_ARCH_SPECIFIC__)        && (__CUDA_ARCH_SPECIFIC__        >= 1000)) || \
     (defined(__CUDA_ARCH_FAMILY_SPECIFIC__) && (__CUDA_ARCH_FAMILY_SPECIFIC__ >= 1000)))
#define HAS_TC 1
#else
#define HAS_TC 0
#endif

typedef __nv_bfloat16 bf16;

// ---------------------------------------------------------------------------
// Scratch (allocation-free __device__ globals). (hi, lo) = bf16 Dekker planes.
// ---------------------------------------------------------------------------
__device__ bf16  g_qh [MTOT * En],  g_ql [MTOT * En];
__device__ bf16  g_kh [MTOT * En],  g_kl [MTOT * En];
__device__ bf16  g_vth[MTOT * En],  g_vtl[MTOT * En];     // V^T: [En, MTOT]
__device__ float g_s  [(size_t)Bn * Sn * Sn];             // raw scores (fp32)
__device__ bf16  g_ph [(size_t)Bn * Sn * Sn];             // prob planes
__device__ bf16  g_pl [(size_t)Bn * Sn * Sn];
__device__ bf16  g_hh [(size_t)MTOT * DFFn];              // MLP hidden planes
__device__ bf16  g_hl [(size_t)MTOT * DFFn];
__device__ float g_h  [MTOT * En];                        // attention out
__device__ float g_x1 [MTOT * En];
__device__ bf16  g_x1h[MTOT * En], g_x1l[MTOT * En];
__device__ float g_x2 [MTOT * En];
__device__ bf16  g_x2h[MTOT * En], g_x2l[MTOT * En];
__device__ float g_mlp[MTOT * En];
__device__ bf16  g_xh [MTOT * En], g_xl [MTOT * En];
__device__ bf16  g_kvh[MTOT * En], g_kvl[MTOT * En];
__device__ bf16  g_wh [6 * En * En + 2 * DFFn * En];      // weight hi, packed
__device__ bf16  g_wl [6 * En * En + 2 * DFFn * En];      // weight lo, packed

// ---------------------------------------------------------------------------
// Helpers
// ---------------------------------------------------------------------------
__device__ __forceinline__ uint32_t smem_u32(const void* p) {
    uint32_t a;
    asm("{ .reg .u64 t; cvta.to.shared.u64 t, %1; cvt.u32.u64 %0, t; }"
        : "=r"(a) : "l"(p));
    return a;
}

__device__ __forceinline__ void bf16_split(float x, bf16& h, bf16& l) {
    h = __float2bfloat16_rn(x);
    l = __float2bfloat16_rn(x - __bfloat162float(h));
}

#if HAS_TC
__device__ __forceinline__ uint32_t elect_one() {
    uint32_t pred;
    asm volatile("{\n\t.reg .pred p;\n\telect.sync _|p, 0xFFFFFFFF;\n\t"
                 "selp.b32 %0, 1, 0, p;\n\t}" : "=r"(pred));
    return pred;
}

#define MBARRIER_INIT(addr, cnt) \
    asm volatile("mbarrier.init.shared.b64 [%0], %1;" :: "r"(addr), "r"(cnt) : "memory")

#define MBARRIER_WAIT_PARITY(mbar_addr, phase_parity) do {                          \
    uint32_t _mbar = (uint32_t)(mbar_addr);                                         \
    uint32_t _par  = (uint32_t)(phase_parity);                                      \
    uint32_t _done;                                                                 \
    asm volatile("{\n\t.reg .pred p;\n\t"                                           \
        "mbarrier.try_wait.parity.acquire.cta.shared::cta.b64 p, [%1], %2;\n\t"     \
        "selp.b32 %0, 1, 0, p;\n\t}"                                                \
        : "=r"(_done) : "r"(_mbar), "r"(_par) : "memory");                          \
    if (!_done) {                                                                   \
        asm volatile("{\n\t.reg .pred P1;\n\t"                                      \
        "WAIT_LOOP_%=:\n\t"                                                         \
        "mbarrier.try_wait.parity.acquire.cta.shared::cta.b64 P1, [%0], %1, 0x989680;\n\t" \
        "@P1 bra.uni WAIT_DONE_%=;\n\t"                                             \
        "bra.uni WAIT_LOOP_%=;\n\t"                                                 \
        "WAIT_DONE_%=:\n\t}"                                                        \
        :: "r"(_mbar), "r"(_par) : "memory");                                       \
    }                                                                               \
} while (0)

#define TCGEN05_ALLOC(smem_res, ncols) \
    asm volatile("tcgen05.alloc.cta_group::1.sync.aligned.shared::cta.b32 [%0], %1;" \
                 :: "r"((uint32_t)(smem_res)), "r"((uint32_t)(ncols)) : "memory")
#define TCGEN05_DEALLOC(tmem, ncols) \
    asm volatile("tcgen05.dealloc.cta_group::1.sync.aligned.b32 %0, %1;" \
                 :: "r"(tmem), "r"((uint32_t)(ncols)))
#define TCGEN05_RELINQUISH() \
    asm volatile("tcgen05.relinquish_alloc_permit.cta_group::1.sync.aligned;")
#define TCGEN05_COMMIT(mbar) \
    asm volatile("tcgen05.commit.cta_group::1.mbarrier::arrive::one.shared::cluster.b64 [%0];" \
                 :: "r"((uint32_t)(mbar)) : "memory")
#define TCGEN05_FENCE_AFTER() \
    asm volatile("tcgen05.fence::after_thread_sync;" ::: "memory")
#define TCGEN05_FENCE_BEFORE() \
    asm volatile("tcgen05.fence::before_thread_sync;" ::: "memory")
#define TCGEN05_WAIT_LD() \
    asm volatile("tcgen05.wait::ld.sync.aligned;" ::: "memory")
#define FENCE_ASYNC() \
    asm volatile("fence.proxy.async;" ::: "memory")

#define TCGEN05_LD_32X32B_X32(r, tmem_addr) \
    asm volatile( \
        "tcgen05.ld.sync.aligned.32x32b.x32.b32 " \
        "{%0, %1, %2, %3, %4, %5, %6, %7, " \
        " %8, %9, %10, %11, %12, %13, %14, %15, " \
        " %16, %17, %18, %19, %20, %21, %22, %23, " \
        " %24, %25, %26, %27, %28, %29, %30, %31}, [%32];" \
        : "=r"((r)[0]),  "=r"((r)[1]),  "=r"((r)[2]),  "=r"((r)[3]), \
          "=r"((r)[4]),  "=r"((r)[5]),  "=r"((r)[6]),  "=r"((r)[7]), \
          "=r"((r)[8]),  "=r"((r)[9]),  "=r"((r)[10]), "=r"((r)[11]), \
          "=r"((r)[12]), "=r"((r)[13]), "=r"((r)[14]), "=r"((r)[15]), \
          "=r"((r)[16]), "=r"((r)[17]), "=r"((r)[18]), "=r"((r)[19]), \
          "=r"((r)[20]), "=r"((r)[21]), "=r"((r)[22]), "=r"((r)[23]), \
          "=r"((r)[24]), "=r"((r)[25]), "=r"((r)[26]), "=r"((r)[27]), \
          "=r"((r)[28]), "=r"((r)[29]), "=r"((r)[30]), "=r"((r)[31]) \
        : "r"(tmem_addr))

// SW128 K-major smem descriptor (validated layout).
__device__ __forceinline__ uint64_t make_desc(uint32_t addr) {
    constexpr uint64_t base =
        (uint64_t(2)  << 61) | (uint64_t(1) << 46) |
        (uint64_t(64) << 32) | (uint64_t(1) << 16);
    return base | ((uint64_t)(addr >> 4) & 0x3FFF);
}

// tcgen05.mma kind::f16 (bf16 in, fp32 acc), SS, cg1; M=128, N=256.
__device__ __forceinline__ void mma_bf16(uint32_t d_tmem, uint64_t da, uint64_t db,
                                         uint32_t idesc, uint32_t acc) {
    asm volatile(
        "{\n\t.reg .pred p;\n\tsetp.ne.u32 p, %4, 0;\n\t"
        "tcgen05.mma.cta_group::1.kind::f16 [%0], %1, %2, %3, {%5, %5, %5, %5}, p;\n\t}"
        :: "r"(d_tmem), "l"(da), "l"(db), "r"(idesc), "r"(acc), "r"(0u)
        : "memory");
}
#endif  // HAS_TC

// ---------------------------------------------------------------------------
// GEMM (NT): C[M,N] = A[M,K] * B[N,K]^T, operands = bf16 (hi, lo) planes,
// 3-pass emulation (hh + hl + lh). Tiles BM=128, BN=256, BK=64.
//   EPI 0: +bias[n]  1: relu(+bias[n])  2: *scale  3: +bias[m]  4: none
//   OUT 0: fp32 C    1: bf16 split planes (Ch, Cl)
//   causal 0: none   1: skip tiles above diagonal (score GEMM)
//          2: limit K-loop to k < rm+128 (causal PV; prob tail is exact zero)
// ---------------------------------------------------------------------------
static constexpr int SM_TILE0  = 1024;
static constexpr int SM_A_HI   = 0;          // 128x64 bf16 = 16 KB
static constexpr int SM_A_LO   = 16384;
static constexpr int SM_B_HI   = 32768;      // 256x64 bf16 = 32 KB
static constexpr int SM_B_LO   = 65536;
static constexpr int SM_STAGE  = 98304;
static constexpr int GEMM_SMEM = SM_TILE0 + 2 * SM_STAGE;   // 197632 B
static constexpr uint32_t IDESC_BF16 =
    (1u << 4) | (1u << 7) | (1u << 10) | ((256u / 8u) << 17) | ((128u / 16u) << 24);

#if HAS_TC
// Copy a ROWSx64 bf16 tile (row-major gmem, ld elems) into SW128 smem.
template<int ROWS>
__device__ __forceinline__ void cpa_plane(const bf16* __restrict__ g, int ld,
                                          long koff, uint32_t dst, int tid)
{
#pragma unroll
    for (int i = 0; i < ROWS / 32; i++) {     // ROWS*8 quads / 256 threads
        const int q   = i * 256 + tid;
        const int row = q >> 3;
        const int qc  = q & 7;
        const bf16* src = g + (long)row * ld + koff + qc * 8;
        uint32_t off = (uint32_t)(row * 128 + qc * 16);
        off ^= (off >> 3) & 0x70;             // SW128 swizzle
        asm volatile("cp.async.cg.shared.global [%0], [%1], 16;"
                     :: "r"(dst + off), "l"(src));
    }
}
#define CPA_COMMIT_WAIT() do {                                      \
    asm volatile("cp.async.commit_group;" ::: "memory");            \
    asm volatile("cp.async.wait_group 0;" ::: "memory");            \
} while (0)
#endif

template<int EPI, int OUT>
__global__ void __launch_bounds__(288, 1)
gemm_tc(const bf16* __restrict__ Ah, const bf16* __restrict__ Al,
        const bf16* __restrict__ Bh, const bf16* __restrict__ Bl,
        const float* __restrict__ bias,
        float* __restrict__ C, bf16* __restrict__ Ch, bf16* __restrict__ Cl,
        int K, int lda, int ldb, int ldc,
        long sA, long sB, long sC, float scale, int causal)
{
    extern __shared__ __align__(1024) char smem[];
    const int tid = threadIdx.x;

    const int rm = blockIdx.y * 128;
    const int cn = blockIdx.x * 256;
    if (causal == 1 && cn > rm + 127) return;   // tile fully above diagonal

    Ah += (long)blockIdx.z * sA;  Al += (long)blockIdx.z * sA;
    Bh += (long)blockIdx.z * sB;  Bl += (long)blockIdx.z * sB;
    if (OUT == 0) C += (long)blockIdx.z * sC;
    else { Ch += (long)blockIdx.z * sC; Cl += (long)blockIdx.z * sC; }

    // Causal PV: rows [rm, rm+128) only need k < rm+128 (tail probs are 0).
    int Keff = K;
    if (causal == 2) Keff = min(K, rm + 128);

#if HAS_TC
    // -------------------- tcgen05 bf16x2 (3-pass) path ---------------------
    const uint32_t smem_base = smem_u32(smem);
    const int wid = tid >> 5;

    if (tid == 0) {
        MBARRIER_INIT(smem_base + 8, 1);
        MBARRIER_INIT(smem_base + 16, 1);
    }
    if (wid == 8) TCGEN05_ALLOC(smem_base + 0, 256);
    __syncthreads();

    uint32_t tmem;
    asm volatile("ld.shared.b32 %0, [%1];" : "=r"(tmem) : "r"(smem_base));

    const int NC = Keff >> 6;
    const bf16* Abh = Ah + (long)rm * lda;
    const bf16* Abl = Al + (long)rm * lda;
    const bf16* Bbh = Bh + (long)cn * ldb;
    const bf16* Bbl = Bl + (long)cn * ldb;

    if (tid < 256) {                            // preload chunk 0 -> stage 0
        const uint32_t t0 = smem_base + SM_TILE0;
        cpa_plane<128>(Abh, lda, 0, t0 + SM_A_HI, tid);
        cpa_plane<128>(Abl, lda, 0, t0 + SM_A_LO, tid);
        cpa_plane<256>(Bbh, ldb, 0, t0 + SM_B_HI, tid);
        cpa_plane<256>(Bbl, ldb, 0, t0 + SM_B_LO, tid);
        CPA_COMMIT_WAIT();
        FENCE_ASYNC();
    }
    __syncthreads();

    for (int c = 0; c < NC; c++) {
        const int s = c & 1;
        if (wid == 8 && elect_one()) {
            const uint32_t tb = smem_base + SM_TILE0 + s * SM_STAGE;
            const uint64_t dah = make_desc(tb + SM_A_HI);
            const uint64_t dal = make_desc(tb + SM_A_LO);
            const uint64_t dbh = make_desc(tb + SM_B_HI);
            const uint64_t dbl = make_desc(tb + SM_B_LO);
#pragma unroll
            for (int st = 0; st < 4; st++)       // hi*hi  (K=16 per step)
                mma_bf16(tmem, dah + st * 2, dbh + st * 2, IDESC_BF16,
                         (c == 0 && st == 0) ? 0u : 1u);
#pragma unroll
            for (int st = 0; st < 4; st++)       // hi*lo
                mma_bf16(tmem, dah + st * 2, dbl + st * 2, IDESC_BF16, 1u);
#pragma unroll
            for (int st = 0; st < 4; st++)       // lo*hi
                mma_bf16(tmem, dal + st * 2, dbh + st * 2, IDESC_BF16, 1u);
            TCGEN05_COMMIT(smem_base + 8 + s * 8);
        }
        if (tid < 256 && c + 1 < NC) {
            if (c >= 1)   // stage s^1 still feeding chunk c-1's MMAs
                MBARRIER_WAIT_PARITY(smem_base + 8 + (s ^ 1) * 8, ((c - 1) >> 1) & 1);
            const uint32_t tn = smem_base + SM_TILE0 + (s ^ 1) * SM_STAGE;
            const long koff = (long)(c + 1) << 6;
            cpa_plane<128>(Abh, lda, koff, tn + SM_A_HI, tid);
            cpa_plane<128>(Abl, lda, koff, tn + SM_A_LO, tid);
            cpa_plane<256>(Bbh, ldb, koff, tn + SM_B_HI, tid);
            cpa_plane<256>(Bbl, ldb, koff, tn + SM_B_LO, tid);
            CPA_COMMIT_WAIT();
            FENCE_ASYNC();
        }
        __syncthreads();
    }

    MBARRIER_WAIT_PARITY(smem_base + 8 + ((NC - 1) & 1) * 8, ((NC - 1) >> 1) & 1);
    TCGEN05_FENCE_AFTER();

    if (wid < 4) {
        const int lane = tid & 31;
        const int m = rm + wid * 32 + lane;      // TMEM lane -> D row
        const float biasm = (EPI == 3) ? bias[m] : 0.f;
#pragma unroll
        for (int seg = 0; seg < 8; seg++) {      // 256 cols
            uint32_t r[32];
            TCGEN05_LD_32X32B_X32(r, tmem + seg * 32);
            TCGEN05_WAIT_LD();
#pragma unroll
            for (int j = 0; j < 32; j += 4) {
                float v[4];
#pragma unroll
                for (int t = 0; t < 4; t++) {
                    const int n = cn + seg * 32 + j + t;
                    float x = __uint_as_float(r[j + t]);
                    if (EPI == 0)      x += bias[n];
                    else if (EPI == 1) x = fmaxf(x + bias[n], 0.f);
                    else if (EPI == 2) x *= scale;
                    else if (EPI == 3) x += biasm;
                    v[t] = x;
                }
                const long base = (long)m * ldc + cn + seg * 32 + j;
                if (OUT == 0) {
                    *(float4*)(C + base) = make_float4(v[0], v[1], v[2], v[3]);
                } else {
                    __nv_bfloat162 h0, h1, l0, l1;
                    bf16 hh, ll;
                    bf16_split(v[0], hh, ll); h0.x = hh; l0.x = ll;
                    bf16_split(v[1], hh, ll); h0.y = hh; l0.y = ll;
                    bf16_split(v[2], hh, ll); h1.x = hh; l1.x = ll;
                    bf16_split(v[3], hh, ll); h1.y = hh; l1.y = ll;
                    ((__nv_bfloat162*)(Ch + base))[0] = h0;
                    ((__nv_bfloat162*)(Ch + base))[1] = h1;
                    ((__nv_bfloat162*)(Cl + base))[0] = l0;
                    ((__nv_bfloat162*)(Cl + base))[1] = l1;
                }
            }
        }
        TCGEN05_FENCE_BEFORE();
    }
    __syncthreads();
    if (wid == 8) {
        TCGEN05_RELINQUISH();
        TCGEN05_DEALLOC(tmem, 256);
    }
#else
    // --------------------- SIMT fp32 fallback path -------------------------
    constexpr int BK = 16;
    float (*As)[132] = (float (*)[132])(smem);
    float (*Bs)[132] = (float (*)[132])(smem + BK * 132 * sizeof(float));
    const int tx = tid & 15, ty = tid >> 4;

    for (int half = 0; half < 2; half++) {
        const int cnh = cn + half * 128;
        float acc[8][8];
#pragma unroll
        for (int i = 0; i < 8; i++)
#pragma unroll
            for (int j = 0; j < 8; j++) acc[i][j] = 0.f;

        for (int k0 = 0; k0 < Keff; k0 += BK) {
            if (tid < 256) {
#pragma unroll
                for (int i = 0; i < 2; i++) {
                    const int q = i * 256 + tid;
                    const int row = q >> 1, kc = (q & 1) * 8;
#pragma unroll
                    for (int u = 0; u < 8; u++) {
                        const long ai = (long)(rm + row) * lda + k0 + kc + u;
                        const long bi = (long)(cnh + row) * ldb + k0 + kc + u;
                        As[kc + u][row] = __bfloat162float(Ah[ai]) + __bfloat162float(Al[ai]);
                        Bs[kc + u][row] = __bfloat162float(Bh[bi]) + __bfloat162float(Bl[bi]);
                    }
                }
            }
            __syncthreads();
            if (tid < 256) {
#pragma unroll
                for (int kk = 0; kk < BK; kk++) {
                    float a[8], b[8];
#pragma unroll
                    for (int i = 0; i < 8; i++) a[i] = As[kk][ty * 8 + i];
#pragma unroll
                    for (int j = 0; j < 8; j++) b[j] = Bs[kk][tx * 8 + j];
#pragma unroll
                    for (int i = 0; i < 8; i++)
#pragma unroll
                        for (int j = 0; j < 8; j++) acc[i][j] += a[i] * b[j];
                }
            }
            __syncthreads();
        }

        if (tid < 256) {
#pragma unroll
            for (int i = 0; i < 8; i++) {
                const int m = rm + ty * 8 + i;
                const float biasm = (EPI == 3) ? bias[m] : 0.f;
#pragma unroll
                for (int j = 0; j < 8; j++) {
                    const int n = cnh + tx * 8 + j;
                    float x = acc[i][j];
                    if (EPI == 0)      x += bias[n];
                    else if (EPI == 1) x = fmaxf(x + bias[n], 0.f);
                    else if (EPI == 2) x *= scale;
                    else if (EPI == 3) x += biasm;
                    if (OUT == 0) C[(long)m * ldc + n] = x;
                    else {
                        bf16 hh, ll;
                        bf16_split(x, hh, ll);
                        Ch[(long)m * ldc + n] = hh;
                        Cl[(long)m * ldc + n] = ll;
                    }
                }
            }
        }
        __syncthreads();
    }
#endif
}

// ---------------------------------------------------------------------------
// Elementwise bf16 Dekker split; split2 handles two tensors via blockIdx.y.
// ---------------------------------------------------------------------------
__device__ __forceinline__ void split_body(const float* __restrict__ src,
                                           bf16* __restrict__ hi,
                                           bf16* __restrict__ lo, long n4)
{
    for (long i = blockIdx.x * 256L + threadIdx.x; i < n4; i += (long)gridDim.x * 256) {
        const float4 f = *(const float4*)(src + i * 4);
        __nv_bfloat162 h0, h1, l0, l1;
        bf16 hh, ll;
        bf16_split(f.x, hh, ll); h0.x = hh; l0.x = ll;
        bf16_split(f.y, hh, ll); h0.y = hh; l0.y = ll;
        bf16_split(f.z, hh, ll); h1.x = hh; l1.x = ll;
        bf16_split(f.w, hh, ll); h1.y = hh; l1.y = ll;
        ((__nv_bfloat162*)(hi + i * 4))[0] = h0;
        ((__nv_bfloat162*)(hi + i * 4))[1] = h1;
        ((__nv_bfloat162*)(lo + i * 4))[0] = l0;
        ((__nv_bfloat162*)(lo + i * 4))[1] = l1;
    }
}

__global__ void __launch_bounds__(256)
split2_k(const float* __restrict__ s0, bf16* __restrict__ h0, bf16* __restrict__ l0,
         const float* __restrict__ s1, bf16* __restrict__ h1, bf16* __restrict__ l1,
         long n4)
{
    if (blockIdx.y == 0) split_body(s0, h0, l0, n4);
    else                 split_body(s1, h1, l1, n4);
}

// ---------------------------------------------------------------------------
// Row softmax over fp32 scores -> bf16 (hi, lo) prob planes.
// Causal rows: L=i+1; zero-fill only up to the 128-row diagonal block end
// (((i>>7)+1)<<7) -- exactly the range causal PV reads.
// ---------------------------------------------------------------------------
__global__ void __launch_bounds__(256)
softmax_k(const float* __restrict__ S, bf16* __restrict__ Ph,
          bf16* __restrict__ Pl, int causal)
{
    const int row = blockIdx.x;
    const int b = row >> 11;
    const int i = row & 2047;
    const float* p = S + (long)b * Sn * Sn + (long)i * Sn;
    bf16* ph = Ph + (long)b * Sn * Sn + (long)i * Sn;
    bf16* pl = Pl + (long)b * Sn * Sn + (long)i * Sn;
    const int L = causal ? (i + 1) : Sn;
    const int FILL = causal ? (((i >> 7) + 1) << 7) : Sn;
    const int tid = threadIdx.x;
    __shared__ float sh[8];

    float m = -3.4e38f;
    for (int j = tid; j < L; j += 256) m = fmaxf(m, p[j]);
#pragma unroll
    for (int o = 16; o > 0; o >>= 1) m = fmaxf(m, __shfl_xor_sync(~0u, m, o));
    if ((tid & 31) == 0) sh[tid >> 5] = m;
    __syncthreads();
    m = sh[0];
#pragma unroll
    for (int w = 1; w < 8; w++) m = fmaxf(m, sh[w]);

    float s = 0.f;
    for (int j = tid; j < L; j += 256) s += __expf(p[j] - m);
#pragma unroll
    for (int o = 16; o > 0; o >>= 1) s += __shfl_xor_sync(~0u, s, o);
    __syncthreads();
    if ((tid & 31) == 0) sh[tid >> 5] = s;
    __syncthreads();
    s = 0.f;
#pragma unroll
    for (int w = 0; w < 8; w++) s += sh[w];
    const float inv = 1.f / s;

    for (int j = tid; j < L; j += 256) {
        const float v = __expf(p[j] - m) * inv;
        bf16 hh, ll;
        bf16_split(v, hh, ll);
        ph[j] = hh;
        pl[j] = ll;
    }
    const bf16 z = __float2bfloat16(0.f);
    for (int j = L + tid; j < FILL; j += 256) { ph[j] = z; pl[j] = z; }
}

// ---------------------------------------------------------------------------
// y = LayerNorm(x + h) * g + b; optional bf16 split planes (yh, yl).
// ---------------------------------------------------------------------------
__global__ void __launch_bounds__(256)
add_ln_k(const float* __restrict__ x, const float* __restrict__ h,
         const float* __restrict__ g, const float* __restrict__ bt,
         float* __restrict__ y, bf16* __restrict__ yh, bf16* __restrict__ yl)
{
    const long row = blockIdx.x;
    const float* xr = x + row * En;
    const float* hr = h + row * En;
    const int tid = threadIdx.x;

    float v[3];
    float s = 0.f, s2 = 0.f;
#pragma unroll
    for (int t = 0; t < 3; t++) {
        const int c = tid + t * 256;
        const float u = xr[c] + hr[c];
        v[t] = u;
        s += u;
        s2 += u * u;
    }
    __shared__ float shA[8], shB[8];
#pragma unroll
    for (int o = 16; o > 0; o >>= 1) {
        s  += __shfl_xor_sync(~0u, s,  o);
        s2 += __shfl_xor_sync(~0u, s2, o);
    }
    if ((tid & 31) == 0) { shA[tid >> 5] = s; shB[tid >> 5] = s2; }
    __syncthreads();
    s = 0.f; s2 = 0.f;
#pragma unroll
    for (int w = 0; w < 8; w++) { s += shA[w]; s2 += shB[w]; }

    const float mu   = s * (1.f / En);
    const float var  = s2 * (1.f / En) - mu * mu;
    const float rstd = rsqrtf(var + LNEPS);
#pragma unroll
    for (int t = 0; t < 3; t++) {
        const int c = tid + t * 256;
        const float o = (v[t] - mu) * rstd * g[c] + bt[c];
        y[row * En + c] = o;
        if (yh) {
            bf16 hh, ll;
            bf16_split(o, hh, ll);
            yh[row * En + c] = hh;
            yl[row * En + c] = ll;
        }
    }
}

// ---------------------------------------------------------------------------
// Host launcher
// ---------------------------------------------------------------------------
extern "C" void kernel_launch(void* const* d_in, const int* in_sizes, int n_in,
                              void* d_out, int out_size)
{
    const float* x     = (const float*)d_in[0];
    const float* kv    = (const float*)d_in[1];
    const float* wq_w  = (const float*)d_in[2];
    const float* wq_b  = (const float*)d_in[3];
    const float* wk_w  = (const float*)d_in[4];
    const float* wk_b  = (const float*)d_in[5];
    const float* wv_w  = (const float*)d_in[6];
    const float* wv_b  = (const float*)d_in[7];
    const float* ln1_g = (const float*)d_in[8];
    const float* ln1_b = (const float*)d_in[9];
    const float* wq2_w = (const float*)d_in[10];
    const float* wq2_b = (const float*)d_in[11];
    const float* wk2_w = (const float*)d_in[12];
    const float* wk2_b = (const float*)d_in[13];
    const float* wv2_w = (const float*)d_in[14];
    const float* wv2_b = (const float*)d_in[15];
    const float* ln2_g = (const float*)d_in[16];
    const float* ln2_b = (const float*)d_in[17];
    const float* w1    = (const float*)d_in[18];
    const float* b1    = (const float*)d_in[19];
    const float* w2    = (const float*)d_in[20];
    const float* b2    = (const float*)d_in[21];
    const float* ln3_g = (const float*)d_in[22];
    const float* ln3_b = (const float*)d_in[23];
    float* out = (float*)d_out;

    bf16 *qh, *ql, *kh, *kl, *vth, *vtl, *prh, *prl, *hh, *hl;
    bf16 *x1h, *x1l, *x2h, *x2l, *xh, *xl, *kvh, *kvl, *wh, *wl;
    float *ps, *phf, *x1, *x2, *pmlp;
    cudaGetSymbolAddress((void**)&qh,  g_qh);   cudaGetSymbolAddress((void**)&ql,  g_ql);
    cudaGetSymbolAddress((void**)&kh,  g_kh);   cudaGetSymbolAddress((void**)&kl,  g_kl);
    cudaGetSymbolAddress((void**)&vth, g_vth);  cudaGetSymbolAddress((void**)&vtl, g_vtl);
    cudaGetSymbolAddress((void**)&prh, g_ph);   cudaGetSymbolAddress((void**)&prl, g_pl);
    cudaGetSymbolAddress((void**)&hh,  g_hh);   cudaGetSymbolAddress((void**)&hl,  g_hl);
    cudaGetSymbolAddress((void**)&x1h, g_x1h);  cudaGetSymbolAddress((void**)&x1l, g_x1l);
    cudaGetSymbolAddress((void**)&x2h, g_x2h);  cudaGetSymbolAddress((void**)&x2l, g_x2l);
    cudaGetSymbolAddress((void**)&xh,  g_xh);   cudaGetSymbolAddress((void**)&xl,  g_xl);
    cudaGetSymbolAddress((void**)&kvh, g_kvh);  cudaGetSymbolAddress((void**)&kvl, g_kvl);
    cudaGetSymbolAddress((void**)&wh,  g_wh);   cudaGetSymbolAddress((void**)&wl,  g_wl);
    cudaGetSymbolAddress((void**)&ps,  g_s);
    cudaGetSymbolAddress((void**)&phf, g_h);
    cudaGetSymbolAddress((void**)&x1,  g_x1);
    cudaGetSymbolAddress((void**)&x2,  g_x2);
    cudaGetSymbolAddress((void**)&pmlp, g_mlp);

    const long oWQ = 0, oWK = oWQ + (long)En * En, oWV = oWK + (long)En * En;
    const long oWQ2 = oWV + (long)En * En, oWK2 = oWQ2 + (long)En * En;
    const long oWV2 = oWK2 + (long)En * En;
    const long oW1 = oWV2 + (long)En * En, oW2 = oW1 + (long)DFFn * En;

    cudaFuncSetAttribute(gemm_tc<0,1>, cudaFuncAttributeMaxDynamicSharedMemorySize, GEMM_SMEM);
    cudaFuncSetAttribute(gemm_tc<3,1>, cudaFuncAttributeMaxDynamicSharedMemorySize, GEMM_SMEM);
    cudaFuncSetAttribute(gemm_tc<2,0>, cudaFuncAttributeMaxDynamicSharedMemorySize, GEMM_SMEM);
    cudaFuncSetAttribute(gemm_tc<4,0>, cudaFuncAttributeMaxDynamicSharedMemorySize, GEMM_SMEM);
    cudaFuncSetAttribute(gemm_tc<1,1>, cudaFuncAttributeMaxDynamicSharedMemorySize, GEMM_SMEM);
    cudaFuncSetAttribute(gemm_tc<1,0>, cudaFuncAttributeMaxDynamicSharedMemorySize, GEMM_SMEM);

    const float scale = 0.03608439182435161f;  // 1/sqrt(768)
    const long sQE = (long)Sn * En;
    const long sSS = (long)Sn * Sn;

    const dim3 gProj(En / 256, MTOT / 128, 1);       // 3 x 64
    const dim3 gVT(MTOT / 256, En / 128, 1);         // 32 x 6
    const dim3 gScore(Sn / 256, Sn / 128, Bn);       // 8 x 16 x 4
    const dim3 gPV(En / 256, Sn / 128, Bn);          // 3 x 16 x 4
    const dim3 gFF1(DFFn / 256, MTOT / 128, 1);      // 12 x 64
    const dim3 gFF2(En / 256, MTOT / 128, 1);        // 3 x 64

    const long nXY = (long)MTOT * En / 4;
    const long nW  = (long)En * En / 4;
    const long nFF = (long)DFFn * En / 4;

    // Launch order puts the causal score GEMM at index 5 (ncu -s 5 -c 1).
    // 0: split x + kv
    split2_k<<<dim3(296, 2), 256>>>(x, xh, xl, kv, kvh, kvl, nXY);
    // 1: split wq + wk
    split2_k<<<dim3(148, 2), 256>>>(wq_w, wh + oWQ, wl + oWQ,
                                    wk_w, wh + oWK, wl + oWK, nW);
    // 2: Q proj
    gemm_tc<0,1><<<gProj, 288, GEMM_SMEM>>>(xh, xl, wh + oWQ, wl + oWQ, wq_b,
                                            nullptr, qh, ql, En, En, En, En, 0, 0, 0, 1.f, 0);
    // 3: K proj
    gemm_tc<0,1><<<gProj, 288, GEMM_SMEM>>>(xh, xl, wh + oWK, wl + oWK, wk_b,
                                            nullptr, kh, kl, En, En, En, En, 0, 0, 0, 1.f, 0);
    // 4: split wv + wv2
    split2_k<<<dim3(148, 2), 256>>>(wv_w,  wh + oWV,  wl + oWV,
                                    wv2_w, wh + oWV2, wl + oWV2, nW);
    // 5: causal score GEMM  <-- profiled launch
    gemm_tc<2,0><<<gScore, 288, GEMM_SMEM>>>(qh, ql, kh, kl, nullptr,
                                             ps, nullptr, nullptr, En, En, En, Sn,
                                             sQE, sQE, sSS, scale, 1);
    // 6: V^T = Wv * X^T
    gemm_tc<3,1><<<gVT, 288, GEMM_SMEM>>>(wh + oWV, wl + oWV, xh, xl, wv_b,
                                          nullptr, vth, vtl, En, En, En, MTOT, 0, 0, 0, 1.f, 0);
    // 7: causal softmax
    softmax_k<<<MTOT, 256>>>(ps, prh, prl, 1);
    // 8: causal PV (K-limited)
    gemm_tc<4,0><<<gPV, 288, GEMM_SMEM>>>(prh, prl, vth, vtl, nullptr,
                                          phf, nullptr, nullptr, Sn, Sn, MTOT, En,
                                          sSS, (long)Sn, sQE, 1.f, 2);
    // 9: LN1
    add_ln_k<<<MTOT, 256>>>(x, phf, ln1_g, ln1_b, x1, x1h, x1l);

    // ---- cross-attention ----
    split2_k<<<dim3(148, 2), 256>>>(wq2_w, wh + oWQ2, wl + oWQ2,
                                    wk2_w, wh + oWK2, wl + oWK2, nW);
    gemm_tc<0,1><<<gProj, 288, GEMM_SMEM>>>(x1h, x1l, wh + oWQ2, wl + oWQ2, wq2_b,
                                            nullptr, qh, ql, En, En, En, En, 0, 0, 0, 1.f, 0);
    gemm_tc<0,1><<<gProj, 288, GEMM_SMEM>>>(kvh, kvl, wh + oWK2, wl + oWK2, wk2_b,
                                            nullptr, kh, kl, En, En, En, En, 0, 0, 0, 1.f, 0);
    gemm_tc<3,1><<<gVT, 288, GEMM_SMEM>>>(wh + oWV2, wl + oWV2, kvh, kvl, wv2_b,
                                          nullptr, vth, vtl, En, En, En, MTOT, 0, 0, 0, 1.f, 0);
    gemm_tc<2,0><<<gScore, 288, GEMM_SMEM>>>(qh, ql, kh, kl, nullptr,
                                             ps, nullptr, nullptr, En, En, En, Sn,
                                             sQE, sQE, sSS, scale, 0);
    softmax_k<<<MTOT, 256>>>(ps, prh, prl, 0);
    gemm_tc<4,0><<<gPV, 288, GEMM_SMEM>>>(prh, prl, vth, vtl, nullptr,
                                          phf, nullptr, nullptr, Sn, Sn, MTOT, En,
                                          sSS, (long)Sn, sQE, 1.f, 0);
    add_ln_k<<<MTOT, 256>>>(x1, phf, ln2_g, ln2_b, x2, x2h, x2l);

    // ---- MLP ----
    split2_k<<<dim3(592, 2), 256>>>(w1, wh + oW1, wl + oW1,
                                    w2, wh + oW2, wl + oW2, nFF);
    gemm_tc<1,1><<<gFF1, 288, GEMM_SMEM>>>(x2h, x2l, wh + oW1, wl + oW1, b1,
                                           nullptr, hh, hl, En, En, En, DFFn, 0, 0, 0, 1.f, 0);
    gemm_tc<1,0><<<gFF2, 288, GEMM_SMEM>>>(hh, hl, wh + oW2, wl + oW2, b2,
                                           pmlp, nullptr, nullptr, DFFn, DFFn, DFFn, En, 0, 0, 0, 1.f, 0);
    add_ln_k<<<MTOT, 256>>>(x2, pmlp, ln3_g, ln3_b, out, nullptr, nullptr);
}

// round 8
// speedup vs baseline: 1.8720x; 1.0448x over previous
#include <cuda_runtime.h>
#include <cuda_bf16.h>
#include <cstdint>
#include <math.h>

// ---------------------------------------------------------------------------
// Problem constants
// ---------------------------------------------------------------------------
#define Bn   4
#define Sn   2048
#define En   768
#define DFFn 3072
#define MTOT (Bn * Sn)          // 8192
#define LNEPS 1e-5f

// tcgen05/TMEM are "a"/family-target only; the build also runs a plain
// compute_103 PTX pass which rejects them -> gate all tcgen05 usage.
#if defined(__CUDA_ARCH__) && \
    (defined(__CUDA_ARCH_FEAT_SM103_ALL) || defined(__CUDA_ARCH_FEAT_SM100_ALL) || \
     defined(__CUDA_ARCH_FEAT_SM101_ALL) || \
     (defined(__CUDA_ARCH_SPECIFIC__)        && (__CUDA_ARCH_SPECIFIC__        >= 1000)) || \
     (defined(__CUDA_ARCH_FAMILY_SPECIFIC__) && (__CUDA_ARCH_FAMILY_SPECIFIC__ >= 1000)))
#define HAS_TC 1
#else
#define HAS_TC 0
#endif

typedef __nv_bfloat16 bf16;

// ---------------------------------------------------------------------------
// Scratch (allocation-free __device__ globals). (hi, lo) = bf16 Dekker planes.
// ---------------------------------------------------------------------------
__device__ bf16  g_qh [MTOT * En],  g_ql [MTOT * En];
__device__ bf16  g_kh [MTOT * En],  g_kl [MTOT * En];
__device__ bf16  g_vth[MTOT * En],  g_vtl[MTOT * En];     // V^T: [En, MTOT]
__device__ float g_s  [(size_t)Bn * Sn * Sn];             // raw scores (fp32)
__device__ bf16  g_ph [(size_t)Bn * Sn * Sn];             // prob planes
__device__ bf16  g_pl [(size_t)Bn * Sn * Sn];
__device__ bf16  g_hh [(size_t)MTOT * DFFn];              // MLP hidden planes
__device__ bf16  g_hl [(size_t)MTOT * DFFn];
__device__ float g_h  [MTOT * En];                        // attention out
__device__ float g_x1 [MTOT * En];
__device__ bf16  g_x1h[MTOT * En], g_x1l[MTOT * En];
__device__ float g_x2 [MTOT * En];
__device__ bf16  g_x2h[MTOT * En], g_x2l[MTOT * En];
__device__ float g_mlp[MTOT * En];
__device__ bf16  g_xh [MTOT * En], g_xl [MTOT * En];
__device__ bf16  g_kvh[MTOT * En], g_kvl[MTOT * En];
__device__ bf16  g_wh [6 * En * En + 2 * DFFn * En];      // weight hi, packed
__device__ bf16  g_wl [6 * En * En + 2 * DFFn * En];      // weight lo, packed

// ---------------------------------------------------------------------------
// Helpers
// ---------------------------------------------------------------------------
__device__ __forceinline__ uint32_t smem_u32(const void* p) {
    uint32_t a;
    asm("{ .reg .u64 t; cvta.to.shared.u64 t, %1; cvt.u32.u64 %0, t; }"
        : "=r"(a) : "l"(p));
    return a;
}

__device__ __forceinline__ void bf16_split(float x, bf16& h, bf16& l) {
    h = __float2bfloat16_rn(x);
    l = __float2bfloat16_rn(x - __bfloat162float(h));
}

#if HAS_TC
__device__ __forceinline__ uint32_t elect_one() {
    uint32_t pred;
    asm volatile("{\n\t.reg .pred p;\n\telect.sync _|p, 0xFFFFFFFF;\n\t"
                 "selp.b32 %0, 1, 0, p;\n\t}" : "=r"(pred));
    return pred;
}

#define MBARRIER_INIT(addr, cnt) \
    asm volatile("mbarrier.init.shared.b64 [%0], %1;" :: "r"(addr), "r"(cnt) : "memory")

#define MBARRIER_ARRIVE(addr) \
    asm volatile("mbarrier.arrive.shared.b64 _, [%0];" :: "r"((uint32_t)(addr)) : "memory")

#define MBARRIER_WAIT_PARITY(mbar_addr, phase_parity) do {                          \
    uint32_t _mbar = (uint32_t)(mbar_addr);                                         \
    uint32_t _par  = (uint32_t)(phase_parity);                                      \
    uint32_t _done;                                                                 \
    asm volatile("{\n\t.reg .pred p;\n\t"                                           \
        "mbarrier.try_wait.parity.acquire.cta.shared::cta.b64 p, [%1], %2;\n\t"     \
        "selp.b32 %0, 1, 0, p;\n\t}"                                                \
        : "=r"(_done) : "r"(_mbar), "r"(_par) : "memory");                          \
    if (!_done) {                                                                   \
        asm volatile("{\n\t.reg .pred P1;\n\t"                                      \
        "WAIT_LOOP_%=:\n\t"                                                         \
        "mbarrier.try_wait.parity.acquire.cta.shared::cta.b64 P1, [%0], %1, 0x989680;\n\t" \
        "@P1 bra.uni WAIT_DONE_%=;\n\t"                                             \
        "bra.uni WAIT_LOOP_%=;\n\t"                                                 \
        "WAIT_DONE_%=:\n\t}"                                                        \
        :: "r"(_mbar), "r"(_par) : "memory");                                       \
    }                                                                               \
} while (0)

#define TCGEN05_ALLOC(smem_res, ncols) \
    asm volatile("tcgen05.alloc.cta_group::1.sync.aligned.shared::cta.b32 [%0], %1;" \
                 :: "r"((uint32_t)(smem_res)), "r"((uint32_t)(ncols)) : "memory")
#define TCGEN05_DEALLOC(tmem, ncols) \
    asm volatile("tcgen05.dealloc.cta_group::1.sync.aligned.b32 %0, %1;" \
                 :: "r"(tmem), "r"((uint32_t)(ncols)))
#define TCGEN05_RELINQUISH() \
    asm volatile("tcgen05.relinquish_alloc_permit.cta_group::1.sync.aligned;")
#define TCGEN05_COMMIT(mbar) \
    asm volatile("tcgen05.commit.cta_group::1.mbarrier::arrive::one.shared::cluster.b64 [%0];" \
                 :: "r"((uint32_t)(mbar)) : "memory")
#define TCGEN05_FENCE_AFTER() \
    asm volatile("tcgen05.fence::after_thread_sync;" ::: "memory")
#define TCGEN05_FENCE_BEFORE() \
    asm volatile("tcgen05.fence::before_thread_sync;" ::: "memory")
#define TCGEN05_WAIT_LD() \
    asm volatile("tcgen05.wait::ld.sync.aligned;" ::: "memory")
#define FENCE_ASYNC_SHARED() \
    asm volatile("fence.proxy.async.shared::cta;" ::: "memory")

#define CPA_COMMIT() \
    asm volatile("cp.async.commit_group;" ::: "memory")
#define CPA_WAIT(n) \
    asm volatile("cp.async.wait_group %0;" :: "n"(n) : "memory")

#define TCGEN05_LD_32X32B_X32(r, tmem_addr) \
    asm volatile( \
        "tcgen05.ld.sync.aligned.32x32b.x32.b32 " \
        "{%0, %1, %2, %3, %4, %5, %6, %7, " \
        " %8, %9, %10, %11, %12, %13, %14, %15, " \
        " %16, %17, %18, %19, %20, %21, %22, %23, " \
        " %24, %25, %26, %27, %28, %29, %30, %31}, [%32];" \
        : "=r"((r)[0]),  "=r"((r)[1]),  "=r"((r)[2]),  "=r"((r)[3]), \
          "=r"((r)[4]),  "=r"((r)[5]),  "=r"((r)[6]),  "=r"((r)[7]), \
          "=r"((r)[8]),  "=r"((r)[9]),  "=r"((r)[10]), "=r"((r)[11]), \
          "=r"((r)[12]), "=r"((r)[13]), "=r"((r)[14]), "=r"((r)[15]), \
          "=r"((r)[16]), "=r"((r)[17]), "=r"((r)[18]), "=r"((r)[19]), \
          "=r"((r)[20]), "=r"((r)[21]), "=r"((r)[22]), "=r"((r)[23]), \
          "=r"((r)[24]), "=r"((r)[25]), "=r"((r)[26]), "=r"((r)[27]), \
          "=r"((r)[28]), "=r"((r)[29]), "=r"((r)[30]), "=r"((r)[31]) \
        : "r"(tmem_addr))

// SW128 K-major smem descriptor (validated layout).
__device__ __forceinline__ uint64_t make_desc(uint32_t addr) {
    constexpr uint64_t base =
        (uint64_t(2)  << 61) | (uint64_t(1) << 46) |
        (uint64_t(64) << 32) | (uint64_t(1) << 16);
    return base | ((uint64_t)(addr >> 4) & 0x3FFF);
}

// tcgen05.mma kind::f16 (bf16 in, fp32 acc), SS, cg1; M=128, N=256.
__device__ __forceinline__ void mma_bf16(uint32_t d_tmem, uint64_t da, uint64_t db,
                                         uint32_t idesc, uint32_t acc) {
    asm volatile(
        "{\n\t.reg .pred p;\n\tsetp.ne.u32 p, %4, 0;\n\t"
        "tcgen05.mma.cta_group::1.kind::f16 [%0], %1, %2, %3, {%5, %5, %5, %5}, p;\n\t}"
        :: "r"(d_tmem), "l"(da), "l"(db), "r"(idesc), "r"(acc), "r"(0u)
        : "memory");
}
#endif  // HAS_TC

// ---------------------------------------------------------------------------
// GEMM (NT): C[M,N] = A[M,K] * B[N,K]^T, operands = bf16 (hi, lo) planes,
// 3-pass emulation (hh + hl + lh). Tiles BM=128, BN=256, BK=64.
//   EPI 0: +bias[n]  1: relu(+bias[n])  2: *scale  3: +bias[m]  4: none
//   OUT 0: fp32 C    1: bf16 split planes (Ch, Cl)
//   causal 0: none   1: skip tiles above diagonal (score GEMM)
//          2: limit K-loop to k < rm+128 (causal PV; prob tail is exact zero)
// Warp-specialized pipeline using only session-proven primitives:
//   producers (warps 0-7): wait empty[s] -> cp.async chunk -> commit_group
//     -> wait_group 1 (previous chunk landed) -> mbarrier.arrive full[prev]
//   consumer (warp 8): wait full[s] (acquire) -> fence.proxy.async -> MMAs
//     -> tcgen05.commit empty[s]
// ---------------------------------------------------------------------------
static constexpr int SM_TILE0  = 1024;
static constexpr int SM_A_HI   = 0;          // 128x64 bf16 = 16 KB
static constexpr int SM_A_LO   = 16384;
static constexpr int SM_B_HI   = 32768;      // 256x64 bf16 = 32 KB
static constexpr int SM_B_LO   = 65536;
static constexpr int SM_STAGE  = 98304;
static constexpr int GEMM_SMEM = SM_TILE0 + 2 * SM_STAGE;   // 197632 B
static constexpr uint32_t IDESC_BF16 =
    (1u << 4) | (1u << 7) | (1u << 10) | ((256u / 8u) << 17) | ((128u / 16u) << 24);

// Control smem (within SM_TILE0): 0 = tmem ptr, 8/16 = empty[2], 32/40 = full[2].
#if HAS_TC
// Copy a ROWSx64 bf16 tile (row-major gmem, ld elems) into SW128 smem.
template<int ROWS>
__device__ __forceinline__ void cpa_plane(const bf16* __restrict__ g, int ld,
                                          long koff, uint32_t dst, int tid)
{
#pragma unroll
    for (int i = 0; i < ROWS / 32; i++) {     // ROWS*8 quads / 256 threads
        const int q   = i * 256 + tid;
        const int row = q >> 3;
        const int qc  = q & 7;
        const bf16* src = g + (long)row * ld + koff + qc * 8;
        uint32_t off = (uint32_t)(row * 128 + qc * 16);
        off ^= (off >> 3) & 0x70;             // SW128 swizzle
        asm volatile("cp.async.cg.shared.global [%0], [%1], 16;"
                     :: "r"(dst + off), "l"(src));
    }
}
#endif

template<int EPI, int OUT>
__global__ void __launch_bounds__(288, 1)
gemm_tc(const bf16* __restrict__ Ah, const bf16* __restrict__ Al,
        const bf16* __restrict__ Bh, const bf16* __restrict__ Bl,
        const float* __restrict__ bias,
        float* __restrict__ C, bf16* __restrict__ Ch, bf16* __restrict__ Cl,
        int K, int lda, int ldb, int ldc,
        long sA, long sB, long sC, float scale, int causal)
{
    extern __shared__ __align__(1024) char smem[];
    const int tid = threadIdx.x;

    const int rm = blockIdx.y * 128;
    const int cn = blockIdx.x * 256;
    if (causal == 1 && cn > rm + 127) return;   // tile fully above diagonal

    Ah += (long)blockIdx.z * sA;  Al += (long)blockIdx.z * sA;
    Bh += (long)blockIdx.z * sB;  Bl += (long)blockIdx.z * sB;
    if (OUT == 0) C += (long)blockIdx.z * sC;
    else { Ch += (long)blockIdx.z * sC; Cl += (long)blockIdx.z * sC; }

    // Causal PV: rows [rm, rm+128) only need k < rm+128 (tail probs are 0).
    int Keff = K;
    if (causal == 2) Keff = min(K, rm + 128);

#if HAS_TC
    // -------------------- tcgen05 bf16x2 (3-pass) path ---------------------
    const uint32_t smem_base = smem_u32(smem);
    const int wid = tid >> 5;

    if (tid == 0) {
        MBARRIER_INIT(smem_base + 8,  1);     // empty[0] (tcgen05 commit)
        MBARRIER_INIT(smem_base + 16, 1);     // empty[1]
        MBARRIER_INIT(smem_base + 32, 256);   // full[0]  (producer arrives)
        MBARRIER_INIT(smem_base + 40, 256);   // full[1]
    }
    if (wid == 8) TCGEN05_ALLOC(smem_base + 0, 256);
    __syncthreads();

    uint32_t tmem;
    asm volatile("ld.shared.b32 %0, [%1];" : "=r"(tmem) : "r"(smem_base));

    const int NC = Keff >> 6;
    const bf16* Abh = Ah + (long)rm * lda;
    const bf16* Abl = Al + (long)rm * lda;
    const bf16* Bbh = Bh + (long)cn * ldb;
    const bf16* Bbl = Bl + (long)cn * ldb;

    if (wid == 8) {
        // ---------------- MMA consumer warp ----------------
        for (int c = 0; c < NC; c++) {
            const int s = c & 1;
            MBARRIER_WAIT_PARITY(smem_base + 32 + s * 8, (c >> 1) & 1);
            if (elect_one()) {
                FENCE_ASYNC_SHARED();          // cp.async data -> async proxy
                const uint32_t tb = smem_base + SM_TILE0 + s * SM_STAGE;
                const uint64_t dah = make_desc(tb + SM_A_HI);
                const uint64_t dal = make_desc(tb + SM_A_LO);
                const uint64_t dbh = make_desc(tb + SM_B_HI);
                const uint64_t dbl = make_desc(tb + SM_B_LO);
#pragma unroll
                for (int st = 0; st < 4; st++)   // hi*hi  (K=16 per step)
                    mma_bf16(tmem, dah + st * 2, dbh + st * 2, IDESC_BF16,
                             (c == 0 && st == 0) ? 0u : 1u);
#pragma unroll
                for (int st = 0; st < 4; st++)   // hi*lo
                    mma_bf16(tmem, dah + st * 2, dbl + st * 2, IDESC_BF16, 1u);
#pragma unroll
                for (int st = 0; st < 4; st++)   // lo*hi
                    mma_bf16(tmem, dal + st * 2, dbh + st * 2, IDESC_BF16, 1u);
                TCGEN05_COMMIT(smem_base + 8 + s * 8);
            }
        }
    } else {
        // ---------------- cp.async producer warps (256 threads) ------------
        for (int c = 0; c < NC; c++) {
            const int s = c & 1;
            if (c >= 2)  // stage s still owned by MMA of chunk c-2
                MBARRIER_WAIT_PARITY(smem_base + 8 + s * 8, ((c >> 1) + 1) & 1);
            const uint32_t tn = smem_base + SM_TILE0 + s * SM_STAGE;
            const long koff = (long)c << 6;
            cpa_plane<128>(Abh, lda, koff, tn + SM_A_HI, tid);
            cpa_plane<128>(Abl, lda, koff, tn + SM_A_LO, tid);
            cpa_plane<256>(Bbh, ldb, koff, tn + SM_B_HI, tid);
            cpa_plane<256>(Bbl, ldb, koff, tn + SM_B_LO, tid);
            CPA_COMMIT();
            if (c >= 1) {
                CPA_WAIT(1);                   // chunk c-1's group has landed
                MBARRIER_ARRIVE(smem_base + 32 + (s ^ 1) * 8);   // full[c-1]
            }
        }
        CPA_WAIT(0);                           // last chunk landed
        MBARRIER_ARRIVE(smem_base + 32 + ((NC - 1) & 1) * 8);    // full[NC-1]
    }
    __syncthreads();

    // wait for the last chunk's MMA completion
    MBARRIER_WAIT_PARITY(smem_base + 8 + ((NC - 1) & 1) * 8, ((NC - 1) >> 1) & 1);
    TCGEN05_FENCE_AFTER();

    if (wid < 4) {
        const int lane = tid & 31;
        const int m = rm + wid * 32 + lane;      // TMEM lane -> D row
        const float biasm = (EPI == 3) ? bias[m] : 0.f;
#pragma unroll
        for (int seg = 0; seg < 8; seg++) {      // 256 cols
            uint32_t r[32];
            TCGEN05_LD_32X32B_X32(r, tmem + seg * 32);
            TCGEN05_WAIT_LD();
#pragma unroll
            for (int j = 0; j < 32; j += 4) {
                float v[4];
#pragma unroll
                for (int t = 0; t < 4; t++) {
                    const int n = cn + seg * 32 + j + t;
                    float x = __uint_as_float(r[j + t]);
                    if (EPI == 0)      x += bias[n];
                    else if (EPI == 1) x = fmaxf(x + bias[n], 0.f);
                    else if (EPI == 2) x *= scale;
                    else if (EPI == 3) x += biasm;
                    v[t] = x;
                }
                const long base = (long)m * ldc + cn + seg * 32 + j;
                if (OUT == 0) {
                    *(float4*)(C + base) = make_float4(v[0], v[1], v[2], v[3]);
                } else {
                    __nv_bfloat162 h0, h1, l0, l1;
                    bf16 hh, ll;
                    bf16_split(v[0], hh, ll); h0.x = hh; l0.x = ll;
                    bf16_split(v[1], hh, ll); h0.y = hh; l0.y = ll;
                    bf16_split(v[2], hh, ll); h1.x = hh; l1.x = ll;
                    bf16_split(v[3], hh, ll); h1.y = hh; l1.y = ll;
                    ((__nv_bfloat162*)(Ch + base))[0] = h0;
                    ((__nv_bfloat162*)(Ch + base))[1] = h1;
                    ((__nv_bfloat162*)(Cl + base))[0] = l0;
                    ((__nv_bfloat162*)(Cl + base))[1] = l1;
                }
            }
        }
        TCGEN05_FENCE_BEFORE();
    }
    __syncthreads();
    if (wid == 8) {
        TCGEN05_RELINQUISH();
        TCGEN05_DEALLOC(tmem, 256);
    }
#else
    // --------------------- SIMT fp32 fallback path -------------------------
    constexpr int BK = 16;
    float (*As)[132] = (float (*)[132])(smem);
    float (*Bs)[132] = (float (*)[132])(smem + BK * 132 * sizeof(float));
    const int tx = tid & 15, ty = tid >> 4;

    for (int half = 0; half < 2; half++) {
        const int cnh = cn + half * 128;
        float acc[8][8];
#pragma unroll
        for (int i = 0; i < 8; i++)
#pragma unroll
            for (int j = 0; j < 8; j++) acc[i][j] = 0.f;

        for (int k0 = 0; k0 < Keff; k0 += BK) {
            if (tid < 256) {
#pragma unroll
                for (int i = 0; i < 2; i++) {
                    const int q = i * 256 + tid;
                    const int row = q >> 1, kc = (q & 1) * 8;
#pragma unroll
                    for (int u = 0; u < 8; u++) {
                        const long ai = (long)(rm + row) * lda + k0 + kc + u;
                        const long bi = (long)(cnh + row) * ldb + k0 + kc + u;
                        As[kc + u][row] = __bfloat162float(Ah[ai]) + __bfloat162float(Al[ai]);
                        Bs[kc + u][row] = __bfloat162float(Bh[bi]) + __bfloat162float(Bl[bi]);
                    }
                }
            }
            __syncthreads();
            if (tid < 256) {
#pragma unroll
                for (int kk = 0; kk < BK; kk++) {
                    float a[8], b[8];
#pragma unroll
                    for (int i = 0; i < 8; i++) a[i] = As[kk][ty * 8 + i];
#pragma unroll
                    for (int j = 0; j < 8; j++) b[j] = Bs[kk][tx * 8 + j];
#pragma unroll
                    for (int i = 0; i < 8; i++)
#pragma unroll
                        for (int j = 0; j < 8; j++) acc[i][j] += a[i] * b[j];
                }
            }
            __syncthreads();
        }

        if (tid < 256) {
#pragma unroll
            for (int i = 0; i < 8; i++) {
                const int m = rm + ty * 8 + i;
                const float biasm = (EPI == 3) ? bias[m] : 0.f;
#pragma unroll
                for (int j = 0; j < 8; j++) {
                    const int n = cnh + tx * 8 + j;
                    float x = acc[i][j];
                    if (EPI == 0)      x += bias[n];
                    else if (EPI == 1) x = fmaxf(x + bias[n], 0.f);
                    else if (EPI == 2) x *= scale;
                    else if (EPI == 3) x += biasm;
                    if (OUT == 0) C[(long)m * ldc + n] = x;
                    else {
                        bf16 hh, ll;
                        bf16_split(x, hh, ll);
                        Ch[(long)m * ldc + n] = hh;
                        Cl[(long)m * ldc + n] = ll;
                    }
                }
            }
        }
        __syncthreads();
    }
#endif
}

// ---------------------------------------------------------------------------
// Elementwise bf16 Dekker split; split2 handles two tensors via blockIdx.y.
// ---------------------------------------------------------------------------
__device__ __forceinline__ void split_body(const float* __restrict__ src,
                                           bf16* __restrict__ hi,
                                           bf16* __restrict__ lo, long n4)
{
    for (long i = blockIdx.x * 256L + threadIdx.x; i < n4; i += (long)gridDim.x * 256) {
        const float4 f = *(const float4*)(src + i * 4);
        __nv_bfloat162 h0, h1, l0, l1;
        bf16 hh, ll;
        bf16_split(f.x, hh, ll); h0.x = hh; l0.x = ll;
        bf16_split(f.y, hh, ll); h0.y = hh; l0.y = ll;
        bf16_split(f.z, hh, ll); h1.x = hh; l1.x = ll;
        bf16_split(f.w, hh, ll); h1.y = hh; l1.y = ll;
        ((__nv_bfloat162*)(hi + i * 4))[0] = h0;
        ((__nv_bfloat162*)(hi + i * 4))[1] = h1;
        ((__nv_bfloat162*)(lo + i * 4))[0] = l0;
        ((__nv_bfloat162*)(lo + i * 4))[1] = l1;
    }
}

__global__ void __launch_bounds__(256)
split2_k(const float* __restrict__ s0, bf16* __restrict__ h0, bf16* __restrict__ l0,
         const float* __restrict__ s1, bf16* __restrict__ h1, bf16* __restrict__ l1,
         long n4)
{
    if (blockIdx.y == 0) split_body(s0, h0, l0, n4);
    else                 split_body(s1, h1, l1, n4);
}

// ---------------------------------------------------------------------------
// Row softmax over fp32 scores -> bf16 (hi, lo) prob planes.
// Causal rows: L=i+1; zero-fill only up to the 128-row diagonal block end.
// ---------------------------------------------------------------------------
__global__ void __launch_bounds__(256)
softmax_k(const float* __restrict__ S, bf16* __restrict__ Ph,
          bf16* __restrict__ Pl, int causal)
{
    const int row = blockIdx.x;
    const int b = row >> 11;
    const int i = row & 2047;
    const float* p = S + (long)b * Sn * Sn + (long)i * Sn;
    bf16* ph = Ph + (long)b * Sn * Sn + (long)i * Sn;
    bf16* pl = Pl + (long)b * Sn * Sn + (long)i * Sn;
    const int L = causal ? (i + 1) : Sn;
    const int FILL = causal ? (((i >> 7) + 1) << 7) : Sn;
    const int tid = threadIdx.x;
    __shared__ float sh[8];

    float m = -3.4e38f;
    for (int j = tid; j < L; j += 256) m = fmaxf(m, p[j]);
#pragma unroll
    for (int o = 16; o > 0; o >>= 1) m = fmaxf(m, __shfl_xor_sync(~0u, m, o));
    if ((tid & 31) == 0) sh[tid >> 5] = m;
    __syncthreads();
    m = sh[0];
#pragma unroll
    for (int w = 1; w < 8; w++) m = fmaxf(m, sh[w]);

    float s = 0.f;
    for (int j = tid; j < L; j += 256) s += __expf(p[j] - m);
#pragma unroll
    for (int o = 16; o > 0; o >>= 1) s += __shfl_xor_sync(~0u, s, o);
    __syncthreads();
    if ((tid & 31) == 0) sh[tid >> 5] = s;
    __syncthreads();
    s = 0.f;
#pragma unroll
    for (int w = 0; w < 8; w++) s += sh[w];
    const float inv = 1.f / s;

    for (int j = tid; j < L; j += 256) {
        const float v = __expf(p[j] - m) * inv;
        bf16 hh, ll;
        bf16_split(v, hh, ll);
        ph[j] = hh;
        pl[j] = ll;
    }
    const bf16 z = __float2bfloat16(0.f);
    for (int j = L + tid; j < FILL; j += 256) { ph[j] = z; pl[j] = z; }
}

// ---------------------------------------------------------------------------
// y = LayerNorm(x + h) * g + b; optional bf16 split planes (yh, yl).
// ---------------------------------------------------------------------------
__global__ void __launch_bounds__(256)
add_ln_k(const float* __restrict__ x, const float* __restrict__ h,
         const float* __restrict__ g, const float* __restrict__ bt,
         float* __restrict__ y, bf16* __restrict__ yh, bf16* __restrict__ yl)
{
    const long row = blockIdx.x;
    const float* xr = x + row * En;
    const float* hr = h + row * En;
    const int tid = threadIdx.x;

    float v[3];
    float s = 0.f, s2 = 0.f;
#pragma unroll
    for (int t = 0; t < 3; t++) {
        const int c = tid + t * 256;
        const float u = xr[c] + hr[c];
        v[t] = u;
        s += u;
        s2 += u * u;
    }
    __shared__ float shA[8], shB[8];
#pragma unroll
    for (int o = 16; o > 0; o >>= 1) {
        s  += __shfl_xor_sync(~0u, s,  o);
        s2 += __shfl_xor_sync(~0u, s2, o);
    }
    if ((tid & 31) == 0) { shA[tid >> 5] = s; shB[tid >> 5] = s2; }
    __syncthreads();
    s = 0.f; s2 = 0.f;
#pragma unroll
    for (int w = 0; w < 8; w++) { s += shA[w]; s2 += shB[w]; }

    const float mu   = s * (1.f / En);
    const float var  = s2 * (1.f / En) - mu * mu;
    const float rstd = rsqrtf(var + LNEPS);
#pragma unroll
    for (int t = 0; t < 3; t++) {
        const int c = tid + t * 256;
        const float o = (v[t] - mu) * rstd * g[c] + bt[c];
        y[row * En + c] = o;
        if (yh) {
            bf16 hh, ll;
            bf16_split(o, hh, ll);
            yh[row * En + c] = hh;
            yl[row * En + c] = ll;
        }
    }
}

// ---------------------------------------------------------------------------
// Host launcher
// ---------------------------------------------------------------------------
extern "C" void kernel_launch(void* const* d_in, const int* in_sizes, int n_in,
                              void* d_out, int out_size)
{
    const float* x     = (const float*)d_in[0];
    const float* kv    = (const float*)d_in[1];
    const float* wq_w  = (const float*)d_in[2];
    const float* wq_b  = (const float*)d_in[3];
    const float* wk_w  = (const float*)d_in[4];
    const float* wk_b  = (const float*)d_in[5];
    const float* wv_w  = (const float*)d_in[6];
    const float* wv_b  = (const float*)d_in[7];
    const float* ln1_g = (const float*)d_in[8];
    const float* ln1_b = (const float*)d_in[9];
    const float* wq2_w = (const float*)d_in[10];
    const float* wq2_b = (const float*)d_in[11];
    const float* wk2_w = (const float*)d_in[12];
    const float* wk2_b = (const float*)d_in[13];
    const float* wv2_w = (const float*)d_in[14];
    const float* wv2_b = (const float*)d_in[15];
    const float* ln2_g = (const float*)d_in[16];
    const float* ln2_b = (const float*)d_in[17];
    const float* w1    = (const float*)d_in[18];
    const float* b1    = (const float*)d_in[19];
    const float* w2    = (const float*)d_in[20];
    const float* b2    = (const float*)d_in[21];
    const float* ln3_g = (const float*)d_in[22];
    const float* ln3_b = (const float*)d_in[23];
    float* out = (float*)d_out;

    bf16 *qh, *ql, *kh, *kl, *vth, *vtl, *prh, *prl, *hh, *hl;
    bf16 *x1h, *x1l, *x2h, *x2l, *xh, *xl, *kvh, *kvl, *wh, *wl;
    float *ps, *phf, *x1, *x2, *pmlp;
    cudaGetSymbolAddress((void**)&qh,  g_qh);   cudaGetSymbolAddress((void**)&ql,  g_ql);
    cudaGetSymbolAddress((void**)&kh,  g_kh);   cudaGetSymbolAddress((void**)&kl,  g_kl);
    cudaGetSymbolAddress((void**)&vth, g_vth);  cudaGetSymbolAddress((void**)&vtl, g_vtl);
    cudaGetSymbolAddress((void**)&prh, g_ph);   cudaGetSymbolAddress((void**)&prl, g_pl);
    cudaGetSymbolAddress((void**)&hh,  g_hh);   cudaGetSymbolAddress((void**)&hl,  g_hl);
    cudaGetSymbolAddress((void**)&x1h, g_x1h);  cudaGetSymbolAddress((void**)&x1l, g_x1l);
    cudaGetSymbolAddress((void**)&x2h, g_x2h);  cudaGetSymbolAddress((void**)&x2l, g_x2l);
    cudaGetSymbolAddress((void**)&xh,  g_xh);   cudaGetSymbolAddress((void**)&xl,  g_xl);
    cudaGetSymbolAddress((void**)&kvh, g_kvh);  cudaGetSymbolAddress((void**)&kvl, g_kvl);
    cudaGetSymbolAddress((void**)&wh,  g_wh);   cudaGetSymbolAddress((void**)&wl,  g_wl);
    cudaGetSymbolAddress((void**)&ps,  g_s);
    cudaGetSymbolAddress((void**)&phf, g_h);
    cudaGetSymbolAddress((void**)&x1,  g_x1);
    cudaGetSymbolAddress((void**)&x2,  g_x2);
    cudaGetSymbolAddress((void**)&pmlp, g_mlp);

    const long oWQ = 0, oWK = oWQ + (long)En * En, oWV = oWK + (long)En * En;
    const long oWQ2 = oWV + (long)En * En, oWK2 = oWQ2 + (long)En * En;
    const long oWV2 = oWK2 + (long)En * En;
    const long oW1 = oWV2 + (long)En * En, oW2 = oW1 + (long)DFFn * En;

    cudaFuncSetAttribute(gemm_tc<0,1>, cudaFuncAttributeMaxDynamicSharedMemorySize, GEMM_SMEM);
    cudaFuncSetAttribute(gemm_tc<3,1>, cudaFuncAttributeMaxDynamicSharedMemorySize, GEMM_SMEM);
    cudaFuncSetAttribute(gemm_tc<2,0>, cudaFuncAttributeMaxDynamicSharedMemorySize, GEMM_SMEM);
    cudaFuncSetAttribute(gemm_tc<4,0>, cudaFuncAttributeMaxDynamicSharedMemorySize, GEMM_SMEM);
    cudaFuncSetAttribute(gemm_tc<1,1>, cudaFuncAttributeMaxDynamicSharedMemorySize, GEMM_SMEM);
    cudaFuncSetAttribute(gemm_tc<1,0>, cudaFuncAttributeMaxDynamicSharedMemorySize, GEMM_SMEM);

    const float scale = 0.03608439182435161f;  // 1/sqrt(768)
    const long sQE = (long)Sn * En;
    const long sSS = (long)Sn * Sn;

    const dim3 gProj(En / 256, MTOT / 128, 1);       // 3 x 64
    const dim3 gVT(MTOT / 256, En / 128, 1);         // 32 x 6
    const dim3 gScore(Sn / 256, Sn / 128, Bn);       // 8 x 16 x 4
    const dim3 gPV(En / 256, Sn / 128, Bn);          // 3 x 16 x 4
    const dim3 gFF1(DFFn / 256, MTOT / 128, 1);      // 12 x 64
    const dim3 gFF2(En / 256, MTOT / 128, 1);        // 3 x 64

    const long nXY = (long)MTOT * En / 4;
    const long nW  = (long)En * En / 4;
    const long nFF = (long)DFFn * En / 4;

    // Launch order puts the causal score GEMM at index 5 (ncu -s 5 -c 1).
    split2_k<<<dim3(296, 2), 256>>>(x, xh, xl, kv, kvh, kvl, nXY);
    split2_k<<<dim3(148, 2), 256>>>(wq_w, wh + oWQ, wl + oWQ,
                                    wk_w, wh + oWK, wl + oWK, nW);
    gemm_tc<0,1><<<gProj, 288, GEMM_SMEM>>>(xh, xl, wh + oWQ, wl + oWQ, wq_b,
                                            nullptr, qh, ql, En, En, En, En, 0, 0, 0, 1.f, 0);
    gemm_tc<0,1><<<gProj, 288, GEMM_SMEM>>>(xh, xl, wh + oWK, wl + oWK, wk_b,
                                            nullptr, kh, kl, En, En, En, En, 0, 0, 0, 1.f, 0);
    split2_k<<<dim3(148, 2), 256>>>(wv_w,  wh + oWV,  wl + oWV,
                                    wv2_w, wh + oWV2, wl + oWV2, nW);
    // 5: causal score GEMM  <-- profiled launch
    gemm_tc<2,0><<<gScore, 288, GEMM_SMEM>>>(qh, ql, kh, kl, nullptr,
                                             ps, nullptr, nullptr, En, En, En, Sn,
                                             sQE, sQE, sSS, scale, 1);
    gemm_tc<3,1><<<gVT, 288, GEMM_SMEM>>>(wh + oWV, wl + oWV, xh, xl, wv_b,
                                          nullptr, vth, vtl, En, En, En, MTOT, 0, 0, 0, 1.f, 0);
    softmax_k<<<MTOT, 256>>>(ps, prh, prl, 1);
    gemm_tc<4,0><<<gPV, 288, GEMM_SMEM>>>(prh, prl, vth, vtl, nullptr,
                                          phf, nullptr, nullptr, Sn, Sn, MTOT, En,
                                          sSS, (long)Sn, sQE, 1.f, 2);
    add_ln_k<<<MTOT, 256>>>(x, phf, ln1_g, ln1_b, x1, x1h, x1l);

    // ---- cross-attention ----
    split2_k<<<dim3(148, 2), 256>>>(wq2_w, wh + oWQ2, wl + oWQ2,
                                    wk2_w, wh + oWK2, wl + oWK2, nW);
    gemm_tc<0,1><<<gProj, 288, GEMM_SMEM>>>(x1h, x1l, wh + oWQ2, wl + oWQ2, wq2_b,
                                            nullptr, qh, ql, En, En, En, En, 0, 0, 0, 1.f, 0);
    gemm_tc<0,1><<<gProj, 288, GEMM_SMEM>>>(kvh, kvl, wh + oWK2, wl + oWK2, wk2_b,
                                            nullptr, kh, kl, En, En, En, En, 0, 0, 0, 1.f, 0);
    gemm_tc<3,1><<<gVT, 288, GEMM_SMEM>>>(wh + oWV2, wl + oWV2, kvh, kvl, wv2_b,
                                          nullptr, vth, vtl, En, En, En, MTOT, 0, 0, 0, 1.f, 0);
    gemm_tc<2,0><<<gScore, 288, GEMM_SMEM>>>(qh, ql, kh, kl, nullptr,
                                             ps, nullptr, nullptr, En, En, En, Sn,
                                             sQE, sQE, sSS, scale, 0);
    softmax_k<<<MTOT, 256>>>(ps, prh, prl, 0);
    gemm_tc<4,0><<<gPV, 288, GEMM_SMEM>>>(prh, prl, vth, vtl, nullptr,
                                          phf, nullptr, nullptr, Sn, Sn, MTOT, En,
                                          sSS, (long)Sn, sQE, 1.f, 0);
    add_ln_k<<<MTOT, 256>>>(x1, phf, ln2_g, ln2_b, x2, x2h, x2l);

    // ---- MLP ----
    split2_k<<<dim3(592, 2), 256>>>(w1, wh + oW1, wl + oW1,
                                    w2, wh + oW2, wl + oW2, nFF);
    gemm_tc<1,1><<<gFF1, 288, GEMM_SMEM>>>(x2h, x2l, wh + oW1, wl + oW1, b1,
                                           nullptr, hh, hl, En, En, En, DFFn, 0, 0, 0, 1.f, 0);
    gemm_tc<1,0><<<gFF2, 288, GEMM_SMEM>>>(hh, hl, wh + oW2, wl + oW2, b2,
                                           pmlp, nullptr, nullptr, DFFn, DFFn, DFFn, En, 0, 0, 0, 1.f, 0);
    add_ln_k<<<MTOT, 256>>>(x2, pmlp, ln3_g, ln3_b, out, nullptr, nullptr);
}

// round 9
// speedup vs baseline: 2.1316x; 1.1387x over previous
#include <cuda.h>
#include <cuda_runtime.h>
#include <cuda_bf16.h>
#include <cstdint>
#include <math.h>

// ---------------------------------------------------------------------------
// Problem constants
// ---------------------------------------------------------------------------
#define Bn   4
#define Sn   2048
#define En   768
#define DFFn 3072
#define MTOT (Bn * Sn)          // 8192
#define LNEPS 1e-5f

// tcgen05/TMEM are "a"/family-target only; the build also runs a plain
// compute_103 PTX pass which rejects them -> gate all tcgen05 usage.
#if defined(__CUDA_ARCH__) && \
    (defined(__CUDA_ARCH_FEAT_SM103_ALL) || defined(__CUDA_ARCH_FEAT_SM100_ALL) || \
     defined(__CUDA_ARCH_FEAT_SM101_ALL) || \
     (defined(__CUDA_ARCH_SPECIFIC__)        && (__CUDA_ARCH_SPECIFIC__        >= 1000)) || \
     (defined(__CUDA_ARCH_FAMILY_SPECIFIC__) && (__CUDA_ARCH_FAMILY_SPECIFIC__ >= 1000)))
#define HAS_TC 1
#else
#define HAS_TC 0
#endif

typedef __nv_bfloat16 bf16;

// ---------------------------------------------------------------------------
// Scratch (allocation-free __device__ globals). (hi, lo) = bf16 Dekker planes.
// 128B alignment for TMA global addresses.
// ---------------------------------------------------------------------------
__device__ __align__(128) bf16  g_qh [MTOT * En],  g_ql [MTOT * En];
__device__ __align__(128) bf16  g_kh [MTOT * En],  g_kl [MTOT * En];
__device__ __align__(128) bf16  g_vth[MTOT * En],  g_vtl[MTOT * En];   // V^T: [En, MTOT]
__device__ __align__(128) float g_s  [(size_t)Bn * Sn * Sn];           // raw scores
__device__ __align__(128) bf16  g_ph [(size_t)Bn * Sn * Sn];           // prob planes
__device__ __align__(128) bf16  g_pl [(size_t)Bn * Sn * Sn];
__device__ __align__(128) bf16  g_hh [(size_t)MTOT * DFFn];            // MLP hidden
__device__ __align__(128) bf16  g_hl [(size_t)MTOT * DFFn];
__device__ __align__(128) float g_h  [MTOT * En];                      // attn out
__device__ __align__(128) float g_x1 [MTOT * En];
__device__ __align__(128) bf16  g_x1h[MTOT * En], g_x1l[MTOT * En];
__device__ __align__(128) float g_x2 [MTOT * En];
__device__ __align__(128) bf16  g_x2h[MTOT * En], g_x2l[MTOT * En];
__device__ __align__(128) float g_mlp[MTOT * En];
__device__ __align__(128) bf16  g_xh [MTOT * En], g_xl [MTOT * En];
__device__ __align__(128) bf16  g_kvh[MTOT * En], g_kvl[MTOT * En];
__device__ __align__(128) bf16  g_wh [6 * En * En + 2 * DFFn * En];
__device__ __align__(128) bf16  g_wl [6 * En * En + 2 * DFFn * En];

// ---------------------------------------------------------------------------
// Helpers
// ---------------------------------------------------------------------------
__device__ __forceinline__ uint32_t smem_u32(const void* p) {
    uint32_t a;
    asm("{ .reg .u64 t; cvta.to.shared.u64 t, %1; cvt.u32.u64 %0, t; }"
        : "=r"(a) : "l"(p));
    return a;
}

__device__ __forceinline__ void bf16_split(float x, bf16& h, bf16& l) {
    h = __float2bfloat16_rn(x);
    l = __float2bfloat16_rn(x - __bfloat162float(h));
}

#if HAS_TC
__device__ __forceinline__ uint32_t elect_one() {
    uint32_t pred;
    asm volatile("{\n\t.reg .pred p;\n\telect.sync _|p, 0xFFFFFFFF;\n\t"
                 "selp.b32 %0, 1, 0, p;\n\t}" : "=r"(pred));
    return pred;
}

#define MBARRIER_INIT(addr, cnt) \
    asm volatile("mbarrier.init.shared.b64 [%0], %1;" :: "r"(addr), "r"(cnt) : "memory")

#define MBARRIER_EXPECT_TX(addr, bytes) \
    asm volatile("mbarrier.arrive.expect_tx.shared.b64 _, [%0], %1;" \
                 :: "r"((uint32_t)(addr)), "r"((uint32_t)(bytes)) : "memory")

#define MBARRIER_WAIT_PARITY(mbar_addr, phase_parity) do {                          \
    uint32_t _mbar = (uint32_t)(mbar_addr);                                         \
    uint32_t _par  = (uint32_t)(phase_parity);                                      \
    uint32_t _done;                                                                 \
    asm volatile("{\n\t.reg .pred p;\n\t"                                           \
        "mbarrier.try_wait.parity.acquire.cta.shared::cta.b64 p, [%1], %2;\n\t"     \
        "selp.b32 %0, 1, 0, p;\n\t}"                                                \
        : "=r"(_done) : "r"(_mbar), "r"(_par) : "memory");                          \
    if (!_done) {                                                                   \
        asm volatile("{\n\t.reg .pred P1;\n\t"                                      \
        "WAIT_LOOP_%=:\n\t"                                                         \
        "mbarrier.try_wait.parity.acquire.cta.shared::cta.b64 P1, [%0], %1, 0x989680;\n\t" \
        "@P1 bra.uni WAIT_DONE_%=;\n\t"                                             \
        "bra.uni WAIT_LOOP_%=;\n\t"                                                 \
        "WAIT_DONE_%=:\n\t}"                                                        \
        :: "r"(_mbar), "r"(_par) : "memory");                                       \
    }                                                                               \
} while (0)

#define TCGEN05_ALLOC(smem_res, ncols) \
    asm volatile("tcgen05.alloc.cta_group::1.sync.aligned.shared::cta.b32 [%0], %1;" \
                 :: "r"((uint32_t)(smem_res)), "r"((uint32_t)(ncols)) : "memory")
#define TCGEN05_DEALLOC(tmem, ncols) \
    asm volatile("tcgen05.dealloc.cta_group::1.sync.aligned.b32 %0, %1;" \
                 :: "r"(tmem), "r"((uint32_t)(ncols)))
#define TCGEN05_RELINQUISH() \
    asm volatile("tcgen05.relinquish_alloc_permit.cta_group::1.sync.aligned;")
#define TCGEN05_COMMIT(mbar) \
    asm volatile("tcgen05.commit.cta_group::1.mbarrier::arrive::one.shared::cluster.b64 [%0];" \
                 :: "r"((uint32_t)(mbar)) : "memory")
#define TCGEN05_FENCE_AFTER() \
    asm volatile("tcgen05.fence::after_thread_sync;" ::: "memory")
#define TCGEN05_FENCE_BEFORE() \
    asm volatile("tcgen05.fence::before_thread_sync;" ::: "memory")
#define TCGEN05_WAIT_LD() \
    asm volatile("tcgen05.wait::ld.sync.aligned;" ::: "memory")

// 2D TMA load global->shared::cta with mbarrier complete_tx (validated pattern).
#define TMA_LOAD_2D(smem_addr, map, cx, cy, mbar) \
    asm volatile( \
        "cp.async.bulk.tensor.2d.shared::cta.global.tile.mbarrier::complete_tx::bytes " \
        "[%0], [%1, {%2, %3}], [%4];" \
        :: "r"((uint32_t)(smem_addr)), "l"(map), "r"((int)(cx)), "r"((int)(cy)), \
           "r"((uint32_t)(mbar)) : "memory")

#define TCGEN05_LD_32X32B_X32(r, tmem_addr) \
    asm volatile( \
        "tcgen05.ld.sync.aligned.32x32b.x32.b32 " \
        "{%0, %1, %2, %3, %4, %5, %6, %7, " \
        " %8, %9, %10, %11, %12, %13, %14, %15, " \
        " %16, %17, %18, %19, %20, %21, %22, %23, " \
        " %24, %25, %26, %27, %28, %29, %30, %31}, [%32];" \
        : "=r"((r)[0]),  "=r"((r)[1]),  "=r"((r)[2]),  "=r"((r)[3]), \
          "=r"((r)[4]),  "=r"((r)[5]),  "=r"((r)[6]),  "=r"((r)[7]), \
          "=r"((r)[8]),  "=r"((r)[9]),  "=r"((r)[10]), "=r"((r)[11]), \
          "=r"((r)[12]), "=r"((r)[13]), "=r"((r)[14]), "=r"((r)[15]), \
          "=r"((r)[16]), "=r"((r)[17]), "=r"((r)[18]), "=r"((r)[19]), \
          "=r"((r)[20]), "=r"((r)[21]), "=r"((r)[22]), "=r"((r)[23]), \
          "=r"((r)[24]), "=r"((r)[25]), "=r"((r)[26]), "=r"((r)[27]), \
          "=r"((r)[28]), "=r"((r)[29]), "=r"((r)[30]), "=r"((r)[31]) \
        : "r"(tmem_addr))

// SW128 K-major smem descriptor (validated layout).
__device__ __forceinline__ uint64_t make_desc(uint32_t addr) {
    constexpr uint64_t base =
        (uint64_t(2)  << 61) | (uint64_t(1) << 46) |
        (uint64_t(64) << 32) | (uint64_t(1) << 16);
    return base | ((uint64_t)(addr >> 4) & 0x3FFF);
}

// tcgen05.mma kind::f16 (bf16 in, fp32 acc), SS, cg1; M=128, N=256.
__device__ __forceinline__ void mma_bf16(uint32_t d_tmem, uint64_t da, uint64_t db,
                                         uint32_t idesc, uint32_t acc) {
    asm volatile(
        "{\n\t.reg .pred p;\n\tsetp.ne.u32 p, %4, 0;\n\t"
        "tcgen05.mma.cta_group::1.kind::f16 [%0], %1, %2, %3, {%5, %5, %5, %5}, p;\n\t}"
        :: "r"(d_tmem), "l"(da), "l"(db), "r"(idesc), "r"(acc), "r"(0u)
        : "memory");
}
#endif  // HAS_TC

// ---------------------------------------------------------------------------
// GEMM (NT): C[M,N] = A[M,K] * B[N,K]^T, operands = bf16 (hi, lo) planes,
// 3-pass emulation. Tiles BM=128, BN=256, BK=64. TMA loads + tcgen05 MMA.
//   EPI 0: +bias[n]  1: relu(+bias[n])  2: *scale  3: +bias[m]  4: none
//   OUT 0: fp32 C    1: bf16 split planes (Ch, Cl)
//   causal 0: none   1: skip tiles above diagonal   2: K-limit (causal PV)
// Warps: 0-3 epilogue, 4 = TMA producer (1 thread), 5 = MMA consumer,
//        6-7 idle. 2-stage ring: full[s] via expect_tx, empty[s] via commit.
// ---------------------------------------------------------------------------
static constexpr int SM_TILE0  = 1024;
static constexpr int SM_A_HI   = 0;          // 128x64 bf16 = 16 KB
static constexpr int SM_A_LO   = 16384;
static constexpr int SM_B_HI   = 32768;      // 256x64 bf16 = 32 KB
static constexpr int SM_B_LO   = 65536;
static constexpr int SM_STAGE  = 98304;
static constexpr int GEMM_SMEM = SM_TILE0 + 2 * SM_STAGE;   // 197632 B
static constexpr uint32_t IDESC_BF16 =
    (1u << 4) | (1u << 7) | (1u << 10) | ((256u / 8u) << 17) | ((128u / 16u) << 24);

template<int EPI, int OUT>
__global__ void __launch_bounds__(256, 1)
gemm_tc(const __grid_constant__ CUtensorMap tmAh,
        const __grid_constant__ CUtensorMap tmAl,
        const __grid_constant__ CUtensorMap tmBh,
        const __grid_constant__ CUtensorMap tmBl,
        const bf16* __restrict__ Ah, const bf16* __restrict__ Al,   // fallback
        const bf16* __restrict__ Bh, const bf16* __restrict__ Bl,   // fallback
        const float* __restrict__ bias,
        float* __restrict__ C, bf16* __restrict__ Ch, bf16* __restrict__ Cl,
        int K, int lda, int ldb, int ldc,
        int aYoff, int bXoff, int bYoff, long sC, float scale, int causal)
{
    extern __shared__ __align__(1024) char smem[];
    const int tid = threadIdx.x;

    const int rm = blockIdx.y * 128;
    const int cn = blockIdx.x * 256;
    if (causal == 1 && cn > rm + 127) return;   // tile fully above diagonal

    if (OUT == 0) C += (long)blockIdx.z * sC;
    else { Ch += (long)blockIdx.z * sC; Cl += (long)blockIdx.z * sC; }

    // Causal PV: rows [rm, rm+128) only need k < rm+128 (tail probs are 0).
    int Keff = K;
    if (causal == 2) Keff = min(K, rm + 128);

#if HAS_TC
    // ------------------- TMA + tcgen05 bf16x2 (3-pass) ---------------------
    const uint32_t smem_base = smem_u32(smem);
    const int wid = tid >> 5;

    if (tid == 0) {
        MBARRIER_INIT(smem_base + 8,  1);     // empty[0] (tcgen05 commit)
        MBARRIER_INIT(smem_base + 16, 1);     // empty[1]
        MBARRIER_INIT(smem_base + 32, 1);     // full[0]  (expect_tx)
        MBARRIER_INIT(smem_base + 40, 1);     // full[1]
    }
    if (wid == 5) TCGEN05_ALLOC(smem_base + 0, 256);
    __syncthreads();

    uint32_t tmem;
    asm volatile("ld.shared.b32 %0, [%1];" : "=r"(tmem) : "r"(smem_base));

    const int NC = Keff >> 6;
    const int ay = blockIdx.z * aYoff + rm;
    const int by = blockIdx.z * bYoff + cn;
    const int bx0 = blockIdx.z * bXoff;

    if (wid == 4 && elect_one()) {
        // ---------------- TMA producer (single thread) ----------------
        for (int c = 0; c < NC; c++) {
            const int s = c & 1;
            if (c >= 2)  // stage s still owned by MMA of chunk c-2
                MBARRIER_WAIT_PARITY(smem_base + 8 + s * 8, ((c >> 1) + 1) & 1);
            const uint32_t fullb = smem_base + 32 + s * 8;
            MBARRIER_EXPECT_TX(fullb, (uint32_t)SM_STAGE);
            const uint32_t tn = smem_base + SM_TILE0 + s * SM_STAGE;
            const int kx = c << 6;
            TMA_LOAD_2D(tn + SM_A_HI, &tmAh, kx,       ay, fullb);
            TMA_LOAD_2D(tn + SM_A_LO, &tmAl, kx,       ay, fullb);
            TMA_LOAD_2D(tn + SM_B_HI, &tmBh, bx0 + kx, by, fullb);
            TMA_LOAD_2D(tn + SM_B_LO, &tmBl, bx0 + kx, by, fullb);
        }
    } else if (wid == 5 && elect_one()) {
        // ---------------- MMA consumer (single thread) ----------------
        for (int c = 0; c < NC; c++) {
            const int s = c & 1;
            MBARRIER_WAIT_PARITY(smem_base + 32 + s * 8, (c >> 1) & 1);
            const uint32_t tb = smem_base + SM_TILE0 + s * SM_STAGE;
            const uint64_t dah = make_desc(tb + SM_A_HI);
            const uint64_t dal = make_desc(tb + SM_A_LO);
            const uint64_t dbh = make_desc(tb + SM_B_HI);
            const uint64_t dbl = make_desc(tb + SM_B_LO);
#pragma unroll
            for (int st = 0; st < 4; st++)       // hi*hi  (K=16 per step)
                mma_bf16(tmem, dah + st * 2, dbh + st * 2, IDESC_BF16,
                         (c == 0 && st == 0) ? 0u : 1u);
#pragma unroll
            for (int st = 0; st < 4; st++)       // hi*lo
                mma_bf16(tmem, dah + st * 2, dbl + st * 2, IDESC_BF16, 1u);
#pragma unroll
            for (int st = 0; st < 4; st++)       // lo*hi
                mma_bf16(tmem, dal + st * 2, dbh + st * 2, IDESC_BF16, 1u);
            TCGEN05_COMMIT(smem_base + 8 + s * 8);
        }
    }
    __syncthreads();

    // wait for the last chunk's MMA completion
    MBARRIER_WAIT_PARITY(smem_base + 8 + ((NC - 1) & 1) * 8, ((NC - 1) >> 1) & 1);
    TCGEN05_FENCE_AFTER();

    if (wid < 4) {
        const int lane = tid & 31;
        const int m = rm + wid * 32 + lane;      // TMEM lane -> D row
        const float biasm = (EPI == 3) ? bias[m] : 0.f;
#pragma unroll
        for (int seg = 0; seg < 8; seg++) {      // 256 cols
            uint32_t r[32];
            TCGEN05_LD_32X32B_X32(r, tmem + seg * 32);
            TCGEN05_WAIT_LD();
#pragma unroll
            for (int j = 0; j < 32; j += 4) {
                float v[4];
#pragma unroll
                for (int t = 0; t < 4; t++) {
                    const int n = cn + seg * 32 + j + t;
                    float x = __uint_as_float(r[j + t]);
                    if (EPI == 0)      x += bias[n];
                    else if (EPI == 1) x = fmaxf(x + bias[n], 0.f);
                    else if (EPI == 2) x *= scale;
                    else if (EPI == 3) x += biasm;
                    v[t] = x;
                }
                const long base = (long)m * ldc + cn + seg * 32 + j;
                if (OUT == 0) {
                    *(float4*)(C + base) = make_float4(v[0], v[1], v[2], v[3]);
                } else {
                    __nv_bfloat162 h0, h1, l0, l1;
                    bf16 hh, ll;
                    bf16_split(v[0], hh, ll); h0.x = hh; l0.x = ll;
                    bf16_split(v[1], hh, ll); h0.y = hh; l0.y = ll;
                    bf16_split(v[2], hh, ll); h1.x = hh; l1.x = ll;
                    bf16_split(v[3], hh, ll); h1.y = hh; l1.y = ll;
                    ((__nv_bfloat162*)(Ch + base))[0] = h0;
                    ((__nv_bfloat162*)(Ch + base))[1] = h1;
                    ((__nv_bfloat162*)(Cl + base))[0] = l0;
                    ((__nv_bfloat162*)(Cl + base))[1] = l1;
                }
            }
        }
        TCGEN05_FENCE_BEFORE();
    }
    __syncthreads();
    if (wid == 5) {
        TCGEN05_RELINQUISH();
        TCGEN05_DEALLOC(tmem, 256);
    }
#else
    // --------------------- SIMT fp32 fallback path -------------------------
    constexpr int BK = 16;
    float (*As)[132] = (float (*)[132])(smem);
    float (*Bs)[132] = (float (*)[132])(smem + BK * 132 * sizeof(float));
    const int tx = tid & 15, ty = tid >> 4;

    Ah += (long)(blockIdx.z * aYoff) * lda;
    Al += (long)(blockIdx.z * aYoff) * lda;
    Bh += (long)(blockIdx.z * bYoff) * ldb + blockIdx.z * (long)bXoff;
    Bl += (long)(blockIdx.z * bYoff) * ldb + blockIdx.z * (long)bXoff;

    for (int half = 0; half < 2; half++) {
        const int cnh = cn + half * 128;
        float acc[8][8];
#pragma unroll
        for (int i = 0; i < 8; i++)
#pragma unroll
            for (int j = 0; j < 8; j++) acc[i][j] = 0.f;

        for (int k0 = 0; k0 < Keff; k0 += BK) {
#pragma unroll
            for (int i = 0; i < 2; i++) {
                const int q = i * 256 + tid;
                const int row = q >> 1, kc = (q & 1) * 8;
#pragma unroll
                for (int u = 0; u < 8; u++) {
                    const long ai = (long)(rm + row) * lda + k0 + kc + u;
                    const long bi = (long)(cnh + row) * ldb + k0 + kc + u;
                    As[kc + u][row] = __bfloat162float(Ah[ai]) + __bfloat162float(Al[ai]);
                    Bs[kc + u][row] = __bfloat162float(Bh[bi]) + __bfloat162float(Bl[bi]);
                }
            }
            __syncthreads();
#pragma unroll
            for (int kk = 0; kk < BK; kk++) {
                float a[8], b[8];
#pragma unroll
                for (int i = 0; i < 8; i++) a[i] = As[kk][ty * 8 + i];
#pragma unroll
                for (int j = 0; j < 8; j++) b[j] = Bs[kk][tx * 8 + j];
#pragma unroll
                for (int i = 0; i < 8; i++)
#pragma unroll
                    for (int j = 0; j < 8; j++) acc[i][j] += a[i] * b[j];
            }
            __syncthreads();
        }

#pragma unroll
        for (int i = 0; i < 8; i++) {
            const int m = rm + ty * 8 + i;
            const float biasm = (EPI == 3) ? bias[m] : 0.f;
#pragma unroll
            for (int j = 0; j < 8; j++) {
                const int n = cnh + tx * 8 + j;
                float x = acc[i][j];
                if (EPI == 0)      x += bias[n];
                else if (EPI == 1) x = fmaxf(x + bias[n], 0.f);
                else if (EPI == 2) x *= scale;
                else if (EPI == 3) x += biasm;
                if (OUT == 0) C[(long)m * ldc + n] = x;
                else {
                    bf16 hh, ll;
                    bf16_split(x, hh, ll);
                    Ch[(long)m * ldc + n] = hh;
                    Cl[(long)m * ldc + n] = ll;
                }
            }
        }
        __syncthreads();
    }
#endif
}

// ---------------------------------------------------------------------------
// Elementwise bf16 Dekker split; split2 handles two tensors via blockIdx.y.
// ---------------------------------------------------------------------------
__device__ __forceinline__ void split_body(const float* __restrict__ src,
                                           bf16* __restrict__ hi,
                                           bf16* __restrict__ lo, long n4)
{
    for (long i = blockIdx.x * 256L + threadIdx.x; i < n4; i += (long)gridDim.x * 256) {
        const float4 f = *(const float4*)(src + i * 4);
        __nv_bfloat162 h0, h1, l0, l1;
        bf16 hh, ll;
        bf16_split(f.x, hh, ll); h0.x = hh; l0.x = ll;
        bf16_split(f.y, hh, ll); h0.y = hh; l0.y = ll;
        bf16_split(f.z, hh, ll); h1.x = hh; l1.x = ll;
        bf16_split(f.w, hh, ll); h1.y = hh; l1.y = ll;
        ((__nv_bfloat162*)(hi + i * 4))[0] = h0;
        ((__nv_bfloat162*)(hi + i * 4))[1] = h1;
        ((__nv_bfloat162*)(lo + i * 4))[0] = l0;
        ((__nv_bfloat162*)(lo + i * 4))[1] = l1;
    }
}

__global__ void __launch_bounds__(256)
split2_k(const float* __restrict__ s0, bf16* __restrict__ h0, bf16* __restrict__ l0,
         const float* __restrict__ s1, bf16* __restrict__ h1, bf16* __restrict__ l1,
         long n4)
{
    if (blockIdx.y == 0) split_body(s0, h0, l0, n4);
    else                 split_body(s1, h1, l1, n4);
}

// ---------------------------------------------------------------------------
// Row softmax over fp32 scores -> bf16 (hi, lo) prob planes.
// Causal rows: L=i+1; zero-fill only up to the 128-row diagonal block end.
// ---------------------------------------------------------------------------
__global__ void __launch_bounds__(256)
softmax_k(const float* __restrict__ S, bf16* __restrict__ Ph,
          bf16* __restrict__ Pl, int causal)
{
    const int row = blockIdx.x;
    const int b = row >> 11;
    const int i = row & 2047;
    const float* p = S + (long)b * Sn * Sn + (long)i * Sn;
    bf16* ph = Ph + (long)b * Sn * Sn + (long)i * Sn;
    bf16* pl = Pl + (long)b * Sn * Sn + (long)i * Sn;
    const int L = causal ? (i + 1) : Sn;
    const int FILL = causal ? (((i >> 7) + 1) << 7) : Sn;
    const int tid = threadIdx.x;
    __shared__ float sh[8];

    float m = -3.4e38f;
    for (int j = tid; j < L; j += 256) m = fmaxf(m, p[j]);
#pragma unroll
    for (int o = 16; o > 0; o >>= 1) m = fmaxf(m, __shfl_xor_sync(~0u, m, o));
    if ((tid & 31) == 0) sh[tid >> 5] = m;
    __syncthreads();
    m = sh[0];
#pragma unroll
    for (int w = 1; w < 8; w++) m = fmaxf(m, sh[w]);

    float s = 0.f;
    for (int j = tid; j < L; j += 256) s += __expf(p[j] - m);
#pragma unroll
    for (int o = 16; o > 0; o >>= 1) s += __shfl_xor_sync(~0u, s, o);
    __syncthreads();
    if ((tid & 31) == 0) sh[tid >> 5] = s;
    __syncthreads();
    s = 0.f;
#pragma unroll
    for (int w = 0; w < 8; w++) s += sh[w];
    const float inv = 1.f / s;

    for (int j = tid; j < L; j += 256) {
        const float v = __expf(p[j] - m) * inv;
        bf16 hh, ll;
        bf16_split(v, hh, ll);
        ph[j] = hh;
        pl[j] = ll;
    }
    const bf16 z = __float2bfloat16(0.f);
    for (int j = L + tid; j < FILL; j += 256) { ph[j] = z; pl[j] = z; }
}

// ---------------------------------------------------------------------------
// y = LayerNorm(x + h) * g + b; optional bf16 split planes (yh, yl).
// ---------------------------------------------------------------------------
__global__ void __launch_bounds__(256)
add_ln_k(const float* __restrict__ x, const float* __restrict__ h,
         const float* __restrict__ g, const float* __restrict__ bt,
         float* __restrict__ y, bf16* __restrict__ yh, bf16* __restrict__ yl)
{
    const long row = blockIdx.x;
    const float* xr = x + row * En;
    const float* hr = h + row * En;
    const int tid = threadIdx.x;

    float v[3];
    float s = 0.f, s2 = 0.f;
#pragma unroll
    for (int t = 0; t < 3; t++) {
        const int c = tid + t * 256;
        const float u = xr[c] + hr[c];
        v[t] = u;
        s += u;
        s2 += u * u;
    }
    __shared__ float shA[8], shB[8];
#pragma unroll
    for (int o = 16; o > 0; o >>= 1) {
        s  += __shfl_xor_sync(~0u, s,  o);
        s2 += __shfl_xor_sync(~0u, s2, o);
    }
    if ((tid & 31) == 0) { shA[tid >> 5] = s; shB[tid >> 5] = s2; }
    __syncthreads();
    s = 0.f; s2 = 0.f;
#pragma unroll
    for (int w = 0; w < 8; w++) { s += shA[w]; s2 += shB[w]; }

    const float mu   = s * (1.f / En);
    const float var  = s2 * (1.f / En) - mu * mu;
    const float rstd = rsqrtf(var + LNEPS);
#pragma unroll
    for (int t = 0; t < 3; t++) {
        const int c = tid + t * 256;
        const float o = (v[t] - mu) * rstd * g[c] + bt[c];
        y[row * En + c] = o;
        if (yh) {
            bf16 hh, ll;
            bf16_split(o, hh, ll);
            yh[row * En + c] = hh;
            yl[row * En + c] = ll;
        }
    }
}

// ---------------------------------------------------------------------------
// Host: tensor-map encoding via driver entry point (no -lcuda link needed).
// ---------------------------------------------------------------------------
typedef CUresult (*PFN_tmEncode)(
    CUtensorMap*, CUtensorMapDataType, cuuint32_t, void*,
    const cuuint64_t*, const cuuint64_t*, const cuuint32_t*, const cuuint32_t*,
    CUtensorMapInterleave, CUtensorMapSwizzle, CUtensorMapL2promotion,
    CUtensorMapFloatOOBfill);

static PFN_tmEncode tm_encoder() {
    static PFN_tmEncode fn = nullptr;
    if (!fn) {
        void* p = nullptr;
        cudaDriverEntryPointQueryResult st;
#if CUDART_VERSION >= 12050
        cudaGetDriverEntryPointByVersion("cuTensorMapEncodeTiled", &p, 12000,
                                         cudaEnableDefault, &st);
#else
        cudaGetDriverEntryPoint("cuTensorMapEncodeTiled", &p,
                                cudaEnableDefault, &st);
#endif
        fn = (PFN_tmEncode)p;
    }
    return fn;
}

// 2D bf16 tensor map: dims {rowElems, nRows}, SW128, box {64, boxRows}.
static CUtensorMap make_map(const void* base, long rowElems, long nRows, int boxRows)
{
    CUtensorMap m;
    cuuint64_t dims[2]    = {(cuuint64_t)rowElems, (cuuint64_t)nRows};
    cuuint64_t strides[1] = {(cuuint64_t)rowElems * 2};
    cuuint32_t box[2]     = {64u, (cuuint32_t)boxRows};
    cuuint32_t es[2]      = {1u, 1u};
    tm_encoder()(&m, CU_TENSOR_MAP_DATA_TYPE_BFLOAT16, 2, (void*)base,
                 dims, strides, box, es,
                 CU_TENSOR_MAP_INTERLEAVE_NONE, CU_TENSOR_MAP_SWIZZLE_128B,
                 CU_TENSOR_MAP_L2_PROMOTION_L2_128B,
                 CU_TENSOR_MAP_FLOAT_OOB_FILL_NONE);
    return m;
}

// ---------------------------------------------------------------------------
// Host launcher
// ---------------------------------------------------------------------------
extern "C" void kernel_launch(void* const* d_in, const int* in_sizes, int n_in,
                              void* d_out, int out_size)
{
    const float* x     = (const float*)d_in[0];
    const float* kv    = (const float*)d_in[1];
    const float* wq_w  = (const float*)d_in[2];
    const float* wq_b  = (const float*)d_in[3];
    const float* wk_w  = (const float*)d_in[4];
    const float* wk_b  = (const float*)d_in[5];
    const float* wv_w  = (const float*)d_in[6];
    const float* wv_b  = (const float*)d_in[7];
    const float* ln1_g = (const float*)d_in[8];
    const float* ln1_b = (const float*)d_in[9];
    const float* wq2_w = (const float*)d_in[10];
    const float* wq2_b = (const float*)d_in[11];
    const float* wk2_w = (const float*)d_in[12];
    const float* wk2_b = (const float*)d_in[13];
    const float* wv2_w = (const float*)d_in[14];
    const float* wv2_b = (const float*)d_in[15];
    const float* ln2_g = (const float*)d_in[16];
    const float* ln2_b = (const float*)d_in[17];
    const float* w1    = (const float*)d_in[18];
    const float* b1    = (const float*)d_in[19];
    const float* w2    = (const float*)d_in[20];
    const float* b2    = (const float*)d_in[21];
    const float* ln3_g = (const float*)d_in[22];
    const float* ln3_b = (const float*)d_in[23];
    float* out = (float*)d_out;

    bf16 *qh, *ql, *kh, *kl, *vth, *vtl, *prh, *prl, *hh, *hl;
    bf16 *x1h, *x1l, *x2h, *x2l, *xh, *xl, *kvh, *kvl, *wh, *wl;
    float *ps, *phf, *x1, *x2, *pmlp;
    cudaGetSymbolAddress((void**)&qh,  g_qh);   cudaGetSymbolAddress((void**)&ql,  g_ql);
    cudaGetSymbolAddress((void**)&kh,  g_kh);   cudaGetSymbolAddress((void**)&kl,  g_kl);
    cudaGetSymbolAddress((void**)&vth, g_vth);  cudaGetSymbolAddress((void**)&vtl, g_vtl);
    cudaGetSymbolAddress((void**)&prh, g_ph);   cudaGetSymbolAddress((void**)&prl, g_pl);
    cudaGetSymbolAddress((void**)&hh,  g_hh);   cudaGetSymbolAddress((void**)&hl,  g_hl);
    cudaGetSymbolAddress((void**)&x1h, g_x1h);  cudaGetSymbolAddress((void**)&x1l, g_x1l);
    cudaGetSymbolAddress((void**)&x2h, g_x2h);  cudaGetSymbolAddress((void**)&x2l, g_x2l);
    cudaGetSymbolAddress((void**)&xh,  g_xh);   cudaGetSymbolAddress((void**)&xl,  g_xl);
    cudaGetSymbolAddress((void**)&kvh, g_kvh);  cudaGetSymbolAddress((void**)&kvl, g_kvl);
    cudaGetSymbolAddress((void**)&wh,  g_wh);   cudaGetSymbolAddress((void**)&wl,  g_wl);
    cudaGetSymbolAddress((void**)&ps,  g_s);
    cudaGetSymbolAddress((void**)&phf, g_h);
    cudaGetSymbolAddress((void**)&x1,  g_x1);
    cudaGetSymbolAddress((void**)&x2,  g_x2);
    cudaGetSymbolAddress((void**)&pmlp, g_mlp);

    const long oWQ = 0, oWK = oWQ + (long)En * En, oWV = oWK + (long)En * En;
    const long oWQ2 = oWV + (long)En * En, oWK2 = oWQ2 + (long)En * En;
    const long oWV2 = oWK2 + (long)En * En;
    const long oW1 = oWV2 + (long)En * En, oW2 = oW1 + (long)DFFn * En;

    cudaFuncSetAttribute(gemm_tc<0,1>, cudaFuncAttributeMaxDynamicSharedMemorySize, GEMM_SMEM);
    cudaFuncSetAttribute(gemm_tc<3,1>, cudaFuncAttributeMaxDynamicSharedMemorySize, GEMM_SMEM);
    cudaFuncSetAttribute(gemm_tc<2,0>, cudaFuncAttributeMaxDynamicSharedMemorySize, GEMM_SMEM);
    cudaFuncSetAttribute(gemm_tc<4,0>, cudaFuncAttributeMaxDynamicSharedMemorySize, GEMM_SMEM);
    cudaFuncSetAttribute(gemm_tc<1,1>, cudaFuncAttributeMaxDynamicSharedMemorySize, GEMM_SMEM);
    cudaFuncSetAttribute(gemm_tc<1,0>, cudaFuncAttributeMaxDynamicSharedMemorySize, GEMM_SMEM);

    const float scale = 0.03608439182435161f;  // 1/sqrt(768)
    const long sSS = (long)Sn * Sn;
    const long sQE = (long)Sn * En;

    const dim3 gProj(En / 256, MTOT / 128, 1);       // 3 x 64
    const dim3 gVT(MTOT / 256, En / 128, 1);         // 32 x 6
    const dim3 gScore(Sn / 256, Sn / 128, Bn);       // 8 x 16 x 4
    const dim3 gPV(En / 256, Sn / 128, Bn);          // 3 x 16 x 4
    const dim3 gFF1(DFFn / 256, MTOT / 128, 1);      // 12 x 64
    const dim3 gFF2(En / 256, MTOT / 128, 1);        // 3 x 64

    const long nXY = (long)MTOT * En / 4;
    const long nW  = (long)En * En / 4;
    const long nFF = (long)DFFn * En / 4;

    // Tensor maps (host-side, cheap; baked into the graph at capture).
    CUtensorMap mXh  = make_map(xh,  En,  MTOT, 128), mXl  = make_map(xl,  En,  MTOT, 128);
    CUtensorMap mXhB = make_map(xh,  En,  MTOT, 256), mXlB = make_map(xl,  En,  MTOT, 256);
    CUtensorMap mKvB = make_map(kvh, En,  MTOT, 256), mKvlB= make_map(kvl, En,  MTOT, 256);
    CUtensorMap mKvA = make_map(kvh, En,  MTOT, 128), mKvlA= make_map(kvl, En,  MTOT, 128);
    CUtensorMap mWQh = make_map(wh + oWQ,  En, En, 256), mWQl = make_map(wl + oWQ,  En, En, 256);
    CUtensorMap mWKh = make_map(wh + oWK,  En, En, 256), mWKl = make_map(wl + oWK,  En, En, 256);
    CUtensorMap mWVh = make_map(wh + oWV,  En, En, 128), mWVl = make_map(wl + oWV,  En, En, 128);
    CUtensorMap mWQ2h= make_map(wh + oWQ2, En, En, 256), mWQ2l= make_map(wl + oWQ2, En, En, 256);
    CUtensorMap mWK2h= make_map(wh + oWK2, En, En, 256), mWK2l= make_map(wl + oWK2, En, En, 256);
    CUtensorMap mWV2h= make_map(wh + oWV2, En, En, 128), mWV2l= make_map(wl + oWV2, En, En, 128);
    CUtensorMap mW1h = make_map(wh + oW1, En, DFFn, 256), mW1l = make_map(wl + oW1, En, DFFn, 256);
    CUtensorMap mW2h = make_map(wh + oW2, DFFn, En, 256), mW2l = make_map(wl + oW2, DFFn, En, 256);
    CUtensorMap mQh  = make_map(qh, En, MTOT, 128), mQl  = make_map(ql, En, MTOT, 128);
    CUtensorMap mKh  = make_map(kh, En, MTOT, 256), mKl  = make_map(kl, En, MTOT, 256);
    CUtensorMap mPh  = make_map(prh, Sn, MTOT, 128), mPl  = make_map(prl, Sn, MTOT, 128);
    CUtensorMap mVth = make_map(vth, MTOT, En, 256), mVtl = make_map(vtl, MTOT, En, 256);
    CUtensorMap mX1h = make_map(x1h, En, MTOT, 128), mX1l = make_map(x1l, En, MTOT, 128);
    CUtensorMap mX2h = make_map(x2h, En, MTOT, 128), mX2l = make_map(x2l, En, MTOT, 128);
    CUtensorMap mHh  = make_map(hh, DFFn, MTOT, 128), mHl  = make_map(hl, DFFn, MTOT, 128);

    // Launch order puts the causal score GEMM at index 5 (ncu -s 5 -c 1).
    split2_k<<<dim3(296, 2), 256>>>(x, xh, xl, kv, kvh, kvl, nXY);
    split2_k<<<dim3(148, 2), 256>>>(wq_w, wh + oWQ, wl + oWQ,
                                    wk_w, wh + oWK, wl + oWK, nW);
    gemm_tc<0,1><<<gProj, 256, GEMM_SMEM>>>(mXh, mXl, mWQh, mWQl,
                                            xh, xl, wh + oWQ, wl + oWQ, wq_b,
                                            nullptr, qh, ql, En, En, En, En,
                                            0, 0, 0, 0, 1.f, 0);
    gemm_tc<0,1><<<gProj, 256, GEMM_SMEM>>>(mXh, mXl, mWKh, mWKl,
                                            xh, xl, wh + oWK, wl + oWK, wk_b,
                                            nullptr, kh, kl, En, En, En, En,
                                            0, 0, 0, 0, 1.f, 0);
    split2_k<<<dim3(148, 2), 256>>>(wv_w,  wh + oWV,  wl + oWV,
                                    wv2_w, wh + oWV2, wl + oWV2, nW);
    // 5: causal score GEMM  <-- profiled launch
    gemm_tc<2,0><<<gScore, 256, GEMM_SMEM>>>(mQh, mQl, mKh, mKl,
                                             qh, ql, kh, kl, nullptr,
                                             ps, nullptr, nullptr, En, En, En, Sn,
                                             Sn, 0, Sn, sSS, scale, 1);
    gemm_tc<3,1><<<gVT, 256, GEMM_SMEM>>>(mWVh, mWVl, mXhB, mXlB,
                                          wh + oWV, wl + oWV, xh, xl, wv_b,
                                          nullptr, vth, vtl, En, En, En, MTOT,
                                          0, 0, 0, 0, 1.f, 0);
    softmax_k<<<MTOT, 256>>>(ps, prh, prl, 1);
    gemm_tc<4,0><<<gPV, 256, GEMM_SMEM>>>(mPh, mPl, mVth, mVtl,
                                          prh, prl, vth, vtl, nullptr,
                                          phf, nullptr, nullptr, Sn, Sn, MTOT, En,
                                          Sn, Sn, 0, sQE, 1.f, 2);
    add_ln_k<<<MTOT, 256>>>(x, phf, ln1_g, ln1_b, x1, x1h, x1l);

    // ---- cross-attention ----
    split2_k<<<dim3(148, 2), 256>>>(wq2_w, wh + oWQ2, wl + oWQ2,
                                    wk2_w, wh + oWK2, wl + oWK2, nW);
    gemm_tc<0,1><<<gProj, 256, GEMM_SMEM>>>(mX1h, mX1l, mWQ2h, mWQ2l,
                                            x1h, x1l, wh + oWQ2, wl + oWQ2, wq2_b,
                                            nullptr, qh, ql, En, En, En, En,
                                            0, 0, 0, 0, 1.f, 0);
    gemm_tc<0,1><<<gProj, 256, GEMM_SMEM>>>(mKvA, mKvlA, mWK2h, mWK2l,
                                            kvh, kvl, wh + oWK2, wl + oWK2, wk2_b,
                                            nullptr, kh, kl, En, En, En, En,
                                            0, 0, 0, 0, 1.f, 0);
    gemm_tc<3,1><<<gVT, 256, GEMM_SMEM>>>(mWV2h, mWV2l, mKvB, mKvlB,
                                          wh + oWV2, wl + oWV2, kvh, kvl, wv2_b,
                                          nullptr, vth, vtl, En, En, En, MTOT,
                                          0, 0, 0, 0, 1.f, 0);
    gemm_tc<2,0><<<gScore, 256, GEMM_SMEM>>>(mQh, mQl, mKh, mKl,
                                             qh, ql, kh, kl, nullptr,
                                             ps, nullptr, nullptr, En, En, En, Sn,
                                             Sn, 0, Sn, sSS, scale, 0);
    softmax_k<<<MTOT, 256>>>(ps, prh, prl, 0);
    gemm_tc<4,0><<<gPV, 256, GEMM_SMEM>>>(mPh, mPl, mVth, mVtl,
                                          prh, prl, vth, vtl, nullptr,
                                          phf, nullptr, nullptr, Sn, Sn, MTOT, En,
                                          Sn, Sn, 0, sQE, 1.f, 0);
    add_ln_k<<<MTOT, 256>>>(x1, phf, ln2_g, ln2_b, x2, x2h, x2l);

    // ---- MLP ----
    split2_k<<<dim3(592, 2), 256>>>(w1, wh + oW1, wl + oW1,
                                    w2, wh + oW2, wl + oW2, nFF);
    gemm_tc<1,1><<<gFF1, 256, GEMM_SMEM>>>(mX2h, mX2l, mW1h, mW1l,
                                           x2h, x2l, wh + oW1, wl + oW1, b1,
                                           nullptr, hh, hl, En, En, En, DFFn,
                                           0, 0, 0, 0, 1.f, 0);
    gemm_tc<1,0><<<gFF2, 256, GEMM_SMEM>>>(mHh, mHl, mW2h, mW2l,
                                           hh, hl, wh + oW2, wl + oW2, b2,
                                           pmlp, nullptr, nullptr, DFFn, DFFn, DFFn, En,
                                           0, 0, 0, 0, 1.f, 0);
    add_ln_k<<<MTOT, 256>>>(x2, pmlp, ln3_g, ln3_b, out, nullptr, nullptr);
}

// round 10
// speedup vs baseline: 2.7690x; 1.2990x over previous
#include <cuda.h>
#include <cuda_runtime.h>
#include <cuda_bf16.h>
#include <cstdint>
#include <math.h>

// ---------------------------------------------------------------------------
// Problem constants
// ---------------------------------------------------------------------------
#define Bn   4
#define Sn   2048
#define En   768
#define DFFn 3072
#define MTOT (Bn * Sn)          // 8192
#define LNEPS 1e-5f

#if defined(__CUDA_ARCH__) && \
    (defined(__CUDA_ARCH_FEAT_SM103_ALL) || defined(__CUDA_ARCH_FEAT_SM100_ALL) || \
     defined(__CUDA_ARCH_FEAT_SM101_ALL) || \
     (defined(__CUDA_ARCH_SPECIFIC__)        && (__CUDA_ARCH_SPECIFIC__        >= 1000)) || \
     (defined(__CUDA_ARCH_FAMILY_SPECIFIC__) && (__CUDA_ARCH_FAMILY_SPECIFIC__ >= 1000)))
#define HAS_TC 1
#else
#define HAS_TC 0
#endif

typedef __nv_bfloat16 bf16;

// ---------------------------------------------------------------------------
// Scratch. All bf16 operand tensors live in PANEL layout: 128 rows x 64 cols
// per panel (16 KB), SW128 pre-swizzled, panel index = rowBlk*KB + kBlk.
// probs (g_ph/g_pl) and fp32 tensors stay row-major.
// ---------------------------------------------------------------------------
__device__ __align__(128) bf16  g_qh [MTOT * En],  g_ql [MTOT * En];
__device__ __align__(128) bf16  g_kh [MTOT * En],  g_kl [MTOT * En];
__device__ __align__(128) bf16  g_vth[MTOT * En],  g_vtl[MTOT * En];   // V^T panels [En, MTOT]
__device__ __align__(128) float g_s  [(size_t)Bn * Sn * Sn];           // raw scores
__device__ __align__(128) bf16  g_ph [(size_t)Bn * Sn * Sn];           // prob planes (row-major)
__device__ __align__(128) bf16  g_pl [(size_t)Bn * Sn * Sn];
__device__ __align__(128) bf16  g_hh [(size_t)MTOT * DFFn];            // MLP hidden panels
__device__ __align__(128) bf16  g_hl [(size_t)MTOT * DFFn];
__device__ __align__(128) float g_h  [MTOT * En];
__device__ __align__(128) float g_x1 [MTOT * En];
__device__ __align__(128) bf16  g_x1h[MTOT * En], g_x1l[MTOT * En];
__device__ __align__(128) float g_x2 [MTOT * En];
__device__ __align__(128) bf16  g_x2h[MTOT * En], g_x2l[MTOT * En];
__device__ __align__(128) float g_mlp[MTOT * En];
__device__ __align__(128) bf16  g_xh [MTOT * En], g_xl [MTOT * En];
__device__ __align__(128) bf16  g_kvh[MTOT * En], g_kvl[MTOT * En];
__device__ __align__(128) bf16  g_wh [6 * En * En + 2 * DFFn * En];
__device__ __align__(128) bf16  g_wl [6 * En * En + 2 * DFFn * En];

// ---------------------------------------------------------------------------
// Panel addressing: byte offset of element (row, col) in a tensor with kd cols.
// SW128 swizzle permutes 16B cells within each 128B row; low 4 bits pass thru.
// ---------------------------------------------------------------------------
__device__ __forceinline__ long panel_off(int row, int col, int kd) {
    long p = (long)(row >> 7) * (kd >> 6) + (col >> 6);
    uint32_t b = (uint32_t)((row & 127) * 128 + (col & 63) * 2);
    b ^= (b >> 3) & 0x70;
    return p * 16384 + b;
}

__device__ __forceinline__ uint32_t smem_u32(const void* p) {
    uint32_t a;
    asm("{ .reg .u64 t; cvta.to.shared.u64 t, %1; cvt.u32.u64 %0, t; }"
        : "=r"(a) : "l"(p));
    return a;
}

__device__ __forceinline__ void bf16_split(float x, bf16& h, bf16& l) {
    h = __float2bfloat16_rn(x);
    l = __float2bfloat16_rn(x - __bfloat162float(h));
}

__device__ __forceinline__ uint32_t pack2(bf16 a, bf16 b) {
    __nv_bfloat162 t(a, b);
    return *(uint32_t*)&t;
}

__device__ __forceinline__ float panel_read(const bf16* p, int row, int col, int kd) {
    return __bfloat162float(*(const bf16*)((const char*)p + panel_off(row, col, kd)));
}

#if HAS_TC
__device__ __forceinline__ uint32_t elect_one() {
    uint32_t pred;
    asm volatile("{\n\t.reg .pred p;\n\telect.sync _|p, 0xFFFFFFFF;\n\t"
                 "selp.b32 %0, 1, 0, p;\n\t}" : "=r"(pred));
    return pred;
}

#define MBARRIER_INIT(addr, cnt) \
    asm volatile("mbarrier.init.shared.b64 [%0], %1;" :: "r"(addr), "r"(cnt) : "memory")

#define MBARRIER_EXPECT_TX(addr, bytes) \
    asm volatile("mbarrier.arrive.expect_tx.shared.b64 _, [%0], %1;" \
                 :: "r"((uint32_t)(addr)), "r"((uint32_t)(bytes)) : "memory")

#define MBARRIER_WAIT_PARITY(mbar_addr, phase_parity) do {                          \
    uint32_t _mbar = (uint32_t)(mbar_addr);                                         \
    uint32_t _par  = (uint32_t)(phase_parity);                                      \
    uint32_t _done;                                                                 \
    asm volatile("{\n\t.reg .pred p;\n\t"                                           \
        "mbarrier.try_wait.parity.acquire.cta.shared::cta.b64 p, [%1], %2;\n\t"     \
        "selp.b32 %0, 1, 0, p;\n\t}"                                                \
        : "=r"(_done) : "r"(_mbar), "r"(_par) : "memory");                          \
    if (!_done) {                                                                   \
        asm volatile("{\n\t.reg .pred P1;\n\t"                                      \
        "WAIT_LOOP_%=:\n\t"                                                         \
        "mbarrier.try_wait.parity.acquire.cta.shared::cta.b64 P1, [%0], %1, 0x989680;\n\t" \
        "@P1 bra.uni WAIT_DONE_%=;\n\t"                                             \
        "bra.uni WAIT_LOOP_%=;\n\t"                                                 \
        "WAIT_DONE_%=:\n\t}"                                                        \
        :: "r"(_mbar), "r"(_par) : "memory");                                       \
    }                                                                               \
} while (0)

#define TCGEN05_ALLOC(smem_res, ncols) \
    asm volatile("tcgen05.alloc.cta_group::1.sync.aligned.shared::cta.b32 [%0], %1;" \
                 :: "r"((uint32_t)(smem_res)), "r"((uint32_t)(ncols)) : "memory")
#define TCGEN05_DEALLOC(tmem, ncols) \
    asm volatile("tcgen05.dealloc.cta_group::1.sync.aligned.b32 %0, %1;" \
                 :: "r"(tmem), "r"((uint32_t)(ncols)))
#define TCGEN05_RELINQUISH() \
    asm volatile("tcgen05.relinquish_alloc_permit.cta_group::1.sync.aligned;")
#define TCGEN05_COMMIT(mbar) \
    asm volatile("tcgen05.commit.cta_group::1.mbarrier::arrive::one.shared::cluster.b64 [%0];" \
                 :: "r"((uint32_t)(mbar)) : "memory")
#define TCGEN05_FENCE_AFTER() \
    asm volatile("tcgen05.fence::after_thread_sync;" ::: "memory")
#define TCGEN05_FENCE_BEFORE() \
    asm volatile("tcgen05.fence::before_thread_sync;" ::: "memory")
#define TCGEN05_WAIT_LD() \
    asm volatile("tcgen05.wait::ld.sync.aligned;" ::: "memory")

// 1D contiguous bulk copy gmem->smem, completion via mbarrier complete_tx.
#define BULK_LOAD(dst, src, bytes, mbar) \
    asm volatile("cp.async.bulk.shared::cluster.global.mbarrier::complete_tx::bytes " \
                 "[%0], [%1], %2, [%3];" \
                 :: "r"((uint32_t)(dst)), "l"(src), "r"((uint32_t)(bytes)), \
                    "r"((uint32_t)(mbar)) : "memory")

// 2D TMA load (probs only).
#define TMA_LOAD_2D(smem_addr, map, cx, cy, mbar) \
    asm volatile( \
        "cp.async.bulk.tensor.2d.shared::cta.global.tile.mbarrier::complete_tx::bytes " \
        "[%0], [%1, {%2, %3}], [%4];" \
        :: "r"((uint32_t)(smem_addr)), "l"(map), "r"((int)(cx)), "r"((int)(cy)), \
           "r"((uint32_t)(mbar)) : "memory")

#define TCGEN05_LD_32X32B_X32(r, tmem_addr) \
    asm volatile( \
        "tcgen05.ld.sync.aligned.32x32b.x32.b32 " \
        "{%0, %1, %2, %3, %4, %5, %6, %7, " \
        " %8, %9, %10, %11, %12, %13, %14, %15, " \
        " %16, %17, %18, %19, %20, %21, %22, %23, " \
        " %24, %25, %26, %27, %28, %29, %30, %31}, [%32];" \
        : "=r"((r)[0]),  "=r"((r)[1]),  "=r"((r)[2]),  "=r"((r)[3]), \
          "=r"((r)[4]),  "=r"((r)[5]),  "=r"((r)[6]),  "=r"((r)[7]), \
          "=r"((r)[8]),  "=r"((r)[9]),  "=r"((r)[10]), "=r"((r)[11]), \
          "=r"((r)[12]), "=r"((r)[13]), "=r"((r)[14]), "=r"((r)[15]), \
          "=r"((r)[16]), "=r"((r)[17]), "=r"((r)[18]), "=r"((r)[19]), \
          "=r"((r)[20]), "=r"((r)[21]), "=r"((r)[22]), "=r"((r)[23]), \
          "=r"((r)[24]), "=r"((r)[25]), "=r"((r)[26]), "=r"((r)[27]), \
          "=r"((r)[28]), "=r"((r)[29]), "=r"((r)[30]), "=r"((r)[31]) \
        : "r"(tmem_addr))

__device__ __forceinline__ uint64_t make_desc(uint32_t addr) {
    constexpr uint64_t base =
        (uint64_t(2)  << 61) | (uint64_t(1) << 46) |
        (uint64_t(64) << 32) | (uint64_t(1) << 16);
    return base | ((uint64_t)(addr >> 4) & 0x3FFF);
}

__device__ __forceinline__ void mma_bf16(uint32_t d_tmem, uint64_t da, uint64_t db,
                                         uint32_t idesc, uint32_t acc) {
    asm volatile(
        "{\n\t.reg .pred p;\n\tsetp.ne.u32 p, %4, 0;\n\t"
        "tcgen05.mma.cta_group::1.kind::f16 [%0], %1, %2, %3, {%5, %5, %5, %5}, p;\n\t}"
        :: "r"(d_tmem), "l"(da), "l"(db), "r"(idesc), "r"(acc), "r"(0u)
        : "memory");
}
#endif  // HAS_TC

// ---------------------------------------------------------------------------
// GEMM (NT): C[M,N] = A[M,K] * B[N,K]^T, bf16 (hi, lo) planes, 3-pass.
// Tiles BM=128, BN=256, BK=64. Operands in panel layout (16KB bulk loads);
// LOADA=1 loads A via 2D TMA (probs, row-major).
//   EPI 0:+bias[n] 1:relu(+bias[n]) 2:*scale 3:+bias[m] 4:none
//   OUT 0: fp32 row-major C   1: bf16 panel planes (Ch, Cl)
//   causal 0:none 1:skip upper tiles 2:K-limit (causal PV)
// ---------------------------------------------------------------------------
static constexpr int SM_TILE0  = 1024;
static constexpr int SM_A_HI   = 0;
static constexpr int SM_A_LO   = 16384;
static constexpr int SM_B_HI   = 32768;
static constexpr int SM_B_LO   = 65536;
static constexpr int SM_STAGE  = 98304;
static constexpr int GEMM_SMEM = SM_TILE0 + 2 * SM_STAGE;   // 197632 B
static constexpr uint32_t IDESC_BF16 =
    (1u << 4) | (1u << 7) | (1u << 10) | ((256u / 8u) << 17) | ((128u / 16u) << 24);

template<int EPI, int OUT, int LOADA>
__global__ void __launch_bounds__(256, 1)
gemm_tc(const __grid_constant__ CUtensorMap tmAh,
        const __grid_constant__ CUtensorMap tmAl,
        const bf16* __restrict__ Aph, const bf16* __restrict__ Apl,   // panels (or probs rowmajor for fallback)
        const bf16* __restrict__ Bph, const bf16* __restrict__ Bpl,   // panels
        const float* __restrict__ bias,
        float* __restrict__ C, bf16* __restrict__ Ch, bf16* __restrict__ Cl,
        int K, int KAB, int KBB, int ldc,
        int aYoff, int bXoff, int bYoff, long sC, float scale, int causal)
{
    extern __shared__ __align__(1024) char smem[];
    const int tid = threadIdx.x;

    const int rm = blockIdx.y * 128;
    const int cn = blockIdx.x * 256;
    if (causal == 1 && cn > rm + 127) return;

    if (OUT == 0) C += (long)blockIdx.z * sC;

    int Keff = K;
    if (causal == 2) Keff = min(K, rm + 128);

#if HAS_TC
    const uint32_t smem_base = smem_u32(smem);
    const int wid = tid >> 5;

    if (tid == 0) {
        MBARRIER_INIT(smem_base + 8,  1);     // empty[0]
        MBARRIER_INIT(smem_base + 16, 1);     // empty[1]
        MBARRIER_INIT(smem_base + 32, 1);     // full[0]
        MBARRIER_INIT(smem_base + 40, 1);     // full[1]
    }
    if (wid == 5) TCGEN05_ALLOC(smem_base + 0, 256);
    __syncthreads();

    uint32_t tmem;
    asm volatile("ld.shared.b32 %0, [%1];" : "=r"(tmem) : "r"(smem_base));

    const int NC = Keff >> 6;
    const int ay = blockIdx.z * aYoff + rm;         // TMA row (LOADA=1)
    const long aP = ((long)((blockIdx.z * aYoff + rm) >> 7)) * KAB;   // A panel row base
    const long bP0 = ((long)((blockIdx.z * bYoff + cn) >> 7)) * KBB;  // B panel row 0
    const long bP1 = bP0 + KBB;                                       // B panel row 1
    const int  kB0 = (blockIdx.z * bXoff) >> 6;

    if (wid == 4 && elect_one()) {
        // ---------------- producer (single thread) ----------------
        for (int c = 0; c < NC; c++) {
            const int s = c & 1;
            if (c >= 2)
                MBARRIER_WAIT_PARITY(smem_base + 8 + s * 8, ((c >> 1) + 1) & 1);
            const uint32_t fullb = smem_base + 32 + s * 8;
            MBARRIER_EXPECT_TX(fullb, (uint32_t)SM_STAGE);
            const uint32_t tn = smem_base + SM_TILE0 + s * SM_STAGE;
            if (LOADA == 1) {
                const int kx = c << 6;
                TMA_LOAD_2D(tn + SM_A_HI, &tmAh, kx, ay, fullb);
                TMA_LOAD_2D(tn + SM_A_LO, &tmAl, kx, ay, fullb);
            } else {
                const long pa = (aP + c) * 16384;
                BULK_LOAD(tn + SM_A_HI, (const char*)Aph + pa, 16384, fullb);
                BULK_LOAD(tn + SM_A_LO, (const char*)Apl + pa, 16384, fullb);
            }
            const long pb0 = (bP0 + kB0 + c) * 16384;
            const long pb1 = (bP1 + kB0 + c) * 16384;
            BULK_LOAD(tn + SM_B_HI,         (const char*)Bph + pb0, 16384, fullb);
            BULK_LOAD(tn + SM_B_HI + 16384, (const char*)Bph + pb1, 16384, fullb);
            BULK_LOAD(tn + SM_B_LO,         (const char*)Bpl + pb0, 16384, fullb);
            BULK_LOAD(tn + SM_B_LO + 16384, (const char*)Bpl + pb1, 16384, fullb);
        }
    } else if (wid == 5 && elect_one()) {
        // ---------------- MMA consumer (single thread) ----------------
        for (int c = 0; c < NC; c++) {
            const int s = c & 1;
            MBARRIER_WAIT_PARITY(smem_base + 32 + s * 8, (c >> 1) & 1);
            const uint32_t tb = smem_base + SM_TILE0 + s * SM_STAGE;
            const uint64_t dah = make_desc(tb + SM_A_HI);
            const uint64_t dal = make_desc(tb + SM_A_LO);
            const uint64_t dbh = make_desc(tb + SM_B_HI);
            const uint64_t dbl = make_desc(tb + SM_B_LO);
#pragma unroll
            for (int st = 0; st < 4; st++)
                mma_bf16(tmem, dah + st * 2, dbh + st * 2, IDESC_BF16,
                         (c == 0 && st == 0) ? 0u : 1u);
#pragma unroll
            for (int st = 0; st < 4; st++)
                mma_bf16(tmem, dah + st * 2, dbl + st * 2, IDESC_BF16, 1u);
#pragma unroll
            for (int st = 0; st < 4; st++)
                mma_bf16(tmem, dal + st * 2, dbh + st * 2, IDESC_BF16, 1u);
            TCGEN05_COMMIT(smem_base + 8 + s * 8);
        }
    }
    __syncthreads();

    MBARRIER_WAIT_PARITY(smem_base + 8 + ((NC - 1) & 1) * 8, ((NC - 1) >> 1) & 1);
    TCGEN05_FENCE_AFTER();

    if (wid < 4) {
        const int lane = tid & 31;
        const int m = rm + wid * 32 + lane;
        const float biasm = (EPI == 3) ? bias[m] : 0.f;
#pragma unroll
        for (int seg = 0; seg < 8; seg++) {
            uint32_t r[32];
            TCGEN05_LD_32X32B_X32(r, tmem + seg * 32);
            TCGEN05_WAIT_LD();
#pragma unroll
            for (int j = 0; j < 32; j += 4) {
                float v[4];
#pragma unroll
                for (int t = 0; t < 4; t++) {
                    const int n = cn + seg * 32 + j + t;
                    float x = __uint_as_float(r[j + t]);
                    if (EPI == 0)      x += bias[n];
                    else if (EPI == 1) x = fmaxf(x + bias[n], 0.f);
                    else if (EPI == 2) x *= scale;
                    else if (EPI == 3) x += biasm;
                    v[t] = x;
                }
                if (OUT == 0) {
                    *(float4*)(C + (long)m * ldc + cn + seg * 32 + j) =
                        make_float4(v[0], v[1], v[2], v[3]);
                } else {
                    bf16 h0, l0, h1, l1, h2, l2, h3, l3;
                    bf16_split(v[0], h0, l0); bf16_split(v[1], h1, l1);
                    bf16_split(v[2], h2, l2); bf16_split(v[3], h3, l3);
                    const long off = panel_off(m, cn + seg * 32 + j, ldc);
                    uint2 uh, ul;
                    uh.x = pack2(h0, h1); uh.y = pack2(h2, h3);
                    ul.x = pack2(l0, l1); ul.y = pack2(l2, l3);
                    *(uint2*)((char*)Ch + off) = uh;
                    *(uint2*)((char*)Cl + off) = ul;
                }
            }
        }
        TCGEN05_FENCE_BEFORE();
    }
    __syncthreads();
    if (wid == 5) {
        TCGEN05_RELINQUISH();
        TCGEN05_DEALLOC(tmem, 256);
    }
#else
    // --------------------- SIMT fp32 fallback path -------------------------
    constexpr int BK = 16;
    float (*As)[132] = (float (*)[132])(smem);
    float (*Bs)[132] = (float (*)[132])(smem + BK * 132 * sizeof(float));
    const int tx = tid & 15, ty = tid >> 4;
    const int lda = KAB * 64, ldbK = KBB * 64;

    for (int half = 0; half < 2; half++) {
        const int cnh = cn + half * 128;
        float acc[8][8];
#pragma unroll
        for (int i = 0; i < 8; i++)
#pragma unroll
            for (int j = 0; j < 8; j++) acc[i][j] = 0.f;

        for (int k0 = 0; k0 < Keff; k0 += BK) {
#pragma unroll
            for (int i = 0; i < 2; i++) {
                const int q = i * 256 + tid;
                const int row = q >> 1, kc = (q & 1) * 8;
#pragma unroll
                for (int u = 0; u < 8; u++) {
                    const int k = k0 + kc + u;
                    float av;
                    if (LOADA == 1) {
                        const long ai = (long)(blockIdx.z * aYoff + rm + row) * lda + k;
                        av = __bfloat162float(Aph[ai]) + __bfloat162float(Apl[ai]);
                    } else {
                        const int gr = blockIdx.z * aYoff + rm + row;
                        av = panel_read(Aph, gr, k, lda) + panel_read(Apl, gr, k, lda);
                    }
                    const int gbr = blockIdx.z * bYoff + cnh + row;
                    const int gbk = blockIdx.z * bXoff + k;
                    float bv = panel_read(Bph, gbr, gbk, ldbK) +
                               panel_read(Bpl, gbr, gbk, ldbK);
                    As[kc + u][row] = av;
                    Bs[kc + u][row] = bv;
                }
            }
            __syncthreads();
#pragma unroll
            for (int kk = 0; kk < BK; kk++) {
                float a[8], b[8];
#pragma unroll
                for (int i = 0; i < 8; i++) a[i] = As[kk][ty * 8 + i];
#pragma unroll
                for (int j = 0; j < 8; j++) b[j] = Bs[kk][tx * 8 + j];
#pragma unroll
                for (int i = 0; i < 8; i++)
#pragma unroll
                    for (int j = 0; j < 8; j++) acc[i][j] += a[i] * b[j];
            }
            __syncthreads();
        }

#pragma unroll
        for (int i = 0; i < 8; i++) {
            const int m = rm + ty * 8 + i;
            const float biasm = (EPI == 3) ? bias[m] : 0.f;
#pragma unroll
            for (int j = 0; j < 8; j++) {
                const int n = cnh + tx * 8 + j;
                float x = acc[i][j];
                if (EPI == 0)      x += bias[n];
                else if (EPI == 1) x = fmaxf(x + bias[n], 0.f);
                else if (EPI == 2) x *= scale;
                else if (EPI == 3) x += biasm;
                if (OUT == 0) C[(long)m * ldc + n] = x;
                else {
                    bf16 hh, ll;
                    bf16_split(x, hh, ll);
                    const long off = panel_off(m, n, ldc);
                    *(bf16*)((char*)Ch + off) = hh;
                    *(bf16*)((char*)Cl + off) = ll;
                }
            }
        }
        __syncthreads();
    }
#endif
}

// ---------------------------------------------------------------------------
// Elementwise bf16 Dekker split -> PANEL layout. Two tensors per launch.
// ---------------------------------------------------------------------------
__device__ __forceinline__ void split_body(const float* __restrict__ src,
                                           bf16* __restrict__ hi,
                                           bf16* __restrict__ lo, long n4, int kd)
{
    for (long i = blockIdx.x * 256L + threadIdx.x; i < n4; i += (long)gridDim.x * 256) {
        const float4 f = *(const float4*)(src + i * 4);
        bf16 h0, l0, h1, l1, h2, l2, h3, l3;
        bf16_split(f.x, h0, l0); bf16_split(f.y, h1, l1);
        bf16_split(f.z, h2, l2); bf16_split(f.w, h3, l3);
        const long e0 = i * 4;
        const int row = (int)(e0 / kd);
        const int col = (int)(e0 - (long)row * kd);
        const long off = panel_off(row, col, kd);
        uint2 uh, ul;
        uh.x = pack2(h0, h1); uh.y = pack2(h2, h3);
        ul.x = pack2(l0, l1); ul.y = pack2(l2, l3);
        *(uint2*)((char*)hi + off) = uh;
        *(uint2*)((char*)lo + off) = ul;
    }
}

__global__ void __launch_bounds__(256)
split2_k(const float* __restrict__ s0, bf16* __restrict__ h0, bf16* __restrict__ l0,
         const float* __restrict__ s1, bf16* __restrict__ h1, bf16* __restrict__ l1,
         long n4, int kd0, int kd1)
{
    if (blockIdx.y == 0) split_body(s0, h0, l0, n4, kd0);
    else                 split_body(s1, h1, l1, n4, kd1);
}

// ---------------------------------------------------------------------------
// Row softmax over fp32 scores -> bf16 (hi, lo) prob planes (row-major).
// ---------------------------------------------------------------------------
__global__ void __launch_bounds__(256)
softmax_k(const float* __restrict__ S, bf16* __restrict__ Ph,
          bf16* __restrict__ Pl, int causal)
{
    const int row = blockIdx.x;
    const int b = row >> 11;
    const int i = row & 2047;
    const float* p = S + (long)b * Sn * Sn + (long)i * Sn;
    bf16* ph = Ph + (long)b * Sn * Sn + (long)i * Sn;
    bf16* pl = Pl + (long)b * Sn * Sn + (long)i * Sn;
    const int L = causal ? (i + 1) : Sn;
    const int FILL = causal ? (((i >> 7) + 1) << 7) : Sn;
    const int tid = threadIdx.x;
    __shared__ float sh[8];

    float m = -3.4e38f;
    for (int j = tid; j < L; j += 256) m = fmaxf(m, p[j]);
#pragma unroll
    for (int o = 16; o > 0; o >>= 1) m = fmaxf(m, __shfl_xor_sync(~0u, m, o));
    if ((tid & 31) == 0) sh[tid >> 5] = m;
    __syncthreads();
    m = sh[0];
#pragma unroll
    for (int w = 1; w < 8; w++) m = fmaxf(m, sh[w]);

    float s = 0.f;
    for (int j = tid; j < L; j += 256) s += __expf(p[j] - m);
#pragma unroll
    for (int o = 16; o > 0; o >>= 1) s += __shfl_xor_sync(~0u, s, o);
    __syncthreads();
    if ((tid & 31) == 0) sh[tid >> 5] = s;
    __syncthreads();
    s = 0.f;
#pragma unroll
    for (int w = 0; w < 8; w++) s += sh[w];
    const float inv = 1.f / s;

    for (int j = tid; j < L; j += 256) {
        const float v = __expf(p[j] - m) * inv;
        bf16 hh, ll;
        bf16_split(v, hh, ll);
        ph[j] = hh;
        pl[j] = ll;
    }
    const bf16 z = __float2bfloat16(0.f);
    for (int j = L + tid; j < FILL; j += 256) { ph[j] = z; pl[j] = z; }
}

// ---------------------------------------------------------------------------
// y = LayerNorm(x + h) * g + b; optional panel-layout bf16 splits (yh, yl).
// ---------------------------------------------------------------------------
__global__ void __launch_bounds__(256)
add_ln_k(const float* __restrict__ x, const float* __restrict__ h,
         const float* __restrict__ g, const float* __restrict__ bt,
         float* __restrict__ y, bf16* __restrict__ yh, bf16* __restrict__ yl)
{
    const long row = blockIdx.x;
    const float* xr = x + row * En;
    const float* hr = h + row * En;
    const int tid = threadIdx.x;

    float v[3];
    float s = 0.f, s2 = 0.f;
#pragma unroll
    for (int t = 0; t < 3; t++) {
        const int c = tid + t * 256;
        const float u = xr[c] + hr[c];
        v[t] = u;
        s += u;
        s2 += u * u;
    }
    __shared__ float shA[8], shB[8];
#pragma unroll
    for (int o = 16; o > 0; o >>= 1) {
        s  += __shfl_xor_sync(~0u, s,  o);
        s2 += __shfl_xor_sync(~0u, s2, o);
    }
    if ((tid & 31) == 0) { shA[tid >> 5] = s; shB[tid >> 5] = s2; }
    __syncthreads();
    s = 0.f; s2 = 0.f;
#pragma unroll
    for (int w = 0; w < 8; w++) { s += shA[w]; s2 += shB[w]; }

    const float mu   = s * (1.f / En);
    const float var  = s2 * (1.f / En) - mu * mu;
    const float rstd = rsqrtf(var + LNEPS);
#pragma unroll
    for (int t = 0; t < 3; t++) {
        const int c = tid + t * 256;
        const float o = (v[t] - mu) * rstd * g[c] + bt[c];
        y[row * En + c] = o;
        if (yh) {
            bf16 hh, ll;
            bf16_split(o, hh, ll);
            const long off = panel_off((int)row, c, En);
            *(bf16*)((char*)yh + off) = hh;
            *(bf16*)((char*)yl + off) = ll;
        }
    }
}

// ---------------------------------------------------------------------------
// Host: tensor-map encoding via driver entry point (probs only).
// ---------------------------------------------------------------------------
typedef CUresult (*PFN_tmEncode)(
    CUtensorMap*, CUtensorMapDataType, cuuint32_t, void*,
    const cuuint64_t*, const cuuint64_t*, const cuuint32_t*, const cuuint32_t*,
    CUtensorMapInterleave, CUtensorMapSwizzle, CUtensorMapL2promotion,
    CUtensorMapFloatOOBfill);

static PFN_tmEncode tm_encoder() {
    static PFN_tmEncode fn = nullptr;
    if (!fn) {
        void* p = nullptr;
        cudaDriverEntryPointQueryResult st;
#if CUDART_VERSION >= 12050
        cudaGetDriverEntryPointByVersion("cuTensorMapEncodeTiled", &p, 12000,
                                         cudaEnableDefault, &st);
#else
        cudaGetDriverEntryPoint("cuTensorMapEncodeTiled", &p,
                                cudaEnableDefault, &st);
#endif
        fn = (PFN_tmEncode)p;
    }
    return fn;
}

static CUtensorMap make_map(const void* base, long rowElems, long nRows, int boxRows)
{
    CUtensorMap m;
    cuuint64_t dims[2]    = {(cuuint64_t)rowElems, (cuuint64_t)nRows};
    cuuint64_t strides[1] = {(cuuint64_t)rowElems * 2};
    cuuint32_t box[2]     = {64u, (cuuint32_t)boxRows};
    cuuint32_t es[2]      = {1u, 1u};
    tm_encoder()(&m, CU_TENSOR_MAP_DATA_TYPE_BFLOAT16, 2, (void*)base,
                 dims, strides, box, es,
                 CU_TENSOR_MAP_INTERLEAVE_NONE, CU_TENSOR_MAP_SWIZZLE_128B,
                 CU_TENSOR_MAP_L2_PROMOTION_L2_128B,
                 CU_TENSOR_MAP_FLOAT_OOB_FILL_NONE);
    return m;
}

// ---------------------------------------------------------------------------
// Host launcher
// ---------------------------------------------------------------------------
extern "C" void kernel_launch(void* const* d_in, const int* in_sizes, int n_in,
                              void* d_out, int out_size)
{
    const float* x     = (const float*)d_in[0];
    const float* kv    = (const float*)d_in[1];
    const float* wq_w  = (const float*)d_in[2];
    const float* wq_b  = (const float*)d_in[3];
    const float* wk_w  = (const float*)d_in[4];
    const float* wk_b  = (const float*)d_in[5];
    const float* wv_w  = (const float*)d_in[6];
    const float* wv_b  = (const float*)d_in[7];
    const float* ln1_g = (const float*)d_in[8];
    const float* ln1_b = (const float*)d_in[9];
    const float* wq2_w = (const float*)d_in[10];
    const float* wq2_b = (const float*)d_in[11];
    const float* wk2_w = (const float*)d_in[12];
    const float* wk2_b = (const float*)d_in[13];
    const float* wv2_w = (const float*)d_in[14];
    const float* wv2_b = (const float*)d_in[15];
    const float* ln2_g = (const float*)d_in[16];
    const float* ln2_b = (const float*)d_in[17];
    const float* w1    = (const float*)d_in[18];
    const float* b1    = (const float*)d_in[19];
    const float* w2    = (const float*)d_in[20];
    const float* b2    = (const float*)d_in[21];
    const float* ln3_g = (const float*)d_in[22];
    const float* ln3_b = (const float*)d_in[23];
    float* out = (float*)d_out;

    bf16 *qh, *ql, *kh, *kl, *vth, *vtl, *prh, *prl, *hh, *hl;
    bf16 *x1h, *x1l, *x2h, *x2l, *xh, *xl, *kvh, *kvl, *wh, *wl;
    float *ps, *phf, *x1, *x2, *pmlp;
    cudaGetSymbolAddress((void**)&qh,  g_qh);   cudaGetSymbolAddress((void**)&ql,  g_ql);
    cudaGetSymbolAddress((void**)&kh,  g_kh);   cudaGetSymbolAddress((void**)&kl,  g_kl);
    cudaGetSymbolAddress((void**)&vth, g_vth);  cudaGetSymbolAddress((void**)&vtl, g_vtl);
    cudaGetSymbolAddress((void**)&prh, g_ph);   cudaGetSymbolAddress((void**)&prl, g_pl);
    cudaGetSymbolAddress((void**)&hh,  g_hh);   cudaGetSymbolAddress((void**)&hl,  g_hl);
    cudaGetSymbolAddress((void**)&x1h, g_x1h);  cudaGetSymbolAddress((void**)&x1l, g_x1l);
    cudaGetSymbolAddress((void**)&x2h, g_x2h);  cudaGetSymbolAddress((void**)&x2l, g_x2l);
    cudaGetSymbolAddress((void**)&xh,  g_xh);   cudaGetSymbolAddress((void**)&xl,  g_xl);
    cudaGetSymbolAddress((void**)&kvh, g_kvh);  cudaGetSymbolAddress((void**)&kvl, g_kvl);
    cudaGetSymbolAddress((void**)&wh,  g_wh);   cudaGetSymbolAddress((void**)&wl,  g_wl);
    cudaGetSymbolAddress((void**)&ps,  g_s);
    cudaGetSymbolAddress((void**)&phf, g_h);
    cudaGetSymbolAddress((void**)&x1,  g_x1);
    cudaGetSymbolAddress((void**)&x2,  g_x2);
    cudaGetSymbolAddress((void**)&pmlp, g_mlp);

    const long oWQ = 0, oWK = oWQ + (long)En * En, oWV = oWK + (long)En * En;
    const long oWQ2 = oWV + (long)En * En, oWK2 = oWQ2 + (long)En * En;
    const long oWV2 = oWK2 + (long)En * En;
    const long oW1 = oWV2 + (long)En * En, oW2 = oW1 + (long)DFFn * En;

    cudaFuncSetAttribute(gemm_tc<0,1,0>, cudaFuncAttributeMaxDynamicSharedMemorySize, GEMM_SMEM);
    cudaFuncSetAttribute(gemm_tc<3,1,0>, cudaFuncAttributeMaxDynamicSharedMemorySize, GEMM_SMEM);
    cudaFuncSetAttribute(gemm_tc<2,0,0>, cudaFuncAttributeMaxDynamicSharedMemorySize, GEMM_SMEM);
    cudaFuncSetAttribute(gemm_tc<4,0,1>, cudaFuncAttributeMaxDynamicSharedMemorySize, GEMM_SMEM);
    cudaFuncSetAttribute(gemm_tc<1,1,0>, cudaFuncAttributeMaxDynamicSharedMemorySize, GEMM_SMEM);
    cudaFuncSetAttribute(gemm_tc<1,0,0>, cudaFuncAttributeMaxDynamicSharedMemorySize, GEMM_SMEM);

    const float scale = 0.03608439182435161f;  // 1/sqrt(768)
    const long sSS = (long)Sn * Sn;
    const long sQE = (long)Sn * En;

    const dim3 gProj(En / 256, MTOT / 128, 1);
    const dim3 gVT(MTOT / 256, En / 128, 1);
    const dim3 gScore(Sn / 256, Sn / 128, Bn);
    const dim3 gPV(En / 256, Sn / 128, Bn);
    const dim3 gFF1(DFFn / 256, MTOT / 128, 1);
    const dim3 gFF2(En / 256, MTOT / 128, 1);

    const long nXY = (long)MTOT * En / 4;
    const long nW  = (long)En * En / 4;
    const long nFF = (long)DFFn * En / 4;

    CUtensorMap mPh = make_map(prh, Sn, MTOT, 128);
    CUtensorMap mPl = make_map(prl, Sn, MTOT, 128);

    // Launch order keeps the causal score GEMM at index 5 (ncu -s 5 -c 1).
    split2_k<<<dim3(296, 2), 256>>>(x, xh, xl, kv, kvh, kvl, nXY, En, En);
    split2_k<<<dim3(148, 2), 256>>>(wq_w, wh + oWQ, wl + oWQ,
                                    wk_w, wh + oWK, wl + oWK, nW, En, En);
    gemm_tc<0,1,0><<<gProj, 256, GEMM_SMEM>>>(mPh, mPl, xh, xl, wh + oWQ, wl + oWQ,
        wq_b, nullptr, qh, ql, En, 12, 12, En, 0, 0, 0, 0, 1.f, 0);
    gemm_tc<0,1,0><<<gProj, 256, GEMM_SMEM>>>(mPh, mPl, xh, xl, wh + oWK, wl + oWK,
        wk_b, nullptr, kh, kl, En, 12, 12, En, 0, 0, 0, 0, 1.f, 0);
    split2_k<<<dim3(148, 2), 256>>>(wv_w,  wh + oWV,  wl + oWV,
                                    wv2_w, wh + oWV2, wl + oWV2, nW, En, En);
    // 5: causal score GEMM  <-- profiled launch
    gemm_tc<2,0,0><<<gScore, 256, GEMM_SMEM>>>(mPh, mPl, qh, ql, kh, kl,
        nullptr, ps, nullptr, nullptr, En, 12, 12, Sn, Sn, 0, Sn, sSS, scale, 1);
    gemm_tc<3,1,0><<<gVT, 256, GEMM_SMEM>>>(mPh, mPl, wh + oWV, wl + oWV, xh, xl,
        wv_b, nullptr, vth, vtl, En, 12, 12, MTOT, 0, 0, 0, 0, 1.f, 0);
    softmax_k<<<MTOT, 256>>>(ps, prh, prl, 1);
    gemm_tc<4,0,1><<<gPV, 256, GEMM_SMEM>>>(mPh, mPl, prh, prl, vth, vtl,
        nullptr, phf, nullptr, nullptr, Sn, 32, 128, En, Sn, Sn, 0, sQE, 1.f, 2);
    add_ln_k<<<MTOT, 256>>>(x, phf, ln1_g, ln1_b, x1, x1h, x1l);

    // ---- cross-attention ----
    split2_k<<<dim3(148, 2), 256>>>(wq2_w, wh + oWQ2, wl + oWQ2,
                                    wk2_w, wh + oWK2, wl + oWK2, nW, En, En);
    gemm_tc<0,1,0><<<gProj, 256, GEMM_SMEM>>>(mPh, mPl, x1h, x1l, wh + oWQ2, wl + oWQ2,
        wq2_b, nullptr, qh, ql, En, 12, 12, En, 0, 0, 0, 0, 1.f, 0);
    gemm_tc<0,1,0><<<gProj, 256, GEMM_SMEM>>>(mPh, mPl, kvh, kvl, wh + oWK2, wl + oWK2,
        wk2_b, nullptr, kh, kl, En, 12, 12, En, 0, 0, 0, 0, 1.f, 0);
    gemm_tc<3,1,0><<<gVT, 256, GEMM_SMEM>>>(mPh, mPl, wh + oWV2, wl + oWV2, kvh, kvl,
        wv2_b, nullptr, vth, vtl, En, 12, 12, MTOT, 0, 0, 0, 0, 1.f, 0);
    gemm_tc<2,0,0><<<gScore, 256, GEMM_SMEM>>>(mPh, mPl, qh, ql, kh, kl,
        nullptr, ps, nullptr, nullptr, En, 12, 12, Sn, Sn, 0, Sn, sSS, scale, 0);
    softmax_k<<<MTOT, 256>>>(ps, prh, prl, 0);
    gemm_tc<4,0,1><<<gPV, 256, GEMM_SMEM>>>(mPh, mPl, prh, prl, vth, vtl,
        nullptr, phf, nullptr, nullptr, Sn, 32, 128, En, Sn, Sn, 0, sQE, 1.f, 0);
    add_ln_k<<<MTOT, 256>>>(x1, phf, ln2_g, ln2_b, x2, x2h, x2l);

    // ---- MLP ----
    split2_k<<<dim3(592, 2), 256>>>(w1, wh + oW1, wl + oW1,
                                    w2, wh + oW2, wl + oW2, nFF, En, DFFn);
    gemm_tc<1,1,0><<<gFF1, 256, GEMM_SMEM>>>(mPh, mPl, x2h, x2l, wh + oW1, wl + oW1,
        b1, nullptr, hh, hl, En, 12, 12, DFFn, 0, 0, 0, 0, 1.f, 0);
    gemm_tc<1,0,0><<<gFF2, 256, GEMM_SMEM>>>(mPh, mPl, hh, hl, wh + oW2, wl + oW2,
        b2, pmlp, nullptr, nullptr, DFFn, 48, 48, En, 0, 0, 0, 0, 1.f, 0);
    add_ln_k<<<MTOT, 256>>>(x2, pmlp, ln3_g, ln3_b, out, nullptr, nullptr);
}